// round 9
// baseline (speedup 1.0000x reference)
#include <cuda_runtime.h>
#include <cuda_fp16.h>
#include <math.h>

#define Bc  2
#define Sc  4096
#define DMc 512
#define Hc  8
#define Dc  64
#define Mc  (Bc * Sc)   // 8192

#define SCL (0.125f * 1.44269504f)
#define MSK (-1.44269504e9f)

// fp16 mirrors of inputs/weights + fp16 scratch
__device__ __half g_qh[Mc * DMc];
__device__ __half g_kh[Mc * DMc];
__device__ __half g_vh[Mc * DMc];
__device__ __half g_Wqh[DMc * DMc];
__device__ __half g_Wkh[DMc * DMc];
__device__ __half g_Wvh[DMc * DMc];
__device__ __half g_Woh[DMc * DMc];
__device__ __half g_Qp[Bc * Hc * Sc * Dc];
__device__ __half g_Kp[Bc * Hc * Sc * Dc];
__device__ __half g_Vp[Bc * Hc * Sc * Dc];
__device__ __half g_Ao[Mc * DMc];

// ---------------------------------------------------------------------------
// helpers
// ---------------------------------------------------------------------------
__device__ __forceinline__ unsigned pack_f16x2(float lo, float hi) {
    unsigned r;
    asm("cvt.rn.f16x2.f32 %0, %1, %2;" : "=r"(r) : "f"(hi), "f"(lo));
    return r;
}

__device__ __forceinline__ float ex2(float x) {
    float r;
    asm("ex2.approx.f32 %0, %1;" : "=f"(r) : "f"(x));
    return r;
}

__device__ __forceinline__ unsigned ex2_f16x2(unsigned x) {
    unsigned r;
    asm("ex2.approx.f16x2 %0, %1;" : "=r"(r) : "r"(x));
    return r;
}

__device__ __forceinline__ void cp16(unsigned dst, const void* src) {
    asm volatile("cp.async.cg.shared.global [%0], [%1], 16;"
                 :: "r"(dst), "l"(__cvta_generic_to_global(src)));
}
__device__ __forceinline__ void cp_commit() {
    asm volatile("cp.async.commit_group;");
}
template <int N>
__device__ __forceinline__ void cp_wait() {
    asm volatile("cp.async.wait_group %0;" :: "n"(N));
}

__device__ __forceinline__ void ldsm_x4(unsigned& r0, unsigned& r1,
                                        unsigned& r2, unsigned& r3,
                                        unsigned addr) {
    asm volatile("ldmatrix.sync.aligned.m8n8.x4.shared.b16 {%0,%1,%2,%3}, [%4];"
                 : "=r"(r0), "=r"(r1), "=r"(r2), "=r"(r3) : "r"(addr));
}
__device__ __forceinline__ void ldsm_x4_t(unsigned& r0, unsigned& r1,
                                          unsigned& r2, unsigned& r3,
                                          unsigned addr) {
    asm volatile("ldmatrix.sync.aligned.m8n8.x4.trans.shared.b16 {%0,%1,%2,%3}, [%4];"
                 : "=r"(r0), "=r"(r1), "=r"(r2), "=r"(r3) : "r"(addr));
}
__device__ __forceinline__ void mma_f16(float c[4], unsigned a0, unsigned a1,
                                        unsigned a2, unsigned a3,
                                        unsigned b0, unsigned b1) {
    asm volatile(
        "mma.sync.aligned.m16n8k16.row.col.f32.f16.f16.f32 "
        "{%0,%1,%2,%3}, {%4,%5,%6,%7}, {%8,%9}, {%0,%1,%2,%3};\n"
        : "+f"(c[0]), "+f"(c[1]), "+f"(c[2]), "+f"(c[3])
        : "r"(a0), "r"(a1), "r"(a2), "r"(a3), "r"(b0), "r"(b1));
}

// ---------------------------------------------------------------------------
// fp32 -> fp16 conversion pre-pass
// ---------------------------------------------------------------------------
__global__ __launch_bounds__(256)
void cvt_in(const float* __restrict__ q, const float* __restrict__ k,
            const float* __restrict__ v,
            __half* __restrict__ qh, __half* __restrict__ kh,
            __half* __restrict__ vh)
{
    const int z = blockIdx.z;
    const float* s = z == 0 ? q  : (z == 1 ? k  : v);
    __half*      d = z == 0 ? qh : (z == 1 ? kh : vh);
    int i = blockIdx.x * 256 + threadIdx.x;          // float4 index
    float4 f = ((const float4*)s)[i];
    ((uint2*)d)[i] = make_uint2(pack_f16x2(f.x, f.y), pack_f16x2(f.z, f.w));
}

__global__ __launch_bounds__(256)
void cvt_w(const float* __restrict__ Wq, const float* __restrict__ Wk,
           const float* __restrict__ Wv, const float* __restrict__ Wo,
           __half* __restrict__ Wqh, __half* __restrict__ Wkh,
           __half* __restrict__ Wvh, __half* __restrict__ Woh)
{
    const int z = blockIdx.z;
    const float* s = z == 0 ? Wq  : (z == 1 ? Wk  : (z == 2 ? Wv  : Wo));
    __half*      d = z == 0 ? Wqh : (z == 1 ? Wkh : (z == 2 ? Wvh : Woh));
    int i = blockIdx.x * 256 + threadIdx.x;
    float4 f = ((const float4*)s)[i];
    ((uint2*)d)[i] = make_uint2(pack_f16x2(f.x, f.y), pack_f16x2(f.z, f.w));
}

// ---------------------------------------------------------------------------
// pure-fp16 GEMM, cp.async double-buffered. C = X @ W (+bias) [*scale].
// Block 128x128, BK=32, 8 warps (4m x 2n), warp tile 32x64.
// MODE 0: __half out, head-split layout, scale applied.
// MODE 1: float out, row-major.
// ---------------------------------------------------------------------------
#define ASTR 40
#define BSTR 136
#define A_BYTES (128 * ASTR * 2)
#define B_BYTES (32 * BSTR * 2)
#define STAGE_BYTES (A_BYTES + B_BYTES)

template <int MODE>
__device__ __forceinline__ void gemm_f16_body(
    const __half* __restrict__ X, const __half* __restrict__ W,
    const float* __restrict__ bias, void* outp, float scale)
{
    __shared__ __align__(16) char sh[2 * STAGE_BYTES];

    const int tid  = threadIdx.x;
    const int wid  = tid >> 5;
    const int lane = tid & 31;
    const int g    = lane >> 2;
    const int tig  = lane & 3;
    const int wm   = (wid & 3) << 5;
    const int wn   = (wid >> 2) << 6;
    const int lrow = (lane & 7) + ((lane >> 3) & 1) * 8;
    const int lcol = (lane >> 4) << 3;

    const int m0 = blockIdx.y << 7;
    const int n0 = blockIdx.x << 7;

    const unsigned sh_b = (unsigned)__cvta_generic_to_shared(sh);

    float c[2][8][4];
#pragma unroll
    for (int mt = 0; mt < 2; mt++)
#pragma unroll
        for (int nt = 0; nt < 8; nt++)
#pragma unroll
            for (int j = 0; j < 4; j++) c[mt][nt][j] = 0.f;

    auto issue = [&](int k0, int s) {
        unsigned as = sh_b + s * STAGE_BYTES;
        unsigned bs = as + A_BYTES;
#pragma unroll
        for (int p = 0; p < 2; p++) {
            int i = tid + (p << 8);
            int r = i >> 2, cc = (i & 3) << 3;
            cp16(as + (r * ASTR + cc) * 2, X + (size_t)(m0 + r) * DMc + k0 + cc);
        }
#pragma unroll
        for (int p = 0; p < 2; p++) {
            int i = tid + (p << 8);
            int r = i >> 4, cc = (i & 15) << 3;
            cp16(bs + (r * BSTR + cc) * 2, W + (size_t)(k0 + r) * DMc + n0 + cc);
        }
        cp_commit();
    };

    issue(0, 0);
    int buf = 0;
    for (int kc = 0; kc < 16; kc++) {
        if (kc < 15) { issue((kc + 1) << 5, buf ^ 1); cp_wait<1>(); }
        else         { cp_wait<0>(); }
        __syncthreads();

        const unsigned as_b = sh_b + buf * STAGE_BYTES;
        const unsigned bs_b = as_b + A_BYTES;
#pragma unroll
        for (int ks = 0; ks < 2; ks++) {
            const int kb = ks << 4;
            unsigned a[2][4];
#pragma unroll
            for (int mt = 0; mt < 2; mt++) {
                unsigned addr = as_b +
                    (((wm + (mt << 4) + lrow) * ASTR) + kb + lcol) * 2;
                ldsm_x4(a[mt][0], a[mt][1], a[mt][2], a[mt][3], addr);
            }
#pragma unroll
            for (int np = 0; np < 4; np++) {
                unsigned addr = bs_b +
                    (((kb + lrow) * BSTR) + wn + (np << 4) + lcol) * 2;
                unsigned r0, r1, r2, r3;
                ldsm_x4_t(r0, r1, r2, r3, addr);
                mma_f16(c[0][2 * np],     a[0][0], a[0][1], a[0][2], a[0][3], r0, r1);
                mma_f16(c[0][2 * np + 1], a[0][0], a[0][1], a[0][2], a[0][3], r2, r3);
                mma_f16(c[1][2 * np],     a[1][0], a[1][1], a[1][2], a[1][3], r0, r1);
                mma_f16(c[1][2 * np + 1], a[1][0], a[1][1], a[1][2], a[1][3], r2, r3);
            }
        }
        __syncthreads();
        buf ^= 1;
    }

    const int b_ = m0 >> 12;
#pragma unroll
    for (int mt = 0; mt < 2; mt++) {
        int m  = m0 + wm + (mt << 4) + g;
        int s_ = m & (Sc - 1);
#pragma unroll
        for (int nt = 0; nt < 8; nt++) {
            int n = n0 + wn + (nt << 3) + (tig << 1);
            float bx = bias[n], by = bias[n + 1];
            if (MODE == 0) {
                __half* out = (__half*)outp;
                int h = n >> 6;
                int d = n & 63;
                unsigned u0 = pack_f16x2((c[mt][nt][0] + bx) * scale,
                                         (c[mt][nt][1] + by) * scale);
                unsigned u1 = pack_f16x2((c[mt][nt][2] + bx) * scale,
                                         (c[mt][nt][3] + by) * scale);
                __half* base = out + ((size_t)(b_ * Hc + h) * Sc) * Dc + d;
                *(unsigned*)(base + (size_t)s_ * Dc)       = u0;
                *(unsigned*)(base + (size_t)(s_ + 8) * Dc) = u1;
            } else {
                float* out = (float*)outp;
                *(float2*)(out + (size_t)m * DMc + n) =
                    make_float2(c[mt][nt][0] + bx, c[mt][nt][1] + by);
                *(float2*)(out + (size_t)(m + 8) * DMc + n) =
                    make_float2(c[mt][nt][2] + bx, c[mt][nt][3] + by);
            }
        }
    }
}

__global__ __launch_bounds__(256, 2)
void gemm_qkv(const __half* __restrict__ qh, const __half* __restrict__ kh,
              const __half* __restrict__ vh,
              const __half* __restrict__ Wqh, const __half* __restrict__ Wkh,
              const __half* __restrict__ Wvh,
              const float* __restrict__ bq, const float* __restrict__ bk,
              const float* __restrict__ bv,
              __half* __restrict__ Qp, __half* __restrict__ Kp,
              __half* __restrict__ Vp)
{
    const int z = blockIdx.z;
    const __half* X    = z == 0 ? qh  : (z == 1 ? kh  : vh);
    const __half* W    = z == 0 ? Wqh : (z == 1 ? Wkh : Wvh);
    const float*  bias = z == 0 ? bq  : (z == 1 ? bk  : bv);
    __half*       out  = z == 0 ? Qp  : (z == 1 ? Kp  : Vp);
    gemm_f16_body<0>(X, W, bias, out, z == 0 ? SCL : 1.0f);
}

__global__ __launch_bounds__(256, 2)
void gemm_out(const __half* __restrict__ X, const __half* __restrict__ W,
              const float* __restrict__ bias, float* __restrict__ out)
{
    gemm_f16_body<1>(X, W, bias, out, 1.0f);
}

// ---------------------------------------------------------------------------
// Flash attention, fp16 mma + ldmatrix, cp.async double-buffered K/V.
// Block: 128 threads (4 warps), BQ=128 (32 rows/warp), BK=64, D=64.
// 3 CTAs/SM via __launch_bounds__(128,3); exp'd P packs stored back into c.
// smem halves: Qs[128][72] | Ks[2][64][72] | Vs[2][64][72] | mk[2][64] float
// l carried as a 9th output n-tile (ones-column mma); P via ex2.approx.f16x2.
// ---------------------------------------------------------------------------
#define HSTR 72
#define QS_HALVES (128 * HSTR)
#define KV_STAGE_HALVES (64 * HSTR)
#define KS_HOFF QS_HALVES
#define VS_HOFF (QS_HALVES + 2 * KV_STAGE_HALVES)
#define MK_BYTE_OFF ((QS_HALVES + 4 * KV_STAGE_HALVES) * 2)
#define ATTN_SMEM_BYTES (MK_BYTE_OFF + 2 * 64 * 4)

#define ONES16X2 0x3C003C00u

__global__ __launch_bounds__(128, 3)
void attn_f16(const __half* __restrict__ Qp, const __half* __restrict__ Kp,
              const __half* __restrict__ Vp, const float* __restrict__ mask,
              __half* __restrict__ Ao)
{
    extern __shared__ __align__(16) char smc[];
    __half* Qs = (__half*)smc;
    float*  mk = (float*)(smc + MK_BYTE_OFF);

    const unsigned qs_b = (unsigned)__cvta_generic_to_shared(smc);
    const unsigned ks_b = qs_b + KS_HOFF * 2;
    const unsigned vs_b = qs_b + VS_HOFF * 2;
    const unsigned mk_b = qs_b + MK_BYTE_OFF;

    const int tid  = threadIdx.x;
    const int wid  = tid >> 5;
    const int lane = tid & 31;
    const int g    = lane >> 2;
    const int tig  = lane & 3;
    const int wm   = wid << 5;          // warp's 32-row base
    const int lrow = (lane & 7) + ((lane >> 3) & 1) * 8;
    const int lcol = (lane >> 4) << 3;

    const int bh = blockIdx.y;
    const int b  = bh >> 3;
    const int h  = bh & 7;
    const int q0 = blockIdx.x << 7;

    const __half* Qb = Qp + ((size_t)bh * Sc + q0) * Dc;
    const __half* Kb = Kp + (size_t)bh * Sc * Dc;
    const __half* Vb = Vp + (size_t)bh * Sc * Dc;
    const float*  mb = mask + (size_t)b * Sc;

    // stage issuer: K/V tile t (64 rows) + mask slice into stage s
    auto issue = [&](int t, int s) {
        const __half* Kt = Kb + (size_t)(t << 6) * Dc;
        const __half* Vt = Vb + (size_t)(t << 6) * Dc;
        unsigned ks = ks_b + s * KV_STAGE_HALVES * 2;
        unsigned vs = vs_b + s * KV_STAGE_HALVES * 2;
#pragma unroll
        for (int p = 0; p < 4; p++) {
            int i = tid + (p << 7);
            int r = i >> 3, cc = (i & 7) << 3;
            cp16(ks + (r * HSTR + cc) * 2, Kt + r * Dc + cc);
            cp16(vs + (r * HSTR + cc) * 2, Vt + r * Dc + cc);
        }
        if (tid < 16) cp16(mk_b + s * 256 + tid * 16, mb + (t << 6) + tid * 4);
        cp_commit();
    };

    issue(0, 0);

    // Q tile copy (fp16, already scaled by gemm)
#pragma unroll
    for (int p = 0; p < 8; p++) {
        int i = tid + (p << 7);
        int r = i >> 3, cc = (i & 7) << 3;
        *(uint4*)&Qs[r * HSTR + cc] = *(const uint4*)(Qb + r * Dc + cc);
    }

    float m_i[4] = {-INFINITY, -INFINITY, -INFINITY, -INFINITY};
    // o[mt][8] is the ones-column accumulator = running row sum l
    float o[2][9][4];
#pragma unroll
    for (int mt = 0; mt < 2; mt++)
#pragma unroll
        for (int nt = 0; nt < 9; nt++)
#pragma unroll
            for (int j = 0; j < 4; j++) o[mt][nt][j] = 0.f;

    const int NT = Sc / 64;
    for (int t = 0; t < NT; t++) {
        const int s = t & 1;
        if (t < NT - 1) { issue(t + 1, s ^ 1); cp_wait<1>(); }
        else            { cp_wait<0>(); }
        __syncthreads();

        const unsigned ks_s = ks_b + s * KV_STAGE_HALVES * 2;
        const unsigned vs_s = vs_b + s * KV_STAGE_HALVES * 2;
        const float*   mks  = mk + s * 64;

        // ---- S = Q @ K^T ----
        float c[2][8][4];
#pragma unroll
        for (int mt = 0; mt < 2; mt++)
#pragma unroll
            for (int nt = 0; nt < 8; nt++)
#pragma unroll
                for (int j = 0; j < 4; j++) c[mt][nt][j] = 0.f;

#pragma unroll
        for (int kb4 = 0; kb4 < 4; kb4++) {
            const int kb = kb4 << 4;
            unsigned a[2][4];
#pragma unroll
            for (int mt = 0; mt < 2; mt++) {
                unsigned addr = qs_b +
                    (((wm + (mt << 4) + lrow) * HSTR) + kb + lcol) * 2;
                ldsm_x4(a[mt][0], a[mt][1], a[mt][2], a[mt][3], addr);
            }
#pragma unroll
            for (int np = 0; np < 4; np++) {
                unsigned addr = ks_s +
                    ((((np << 4) + lrow) * HSTR) + kb + lcol) * 2;
                unsigned b0e, b0o, b1e, b1o;
                ldsm_x4(b0e, b0o, b1e, b1o, addr);
                mma_f16(c[0][2 * np],     a[0][0], a[0][1], a[0][2], a[0][3], b0e, b1e);
                mma_f16(c[0][2 * np + 1], a[0][0], a[0][1], a[0][2], a[0][3], b0o, b1o);
                mma_f16(c[1][2 * np],     a[1][0], a[1][1], a[1][2], a[1][3], b0e, b1e);
                mma_f16(c[1][2 * np + 1], a[1][0], a[1][1], a[1][2], a[1][3], b0o, b1o);
            }
        }

        // ---- mask + online softmax (log2 domain, fp16x2 exp) ----
        // exp'd packs are stored back into c[mt][nt][0..1] (register reuse)
#pragma unroll
        for (int mt = 0; mt < 2; mt++) {
            float vmax0 = -INFINITY, vmax1 = -INFINITY;
#pragma unroll
            for (int nt = 0; nt < 8; nt++) {
                float2 mv = *(const float2*)&mks[(nt << 3) + (tig << 1)];
                c[mt][nt][0] = fmaf(mv.x, MSK, c[mt][nt][0]);
                c[mt][nt][1] = fmaf(mv.y, MSK, c[mt][nt][1]);
                c[mt][nt][2] = fmaf(mv.x, MSK, c[mt][nt][2]);
                c[mt][nt][3] = fmaf(mv.y, MSK, c[mt][nt][3]);
                vmax0 = fmaxf(vmax0, fmaxf(c[mt][nt][0], c[mt][nt][1]));
                vmax1 = fmaxf(vmax1, fmaxf(c[mt][nt][2], c[mt][nt][3]));
            }
            vmax0 = fmaxf(vmax0, __shfl_xor_sync(0xffffffffu, vmax0, 1));
            vmax0 = fmaxf(vmax0, __shfl_xor_sync(0xffffffffu, vmax0, 2));
            vmax1 = fmaxf(vmax1, __shfl_xor_sync(0xffffffffu, vmax1, 1));
            vmax1 = fmaxf(vmax1, __shfl_xor_sync(0xffffffffu, vmax1, 2));

            float mn0 = fmaxf(m_i[mt * 2 + 0], vmax0);
            float mn1 = fmaxf(m_i[mt * 2 + 1], vmax1);
            float al0 = ex2(m_i[mt * 2 + 0] - mn0);
            float al1 = ex2(m_i[mt * 2 + 1] - mn1);
            m_i[mt * 2 + 0] = mn0;
            m_i[mt * 2 + 1] = mn1;

            // pack (s - mn) pairs, exponentiate in f16x2, store into c[..][0..1]
#pragma unroll
            for (int nt = 0; nt < 8; nt++) {
                unsigned e0 = ex2_f16x2(
                    pack_f16x2(c[mt][nt][0] - mn0, c[mt][nt][1] - mn0));
                unsigned e1 = ex2_f16x2(
                    pack_f16x2(c[mt][nt][2] - mn1, c[mt][nt][3] - mn1));
                c[mt][nt][0] = __uint_as_float(e0);
                c[mt][nt][1] = __uint_as_float(e1);
            }
            // rescale O and the l-column
#pragma unroll
            for (int nt = 0; nt < 9; nt++) {
                o[mt][nt][0] *= al0; o[mt][nt][1] *= al0;
                o[mt][nt][2] *= al1; o[mt][nt][3] *= al1;
            }
        }

        // ---- O += P @ V ;  l-column += P @ ones ----
#pragma unroll
        for (int kb4 = 0; kb4 < 4; kb4++) {
            unsigned pa[2][4];
#pragma unroll
            for (int mt = 0; mt < 2; mt++) {
                pa[mt][0] = __float_as_uint(c[mt][2 * kb4][0]);
                pa[mt][1] = __float_as_uint(c[mt][2 * kb4][1]);
                pa[mt][2] = __float_as_uint(c[mt][2 * kb4 + 1][0]);
                pa[mt][3] = __float_as_uint(c[mt][2 * kb4 + 1][1]);
            }
#pragma unroll
            for (int dp = 0; dp < 4; dp++) {
                unsigned addr = vs_s +
                    ((((kb4 << 4) + lrow) * HSTR) + (dp << 4) + lcol) * 2;
                unsigned r0, r1, r2, r3;
                ldsm_x4_t(r0, r1, r2, r3, addr);
                mma_f16(o[0][2 * dp],     pa[0][0], pa[0][1], pa[0][2], pa[0][3], r0, r1);
                mma_f16(o[0][2 * dp + 1], pa[0][0], pa[0][1], pa[0][2], pa[0][3], r2, r3);
                mma_f16(o[1][2 * dp],     pa[1][0], pa[1][1], pa[1][2], pa[1][3], r0, r1);
                mma_f16(o[1][2 * dp + 1], pa[1][0], pa[1][1], pa[1][2], pa[1][3], r2, r3);
            }
            mma_f16(o[0][8], pa[0][0], pa[0][1], pa[0][2], pa[0][3],
                    ONES16X2, ONES16X2);
            mma_f16(o[1][8], pa[1][0], pa[1][1], pa[1][2], pa[1][3],
                    ONES16X2, ONES16X2);
        }
        __syncthreads();
    }

    // ---- epilogue: normalize by l (ones-column), write fp16 Ao ----
    __half* AoB = Ao + ((size_t)b * Sc) * DMc + h * Dc;
#pragma unroll
    for (int mt = 0; mt < 2; mt++) {
        float inv0 = 1.f / o[mt][8][0];
        float inv1 = 1.f / o[mt][8][2];
        int r0 = q0 + wm + (mt << 4) + g;
#pragma unroll
        for (int nt = 0; nt < 8; nt++) {
            int d = (nt << 3) + (tig << 1);
            *(unsigned*)(AoB + (size_t)r0 * DMc + d) =
                pack_f16x2(o[mt][nt][0] * inv0, o[mt][nt][1] * inv0);
            *(unsigned*)(AoB + (size_t)(r0 + 8) * DMc + d) =
                pack_f16x2(o[mt][nt][2] * inv1, o[mt][nt][3] * inv1);
        }
    }
}

// ---------------------------------------------------------------------------
extern "C" void kernel_launch(void* const* d_in, const int* in_sizes, int n_in,
                              void* d_out, int out_size)
{
    const float* q    = (const float*)d_in[0];
    const float* k    = (const float*)d_in[1];
    const float* v    = (const float*)d_in[2];
    const float* mask = (const float*)d_in[3];
    const float* Wq   = (const float*)d_in[4];
    const float* bq   = (const float*)d_in[5];
    const float* Wk   = (const float*)d_in[6];
    const float* bk   = (const float*)d_in[7];
    const float* Wv   = (const float*)d_in[8];
    const float* bv   = (const float*)d_in[9];
    const float* Wo   = (const float*)d_in[10];
    const float* bo   = (const float*)d_in[11];
    float* out = (float*)d_out;

    __half *qh, *kh, *vh, *Wqh, *Wkh, *Wvh, *Woh, *Qp, *Kp, *Vp, *Ao;
    cudaGetSymbolAddress((void**)&qh,  g_qh);
    cudaGetSymbolAddress((void**)&kh,  g_kh);
    cudaGetSymbolAddress((void**)&vh,  g_vh);
    cudaGetSymbolAddress((void**)&Wqh, g_Wqh);
    cudaGetSymbolAddress((void**)&Wkh, g_Wkh);
    cudaGetSymbolAddress((void**)&Wvh, g_Wvh);
    cudaGetSymbolAddress((void**)&Woh, g_Woh);
    cudaGetSymbolAddress((void**)&Qp,  g_Qp);
    cudaGetSymbolAddress((void**)&Kp,  g_Kp);
    cudaGetSymbolAddress((void**)&Vp,  g_Vp);
    cudaGetSymbolAddress((void**)&Ao,  g_Ao);

    cudaFuncSetAttribute(attn_f16, cudaFuncAttributeMaxDynamicSharedMemorySize,
                         ATTN_SMEM_BYTES);

    dim3 gin(Mc * DMc / 4 / 256, 1, 3);     // (4096,1,3)
    cvt_in<<<gin, 256>>>(q, k, v, qh, kh, vh);
    dim3 gw(DMc * DMc / 4 / 256, 1, 4);     // (256,1,4)
    cvt_w<<<gw, 256>>>(Wq, Wk, Wv, Wo, Wqh, Wkh, Wvh, Woh);

    dim3 gqkv(DMc / 128, Mc / 128, 3);      // (4, 64, 3)
    gemm_qkv<<<gqkv, 256>>>(qh, kh, vh, Wqh, Wkh, Wvh, bq, bk, bv, Qp, Kp, Vp);

    dim3 ga(Sc / 128, Bc * Hc);             // (32, 16)
    attn_f16<<<ga, 128, ATTN_SMEM_BYTES>>>(Qp, Kp, Vp, mask, Ao);

    dim3 gg(DMc / 128, Mc / 128);           // (4, 64)
    gemm_out<<<gg, 256>>>(Ao, Woh, bo, out);
}

// round 10
// speedup vs baseline: 1.1241x; 1.1241x over previous
#include <cuda_runtime.h>
#include <cuda_fp16.h>
#include <math.h>

#define Bc  2
#define Sc  4096
#define DMc 512
#define Hc  8
#define Dc  64
#define Mc  (Bc * Sc)   // 8192

#define SCL (0.125f * 1.44269504f)
#define MSK (-1.44269504e9f)

// fp16 mirrors of inputs/weights + fp16 scratch
__device__ __half g_qh[Mc * DMc];
__device__ __half g_kh[Mc * DMc];
__device__ __half g_vh[Mc * DMc];
__device__ __half g_Wqh[DMc * DMc];
__device__ __half g_Wkh[DMc * DMc];
__device__ __half g_Wvh[DMc * DMc];
__device__ __half g_Woh[DMc * DMc];
__device__ __half g_Qp[Bc * Hc * Sc * Dc];
__device__ __half g_Kp[Bc * Hc * Sc * Dc];
__device__ __half g_Vp[Bc * Hc * Sc * Dc];
__device__ __half g_Ao[Mc * DMc];

// ---------------------------------------------------------------------------
// helpers
// ---------------------------------------------------------------------------
__device__ __forceinline__ unsigned pack_f16x2(float lo, float hi) {
    unsigned r;
    asm("cvt.rn.f16x2.f32 %0, %1, %2;" : "=r"(r) : "f"(hi), "f"(lo));
    return r;
}

__device__ __forceinline__ float ex2(float x) {
    float r;
    asm("ex2.approx.f32 %0, %1;" : "=f"(r) : "f"(x));
    return r;
}

__device__ __forceinline__ unsigned ex2_f16x2(unsigned x) {
    unsigned r;
    asm("ex2.approx.f16x2 %0, %1;" : "=r"(r) : "r"(x));
    return r;
}

__device__ __forceinline__ void cp16(unsigned dst, const void* src) {
    asm volatile("cp.async.cg.shared.global [%0], [%1], 16;"
                 :: "r"(dst), "l"(__cvta_generic_to_global(src)));
}
__device__ __forceinline__ void cp_commit() {
    asm volatile("cp.async.commit_group;");
}
template <int N>
__device__ __forceinline__ void cp_wait() {
    asm volatile("cp.async.wait_group %0;" :: "n"(N));
}

__device__ __forceinline__ void ldsm_x4(unsigned& r0, unsigned& r1,
                                        unsigned& r2, unsigned& r3,
                                        unsigned addr) {
    asm volatile("ldmatrix.sync.aligned.m8n8.x4.shared.b16 {%0,%1,%2,%3}, [%4];"
                 : "=r"(r0), "=r"(r1), "=r"(r2), "=r"(r3) : "r"(addr));
}
__device__ __forceinline__ void ldsm_x4_t(unsigned& r0, unsigned& r1,
                                          unsigned& r2, unsigned& r3,
                                          unsigned addr) {
    asm volatile("ldmatrix.sync.aligned.m8n8.x4.trans.shared.b16 {%0,%1,%2,%3}, [%4];"
                 : "=r"(r0), "=r"(r1), "=r"(r2), "=r"(r3) : "r"(addr));
}
__device__ __forceinline__ void mma_f16(float c[4], unsigned a0, unsigned a1,
                                        unsigned a2, unsigned a3,
                                        unsigned b0, unsigned b1) {
    asm volatile(
        "mma.sync.aligned.m16n8k16.row.col.f32.f16.f16.f32 "
        "{%0,%1,%2,%3}, {%4,%5,%6,%7}, {%8,%9}, {%0,%1,%2,%3};\n"
        : "+f"(c[0]), "+f"(c[1]), "+f"(c[2]), "+f"(c[3])
        : "r"(a0), "r"(a1), "r"(a2), "r"(a3), "r"(b0), "r"(b1));
}

// ---------------------------------------------------------------------------
// fp32 -> fp16 conversion pre-pass
// ---------------------------------------------------------------------------
__global__ __launch_bounds__(256)
void cvt_in(const float* __restrict__ q, const float* __restrict__ k,
            const float* __restrict__ v,
            __half* __restrict__ qh, __half* __restrict__ kh,
            __half* __restrict__ vh)
{
    const int z = blockIdx.z;
    const float* s = z == 0 ? q  : (z == 1 ? k  : v);
    __half*      d = z == 0 ? qh : (z == 1 ? kh : vh);
    int i = blockIdx.x * 256 + threadIdx.x;          // float4 index
    float4 f = ((const float4*)s)[i];
    ((uint2*)d)[i] = make_uint2(pack_f16x2(f.x, f.y), pack_f16x2(f.z, f.w));
}

__global__ __launch_bounds__(256)
void cvt_w(const float* __restrict__ Wq, const float* __restrict__ Wk,
           const float* __restrict__ Wv, const float* __restrict__ Wo,
           __half* __restrict__ Wqh, __half* __restrict__ Wkh,
           __half* __restrict__ Wvh, __half* __restrict__ Woh)
{
    const int z = blockIdx.z;
    const float* s = z == 0 ? Wq  : (z == 1 ? Wk  : (z == 2 ? Wv  : Wo));
    __half*      d = z == 0 ? Wqh : (z == 1 ? Wkh : (z == 2 ? Wvh : Woh));
    int i = blockIdx.x * 256 + threadIdx.x;
    float4 f = ((const float4*)s)[i];
    ((uint2*)d)[i] = make_uint2(pack_f16x2(f.x, f.y), pack_f16x2(f.z, f.w));
}

// ---------------------------------------------------------------------------
// pure-fp16 GEMM, cp.async double-buffered. C = X @ W (+bias) [*scale].
// Block 128x128, BK=32, 8 warps (4m x 2n), warp tile 32x64.
// MODE 0: __half out, head-split layout, scale applied.
// MODE 1: float out, row-major.
// ---------------------------------------------------------------------------
#define ASTR 40
#define BSTR 136
#define A_BYTES (128 * ASTR * 2)
#define B_BYTES (32 * BSTR * 2)
#define STAGE_BYTES (A_BYTES + B_BYTES)

template <int MODE>
__device__ __forceinline__ void gemm_f16_body(
    const __half* __restrict__ X, const __half* __restrict__ W,
    const float* __restrict__ bias, void* outp, float scale)
{
    __shared__ __align__(16) char sh[2 * STAGE_BYTES];

    const int tid  = threadIdx.x;
    const int wid  = tid >> 5;
    const int lane = tid & 31;
    const int g    = lane >> 2;
    const int tig  = lane & 3;
    const int wm   = (wid & 3) << 5;
    const int wn   = (wid >> 2) << 6;
    const int lrow = (lane & 7) + ((lane >> 3) & 1) * 8;
    const int lcol = (lane >> 4) << 3;

    const int m0 = blockIdx.y << 7;
    const int n0 = blockIdx.x << 7;

    const unsigned sh_b = (unsigned)__cvta_generic_to_shared(sh);

    float c[2][8][4];
#pragma unroll
    for (int mt = 0; mt < 2; mt++)
#pragma unroll
        for (int nt = 0; nt < 8; nt++)
#pragma unroll
            for (int j = 0; j < 4; j++) c[mt][nt][j] = 0.f;

    auto issue = [&](int k0, int s) {
        unsigned as = sh_b + s * STAGE_BYTES;
        unsigned bs = as + A_BYTES;
#pragma unroll
        for (int p = 0; p < 2; p++) {
            int i = tid + (p << 8);
            int r = i >> 2, cc = (i & 3) << 3;
            cp16(as + (r * ASTR + cc) * 2, X + (size_t)(m0 + r) * DMc + k0 + cc);
        }
#pragma unroll
        for (int p = 0; p < 2; p++) {
            int i = tid + (p << 8);
            int r = i >> 4, cc = (i & 15) << 3;
            cp16(bs + (r * BSTR + cc) * 2, W + (size_t)(k0 + r) * DMc + n0 + cc);
        }
        cp_commit();
    };

    issue(0, 0);
    int buf = 0;
    for (int kc = 0; kc < 16; kc++) {
        if (kc < 15) { issue((kc + 1) << 5, buf ^ 1); cp_wait<1>(); }
        else         { cp_wait<0>(); }
        __syncthreads();

        const unsigned as_b = sh_b + buf * STAGE_BYTES;
        const unsigned bs_b = as_b + A_BYTES;
#pragma unroll
        for (int ks = 0; ks < 2; ks++) {
            const int kb = ks << 4;
            unsigned a[2][4];
#pragma unroll
            for (int mt = 0; mt < 2; mt++) {
                unsigned addr = as_b +
                    (((wm + (mt << 4) + lrow) * ASTR) + kb + lcol) * 2;
                ldsm_x4(a[mt][0], a[mt][1], a[mt][2], a[mt][3], addr);
            }
#pragma unroll
            for (int np = 0; np < 4; np++) {
                unsigned addr = bs_b +
                    (((kb + lrow) * BSTR) + wn + (np << 4) + lcol) * 2;
                unsigned r0, r1, r2, r3;
                ldsm_x4_t(r0, r1, r2, r3, addr);
                mma_f16(c[0][2 * np],     a[0][0], a[0][1], a[0][2], a[0][3], r0, r1);
                mma_f16(c[0][2 * np + 1], a[0][0], a[0][1], a[0][2], a[0][3], r2, r3);
                mma_f16(c[1][2 * np],     a[1][0], a[1][1], a[1][2], a[1][3], r0, r1);
                mma_f16(c[1][2 * np + 1], a[1][0], a[1][1], a[1][2], a[1][3], r2, r3);
            }
        }
        __syncthreads();
        buf ^= 1;
    }

    const int b_ = m0 >> 12;
#pragma unroll
    for (int mt = 0; mt < 2; mt++) {
        int m  = m0 + wm + (mt << 4) + g;
        int s_ = m & (Sc - 1);
#pragma unroll
        for (int nt = 0; nt < 8; nt++) {
            int n = n0 + wn + (nt << 3) + (tig << 1);
            float bx = bias[n], by = bias[n + 1];
            if (MODE == 0) {
                __half* out = (__half*)outp;
                int h = n >> 6;
                int d = n & 63;
                unsigned u0 = pack_f16x2((c[mt][nt][0] + bx) * scale,
                                         (c[mt][nt][1] + by) * scale);
                unsigned u1 = pack_f16x2((c[mt][nt][2] + bx) * scale,
                                         (c[mt][nt][3] + by) * scale);
                __half* base = out + ((size_t)(b_ * Hc + h) * Sc) * Dc + d;
                *(unsigned*)(base + (size_t)s_ * Dc)       = u0;
                *(unsigned*)(base + (size_t)(s_ + 8) * Dc) = u1;
            } else {
                float* out = (float*)outp;
                *(float2*)(out + (size_t)m * DMc + n) =
                    make_float2(c[mt][nt][0] + bx, c[mt][nt][1] + by);
                *(float2*)(out + (size_t)(m + 8) * DMc + n) =
                    make_float2(c[mt][nt][2] + bx, c[mt][nt][3] + by);
            }
        }
    }
}

__global__ __launch_bounds__(256, 2)
void gemm_qkv(const __half* __restrict__ qh, const __half* __restrict__ kh,
              const __half* __restrict__ vh,
              const __half* __restrict__ Wqh, const __half* __restrict__ Wkh,
              const __half* __restrict__ Wvh,
              const float* __restrict__ bq, const float* __restrict__ bk,
              const float* __restrict__ bv,
              __half* __restrict__ Qp, __half* __restrict__ Kp,
              __half* __restrict__ Vp)
{
    const int z = blockIdx.z;
    const __half* X    = z == 0 ? qh  : (z == 1 ? kh  : vh);
    const __half* W    = z == 0 ? Wqh : (z == 1 ? Wkh : Wvh);
    const float*  bias = z == 0 ? bq  : (z == 1 ? bk  : bv);
    __half*       out  = z == 0 ? Qp  : (z == 1 ? Kp  : Vp);
    gemm_f16_body<0>(X, W, bias, out, z == 0 ? SCL : 1.0f);
}

__global__ __launch_bounds__(256, 2)
void gemm_out(const __half* __restrict__ X, const __half* __restrict__ W,
              const float* __restrict__ bias, float* __restrict__ out)
{
    gemm_f16_body<1>(X, W, bias, out, 1.0f);
}

// ---------------------------------------------------------------------------
// Flash attention, fp16 mma + ldmatrix, cp.async double-buffered K/V.
// Block: 128 threads (4 warps), BQ=128 (32 rows/warp), BK=64, D=64.
// EPOCH-MAX: the running max / O-rescale is refreshed only every 4th tile;
// in between, the stale max is a valid uniform upper-bound shift (fp16 exp
// headroom ~2^15 makes overflow a >10-sigma event).
// smem halves: Qs[128][72] | Ks[2][64][72] | Vs[2][64][72] | mk[2][64] float
// l carried as a 9th output n-tile (ones-column mma); P via ex2.approx.f16x2.
// ---------------------------------------------------------------------------
#define HSTR 72
#define QS_HALVES (128 * HSTR)
#define KV_STAGE_HALVES (64 * HSTR)
#define KS_HOFF QS_HALVES
#define VS_HOFF (QS_HALVES + 2 * KV_STAGE_HALVES)
#define MK_BYTE_OFF ((QS_HALVES + 4 * KV_STAGE_HALVES) * 2)
#define ATTN_SMEM_BYTES (MK_BYTE_OFF + 2 * 64 * 4)

#define ONES16X2 0x3C003C00u

__global__ __launch_bounds__(128, 2)
void attn_f16(const __half* __restrict__ Qp, const __half* __restrict__ Kp,
              const __half* __restrict__ Vp, const float* __restrict__ mask,
              __half* __restrict__ Ao)
{
    extern __shared__ __align__(16) char smc[];
    __half* Qs = (__half*)smc;
    float*  mk = (float*)(smc + MK_BYTE_OFF);

    const unsigned qs_b = (unsigned)__cvta_generic_to_shared(smc);
    const unsigned ks_b = qs_b + KS_HOFF * 2;
    const unsigned vs_b = qs_b + VS_HOFF * 2;
    const unsigned mk_b = qs_b + MK_BYTE_OFF;

    const int tid  = threadIdx.x;
    const int wid  = tid >> 5;
    const int lane = tid & 31;
    const int g    = lane >> 2;
    const int tig  = lane & 3;
    const int wm   = wid << 5;          // warp's 32-row base
    const int lrow = (lane & 7) + ((lane >> 3) & 1) * 8;
    const int lcol = (lane >> 4) << 3;

    const int bh = blockIdx.y;
    const int b  = bh >> 3;
    const int h  = bh & 7;
    const int q0 = blockIdx.x << 7;

    const __half* Qb = Qp + ((size_t)bh * Sc + q0) * Dc;
    const __half* Kb = Kp + (size_t)bh * Sc * Dc;
    const __half* Vb = Vp + (size_t)bh * Sc * Dc;
    const float*  mb = mask + (size_t)b * Sc;

    // stage issuer: K/V tile t (64 rows) + mask slice into stage s
    auto issue = [&](int t, int s) {
        const __half* Kt = Kb + (size_t)(t << 6) * Dc;
        const __half* Vt = Vb + (size_t)(t << 6) * Dc;
        unsigned ks = ks_b + s * KV_STAGE_HALVES * 2;
        unsigned vs = vs_b + s * KV_STAGE_HALVES * 2;
#pragma unroll
        for (int p = 0; p < 4; p++) {
            int i = tid + (p << 7);
            int r = i >> 3, cc = (i & 7) << 3;
            cp16(ks + (r * HSTR + cc) * 2, Kt + r * Dc + cc);
            cp16(vs + (r * HSTR + cc) * 2, Vt + r * Dc + cc);
        }
        if (tid < 16) cp16(mk_b + s * 256 + tid * 16, mb + (t << 6) + tid * 4);
        cp_commit();
    };

    issue(0, 0);

    // Q tile copy (fp16, already scaled by gemm)
#pragma unroll
    for (int p = 0; p < 8; p++) {
        int i = tid + (p << 7);
        int r = i >> 3, cc = (i & 7) << 3;
        *(uint4*)&Qs[r * HSTR + cc] = *(const uint4*)(Qb + r * Dc + cc);
    }

    float m_i[4] = {-INFINITY, -INFINITY, -INFINITY, -INFINITY};
    // o[mt][8] is the ones-column accumulator = running row sum l
    float o[2][9][4];
#pragma unroll
    for (int mt = 0; mt < 2; mt++)
#pragma unroll
        for (int nt = 0; nt < 9; nt++)
#pragma unroll
            for (int j = 0; j < 4; j++) o[mt][nt][j] = 0.f;

    const int NT = Sc / 64;
    for (int t = 0; t < NT; t++) {
        const int s = t & 1;
        if (t < NT - 1) { issue(t + 1, s ^ 1); cp_wait<1>(); }
        else            { cp_wait<0>(); }
        __syncthreads();

        const unsigned ks_s = ks_b + s * KV_STAGE_HALVES * 2;
        const unsigned vs_s = vs_b + s * KV_STAGE_HALVES * 2;
        const float*   mks  = mk + s * 64;

        // ---- S = Q @ K^T ----
        float c[2][8][4];
#pragma unroll
        for (int mt = 0; mt < 2; mt++)
#pragma unroll
            for (int nt = 0; nt < 8; nt++)
#pragma unroll
                for (int j = 0; j < 4; j++) c[mt][nt][j] = 0.f;

#pragma unroll
        for (int kb4 = 0; kb4 < 4; kb4++) {
            const int kb = kb4 << 4;
            unsigned a[2][4];
#pragma unroll
            for (int mt = 0; mt < 2; mt++) {
                unsigned addr = qs_b +
                    (((wm + (mt << 4) + lrow) * HSTR) + kb + lcol) * 2;
                ldsm_x4(a[mt][0], a[mt][1], a[mt][2], a[mt][3], addr);
            }
#pragma unroll
            for (int np = 0; np < 4; np++) {
                unsigned addr = ks_s +
                    ((((np << 4) + lrow) * HSTR) + kb + lcol) * 2;
                unsigned b0e, b0o, b1e, b1o;
                ldsm_x4(b0e, b0o, b1e, b1o, addr);
                mma_f16(c[0][2 * np],     a[0][0], a[0][1], a[0][2], a[0][3], b0e, b1e);
                mma_f16(c[0][2 * np + 1], a[0][0], a[0][1], a[0][2], a[0][3], b0o, b1o);
                mma_f16(c[1][2 * np],     a[1][0], a[1][1], a[1][2], a[1][3], b0e, b1e);
                mma_f16(c[1][2 * np + 1], a[1][0], a[1][1], a[1][2], a[1][3], b0o, b1o);
            }
        }

        // ---- mask (fp32 FMA, mask shared across mt via CSE) ----
#pragma unroll
        for (int mt = 0; mt < 2; mt++)
#pragma unroll
            for (int nt = 0; nt < 8; nt++) {
                float2 mv = *(const float2*)&mks[(nt << 3) + (tig << 1)];
                c[mt][nt][0] = fmaf(mv.x, MSK, c[mt][nt][0]);
                c[mt][nt][1] = fmaf(mv.y, MSK, c[mt][nt][1]);
                c[mt][nt][2] = fmaf(mv.x, MSK, c[mt][nt][2]);
                c[mt][nt][3] = fmaf(mv.y, MSK, c[mt][nt][3]);
            }

        // ---- epoch boundary: refresh running max, rescale O + l ----
        if ((t & 3) == 0) {
#pragma unroll
            for (int mt = 0; mt < 2; mt++) {
                float vmax0 = -INFINITY, vmax1 = -INFINITY;
#pragma unroll
                for (int nt = 0; nt < 8; nt++) {
                    vmax0 = fmaxf(vmax0, fmaxf(c[mt][nt][0], c[mt][nt][1]));
                    vmax1 = fmaxf(vmax1, fmaxf(c[mt][nt][2], c[mt][nt][3]));
                }
                vmax0 = fmaxf(vmax0, __shfl_xor_sync(0xffffffffu, vmax0, 1));
                vmax0 = fmaxf(vmax0, __shfl_xor_sync(0xffffffffu, vmax0, 2));
                vmax1 = fmaxf(vmax1, __shfl_xor_sync(0xffffffffu, vmax1, 1));
                vmax1 = fmaxf(vmax1, __shfl_xor_sync(0xffffffffu, vmax1, 2));

                float mn0 = fmaxf(m_i[mt * 2 + 0], vmax0);
                float mn1 = fmaxf(m_i[mt * 2 + 1], vmax1);
                float al0 = ex2(m_i[mt * 2 + 0] - mn0);
                float al1 = ex2(m_i[mt * 2 + 1] - mn1);
                m_i[mt * 2 + 0] = mn0;
                m_i[mt * 2 + 1] = mn1;
#pragma unroll
                for (int nt = 0; nt < 9; nt++) {
                    o[mt][nt][0] *= al0; o[mt][nt][1] *= al0;
                    o[mt][nt][2] *= al1; o[mt][nt][3] *= al1;
                }
            }
        }

        // ---- exp (log2 domain, fp16x2) with current epoch max ----
        unsigned pu[2][8][2];
#pragma unroll
        for (int mt = 0; mt < 2; mt++) {
            float mn0 = m_i[mt * 2 + 0];
            float mn1 = m_i[mt * 2 + 1];
#pragma unroll
            for (int nt = 0; nt < 8; nt++) {
                pu[mt][nt][0] = ex2_f16x2(
                    pack_f16x2(c[mt][nt][0] - mn0, c[mt][nt][1] - mn0));
                pu[mt][nt][1] = ex2_f16x2(
                    pack_f16x2(c[mt][nt][2] - mn1, c[mt][nt][3] - mn1));
            }
        }

        // ---- O += P @ V ;  l-column += P @ ones ----
#pragma unroll
        for (int kb4 = 0; kb4 < 4; kb4++) {
            unsigned pa[2][4];
#pragma unroll
            for (int mt = 0; mt < 2; mt++) {
                pa[mt][0] = pu[mt][2 * kb4][0];
                pa[mt][1] = pu[mt][2 * kb4][1];
                pa[mt][2] = pu[mt][2 * kb4 + 1][0];
                pa[mt][3] = pu[mt][2 * kb4 + 1][1];
            }
#pragma unroll
            for (int dp = 0; dp < 4; dp++) {
                unsigned addr = vs_s +
                    ((((kb4 << 4) + lrow) * HSTR) + (dp << 4) + lcol) * 2;
                unsigned r0, r1, r2, r3;
                ldsm_x4_t(r0, r1, r2, r3, addr);
                mma_f16(o[0][2 * dp],     pa[0][0], pa[0][1], pa[0][2], pa[0][3], r0, r1);
                mma_f16(o[0][2 * dp + 1], pa[0][0], pa[0][1], pa[0][2], pa[0][3], r2, r3);
                mma_f16(o[1][2 * dp],     pa[1][0], pa[1][1], pa[1][2], pa[1][3], r0, r1);
                mma_f16(o[1][2 * dp + 1], pa[1][0], pa[1][1], pa[1][2], pa[1][3], r2, r3);
            }
            mma_f16(o[0][8], pa[0][0], pa[0][1], pa[0][2], pa[0][3],
                    ONES16X2, ONES16X2);
            mma_f16(o[1][8], pa[1][0], pa[1][1], pa[1][2], pa[1][3],
                    ONES16X2, ONES16X2);
        }
        __syncthreads();
    }

    // ---- epilogue: normalize by l (ones-column), write fp16 Ao ----
    __half* AoB = Ao + ((size_t)b * Sc) * DMc + h * Dc;
#pragma unroll
    for (int mt = 0; mt < 2; mt++) {
        float inv0 = 1.f / o[mt][8][0];
        float inv1 = 1.f / o[mt][8][2];
        int r0 = q0 + wm + (mt << 4) + g;
#pragma unroll
        for (int nt = 0; nt < 8; nt++) {
            int d = (nt << 3) + (tig << 1);
            *(unsigned*)(AoB + (size_t)r0 * DMc + d) =
                pack_f16x2(o[mt][nt][0] * inv0, o[mt][nt][1] * inv0);
            *(unsigned*)(AoB + (size_t)(r0 + 8) * DMc + d) =
                pack_f16x2(o[mt][nt][2] * inv1, o[mt][nt][3] * inv1);
        }
    }
}

// ---------------------------------------------------------------------------
extern "C" void kernel_launch(void* const* d_in, const int* in_sizes, int n_in,
                              void* d_out, int out_size)
{
    const float* q    = (const float*)d_in[0];
    const float* k    = (const float*)d_in[1];
    const float* v    = (const float*)d_in[2];
    const float* mask = (const float*)d_in[3];
    const float* Wq   = (const float*)d_in[4];
    const float* bq   = (const float*)d_in[5];
    const float* Wk   = (const float*)d_in[6];
    const float* bk   = (const float*)d_in[7];
    const float* Wv   = (const float*)d_in[8];
    const float* bv   = (const float*)d_in[9];
    const float* Wo   = (const float*)d_in[10];
    const float* bo   = (const float*)d_in[11];
    float* out = (float*)d_out;

    __half *qh, *kh, *vh, *Wqh, *Wkh, *Wvh, *Woh, *Qp, *Kp, *Vp, *Ao;
    cudaGetSymbolAddress((void**)&qh,  g_qh);
    cudaGetSymbolAddress((void**)&kh,  g_kh);
    cudaGetSymbolAddress((void**)&vh,  g_vh);
    cudaGetSymbolAddress((void**)&Wqh, g_Wqh);
    cudaGetSymbolAddress((void**)&Wkh, g_Wkh);
    cudaGetSymbolAddress((void**)&Wvh, g_Wvh);
    cudaGetSymbolAddress((void**)&Woh, g_Woh);
    cudaGetSymbolAddress((void**)&Qp,  g_Qp);
    cudaGetSymbolAddress((void**)&Kp,  g_Kp);
    cudaGetSymbolAddress((void**)&Vp,  g_Vp);
    cudaGetSymbolAddress((void**)&Ao,  g_Ao);

    cudaFuncSetAttribute(attn_f16, cudaFuncAttributeMaxDynamicSharedMemorySize,
                         ATTN_SMEM_BYTES);

    dim3 gin(Mc * DMc / 4 / 256, 1, 3);     // (4096,1,3)
    cvt_in<<<gin, 256>>>(q, k, v, qh, kh, vh);
    dim3 gw(DMc * DMc / 4 / 256, 1, 4);     // (256,1,4)
    cvt_w<<<gw, 256>>>(Wq, Wk, Wv, Wo, Wqh, Wkh, Wvh, Woh);

    dim3 gqkv(DMc / 128, Mc / 128, 3);      // (4, 64, 3)
    gemm_qkv<<<gqkv, 256>>>(qh, kh, vh, Wqh, Wkh, Wvh, bq, bk, bv, Qp, Kp, Vp);

    dim3 ga(Sc / 128, Bc * Hc);             // (32, 16)
    attn_f16<<<ga, 128, ATTN_SMEM_BYTES>>>(Qp, Kp, Vp, mask, Ao);

    dim3 gg(DMc / 128, Mc / 128);           // (4, 64)
    gemm_out<<<gg, 256>>>(Ao, Woh, bo, out);
}

// round 11
// speedup vs baseline: 1.1364x; 1.0109x over previous
#include <cuda_runtime.h>
#include <cuda_fp16.h>
#include <math.h>

#define Bc  2
#define Sc  4096
#define DMc 512
#define Hc  8
#define Dc  64
#define Mc  (Bc * Sc)   // 8192

#define SCL (0.125f * 1.44269504f)

// fp16 mirrors of inputs/weights + fp16 scratch
__device__ __half g_qh[Mc * DMc];
__device__ __half g_kh[Mc * DMc];
__device__ __half g_vh[Mc * DMc];
__device__ __half g_Wqh[DMc * DMc];
__device__ __half g_Wkh[DMc * DMc];
__device__ __half g_Wvh[DMc * DMc];
__device__ __half g_Woh[DMc * DMc];
__device__ __half g_Qp[Bc * Hc * Sc * Dc];
__device__ __half g_Kp[Bc * Hc * Sc * Dc];
__device__ __half g_Vp[Bc * Hc * Sc * Dc];
__device__ __half g_Ao[Mc * DMc];
__device__ __half g_mkh[Bc * Sc];          // mask as f16: 0 or -inf

// ---------------------------------------------------------------------------
// helpers
// ---------------------------------------------------------------------------
__device__ __forceinline__ unsigned pack_f16x2(float lo, float hi) {
    unsigned r;
    asm("cvt.rn.f16x2.f32 %0, %1, %2;" : "=r"(r) : "f"(hi), "f"(lo));
    return r;
}

__device__ __forceinline__ float ex2(float x) {
    float r;
    asm("ex2.approx.f32 %0, %1;" : "=f"(r) : "f"(x));
    return r;
}

__device__ __forceinline__ unsigned ex2_f16x2(unsigned x) {
    unsigned r;
    asm("ex2.approx.f16x2 %0, %1;" : "=r"(r) : "r"(x));
    return r;
}

__device__ __forceinline__ unsigned hadd2(unsigned a, unsigned b) {
    unsigned r;
    asm("add.rn.f16x2 %0, %1, %2;" : "=r"(r) : "r"(a), "r"(b));
    return r;
}

__device__ __forceinline__ void cp16(unsigned dst, const void* src) {
    asm volatile("cp.async.cg.shared.global [%0], [%1], 16;"
                 :: "r"(dst), "l"(__cvta_generic_to_global(src)));
}
__device__ __forceinline__ void cp_commit() {
    asm volatile("cp.async.commit_group;");
}
template <int N>
__device__ __forceinline__ void cp_wait() {
    asm volatile("cp.async.wait_group %0;" :: "n"(N));
}

__device__ __forceinline__ void ldsm_x4(unsigned& r0, unsigned& r1,
                                        unsigned& r2, unsigned& r3,
                                        unsigned addr) {
    asm volatile("ldmatrix.sync.aligned.m8n8.x4.shared.b16 {%0,%1,%2,%3}, [%4];"
                 : "=r"(r0), "=r"(r1), "=r"(r2), "=r"(r3) : "r"(addr));
}
__device__ __forceinline__ void ldsm_x4_t(unsigned& r0, unsigned& r1,
                                          unsigned& r2, unsigned& r3,
                                          unsigned addr) {
    asm volatile("ldmatrix.sync.aligned.m8n8.x4.trans.shared.b16 {%0,%1,%2,%3}, [%4];"
                 : "=r"(r0), "=r"(r1), "=r"(r2), "=r"(r3) : "r"(addr));
}
__device__ __forceinline__ void mma_f16(float c[4], unsigned a0, unsigned a1,
                                        unsigned a2, unsigned a3,
                                        unsigned b0, unsigned b1) {
    asm volatile(
        "mma.sync.aligned.m16n8k16.row.col.f32.f16.f16.f32 "
        "{%0,%1,%2,%3}, {%4,%5,%6,%7}, {%8,%9}, {%0,%1,%2,%3};\n"
        : "+f"(c[0]), "+f"(c[1]), "+f"(c[2]), "+f"(c[3])
        : "r"(a0), "r"(a1), "r"(a2), "r"(a3), "r"(b0), "r"(b1));
}

// ---------------------------------------------------------------------------
// fp32 -> fp16 conversion pre-pass
// ---------------------------------------------------------------------------
__global__ __launch_bounds__(256)
void cvt_in(const float* __restrict__ q, const float* __restrict__ k,
            const float* __restrict__ v,
            __half* __restrict__ qh, __half* __restrict__ kh,
            __half* __restrict__ vh)
{
    const int z = blockIdx.z;
    const float* s = z == 0 ? q  : (z == 1 ? k  : v);
    __half*      d = z == 0 ? qh : (z == 1 ? kh : vh);
    int i = blockIdx.x * 256 + threadIdx.x;          // float4 index
    float4 f = ((const float4*)s)[i];
    ((uint2*)d)[i] = make_uint2(pack_f16x2(f.x, f.y), pack_f16x2(f.z, f.w));
}

__global__ __launch_bounds__(256)
void cvt_w(const float* __restrict__ Wq, const float* __restrict__ Wk,
           const float* __restrict__ Wv, const float* __restrict__ Wo,
           __half* __restrict__ Wqh, __half* __restrict__ Wkh,
           __half* __restrict__ Wvh, __half* __restrict__ Woh)
{
    const int z = blockIdx.z;
    const float* s = z == 0 ? Wq  : (z == 1 ? Wk  : (z == 2 ? Wv  : Wo));
    __half*      d = z == 0 ? Wqh : (z == 1 ? Wkh : (z == 2 ? Wvh : Woh));
    int i = blockIdx.x * 256 + threadIdx.x;
    float4 f = ((const float4*)s)[i];
    ((uint2*)d)[i] = make_uint2(pack_f16x2(f.x, f.y), pack_f16x2(f.z, f.w));
}

// mask fp32 (1.0 = masked) -> f16 additive mask (0 or -inf)
__global__ __launch_bounds__(256)
void cvt_mask(const float* __restrict__ mask, __half* __restrict__ mkh)
{
    int i = blockIdx.x * 256 + threadIdx.x;
    mkh[i] = __ushort_as_half(mask[i] > 0.5f ? (unsigned short)0xFC00
                                             : (unsigned short)0x0000);
}

// ---------------------------------------------------------------------------
// pure-fp16 GEMM, cp.async double-buffered. C = X @ W (+bias) [*scale].
// Block 128x128, BK=32, 8 warps (4m x 2n), warp tile 32x64.
// MODE 0: __half out, head-split layout, scale applied.
// MODE 1: float out, row-major.
// ---------------------------------------------------------------------------
#define ASTR 40
#define BSTR 136
#define A_BYTES (128 * ASTR * 2)
#define B_BYTES (32 * BSTR * 2)
#define STAGE_BYTES (A_BYTES + B_BYTES)

template <int MODE>
__device__ __forceinline__ void gemm_f16_body(
    const __half* __restrict__ X, const __half* __restrict__ W,
    const float* __restrict__ bias, void* outp, float scale)
{
    __shared__ __align__(16) char sh[2 * STAGE_BYTES];

    const int tid  = threadIdx.x;
    const int wid  = tid >> 5;
    const int lane = tid & 31;
    const int g    = lane >> 2;
    const int tig  = lane & 3;
    const int wm   = (wid & 3) << 5;
    const int wn   = (wid >> 2) << 6;
    const int lrow = (lane & 7) + ((lane >> 3) & 1) * 8;
    const int lcol = (lane >> 4) << 3;

    const int m0 = blockIdx.y << 7;
    const int n0 = blockIdx.x << 7;

    const unsigned sh_b = (unsigned)__cvta_generic_to_shared(sh);

    float c[2][8][4];
#pragma unroll
    for (int mt = 0; mt < 2; mt++)
#pragma unroll
        for (int nt = 0; nt < 8; nt++)
#pragma unroll
            for (int j = 0; j < 4; j++) c[mt][nt][j] = 0.f;

    auto issue = [&](int k0, int s) {
        unsigned as = sh_b + s * STAGE_BYTES;
        unsigned bs = as + A_BYTES;
#pragma unroll
        for (int p = 0; p < 2; p++) {
            int i = tid + (p << 8);
            int r = i >> 2, cc = (i & 3) << 3;
            cp16(as + (r * ASTR + cc) * 2, X + (size_t)(m0 + r) * DMc + k0 + cc);
        }
#pragma unroll
        for (int p = 0; p < 2; p++) {
            int i = tid + (p << 8);
            int r = i >> 4, cc = (i & 15) << 3;
            cp16(bs + (r * BSTR + cc) * 2, W + (size_t)(k0 + r) * DMc + n0 + cc);
        }
        cp_commit();
    };

    issue(0, 0);
    int buf = 0;
    for (int kc = 0; kc < 16; kc++) {
        if (kc < 15) { issue((kc + 1) << 5, buf ^ 1); cp_wait<1>(); }
        else         { cp_wait<0>(); }
        __syncthreads();

        const unsigned as_b = sh_b + buf * STAGE_BYTES;
        const unsigned bs_b = as_b + A_BYTES;
#pragma unroll
        for (int ks = 0; ks < 2; ks++) {
            const int kb = ks << 4;
            unsigned a[2][4];
#pragma unroll
            for (int mt = 0; mt < 2; mt++) {
                unsigned addr = as_b +
                    (((wm + (mt << 4) + lrow) * ASTR) + kb + lcol) * 2;
                ldsm_x4(a[mt][0], a[mt][1], a[mt][2], a[mt][3], addr);
            }
#pragma unroll
            for (int np = 0; np < 4; np++) {
                unsigned addr = bs_b +
                    (((kb + lrow) * BSTR) + wn + (np << 4) + lcol) * 2;
                unsigned r0, r1, r2, r3;
                ldsm_x4_t(r0, r1, r2, r3, addr);
                mma_f16(c[0][2 * np],     a[0][0], a[0][1], a[0][2], a[0][3], r0, r1);
                mma_f16(c[0][2 * np + 1], a[0][0], a[0][1], a[0][2], a[0][3], r2, r3);
                mma_f16(c[1][2 * np],     a[1][0], a[1][1], a[1][2], a[1][3], r0, r1);
                mma_f16(c[1][2 * np + 1], a[1][0], a[1][1], a[1][2], a[1][3], r2, r3);
            }
        }
        __syncthreads();
        buf ^= 1;
    }

    const int b_ = m0 >> 12;
#pragma unroll
    for (int mt = 0; mt < 2; mt++) {
        int m  = m0 + wm + (mt << 4) + g;
        int s_ = m & (Sc - 1);
#pragma unroll
        for (int nt = 0; nt < 8; nt++) {
            int n = n0 + wn + (nt << 3) + (tig << 1);
            float bx = bias[n], by = bias[n + 1];
            if (MODE == 0) {
                __half* out = (__half*)outp;
                int h = n >> 6;
                int d = n & 63;
                unsigned u0 = pack_f16x2((c[mt][nt][0] + bx) * scale,
                                         (c[mt][nt][1] + by) * scale);
                unsigned u1 = pack_f16x2((c[mt][nt][2] + bx) * scale,
                                         (c[mt][nt][3] + by) * scale);
                __half* base = out + ((size_t)(b_ * Hc + h) * Sc) * Dc + d;
                *(unsigned*)(base + (size_t)s_ * Dc)       = u0;
                *(unsigned*)(base + (size_t)(s_ + 8) * Dc) = u1;
            } else {
                float* out = (float*)outp;
                *(float2*)(out + (size_t)m * DMc + n) =
                    make_float2(c[mt][nt][0] + bx, c[mt][nt][1] + by);
                *(float2*)(out + (size_t)(m + 8) * DMc + n) =
                    make_float2(c[mt][nt][2] + bx, c[mt][nt][3] + by);
            }
        }
    }
}

__global__ __launch_bounds__(256, 2)
void gemm_qkv(const __half* __restrict__ qh, const __half* __restrict__ kh,
              const __half* __restrict__ vh,
              const __half* __restrict__ Wqh, const __half* __restrict__ Wkh,
              const __half* __restrict__ Wvh,
              const float* __restrict__ bq, const float* __restrict__ bk,
              const float* __restrict__ bv,
              __half* __restrict__ Qp, __half* __restrict__ Kp,
              __half* __restrict__ Vp)
{
    const int z = blockIdx.z;
    const __half* X    = z == 0 ? qh  : (z == 1 ? kh  : vh);
    const __half* W    = z == 0 ? Wqh : (z == 1 ? Wkh : Wvh);
    const float*  bias = z == 0 ? bq  : (z == 1 ? bk  : bv);
    __half*       out  = z == 0 ? Qp  : (z == 1 ? Kp  : Vp);
    gemm_f16_body<0>(X, W, bias, out, z == 0 ? SCL : 1.0f);
}

__global__ __launch_bounds__(256, 2)
void gemm_out(const __half* __restrict__ X, const __half* __restrict__ W,
              const float* __restrict__ bias, float* __restrict__ out)
{
    gemm_f16_body<1>(X, W, bias, out, 1.0f);
}

// ---------------------------------------------------------------------------
// Flash attention, fp16 mma + ldmatrix, cp.async double-buffered K/V.
// Block: 128 threads (4 warps), BQ=128 (32 rows/warp), BK=64, D=64.
// Q A-fragments hoisted into registers (loaded once, loop-invariant).
// Mask fused as f16 -inf into the pack->ex2.f16x2 chain (no fp32 mask FMA);
// epoch max is over UNMASKED logits (>= masked max, uniform per row: valid).
// EPOCH-MAX: max/rescale refreshed every 4th tile.
// smem halves: Qs[128][72] | Ks[2][64][72] | Vs[2][64][72] | mk16[2][64] half
// l carried as a 9th output n-tile (ones-column mma).
// ---------------------------------------------------------------------------
#define HSTR 72
#define QS_HALVES (128 * HSTR)
#define KV_STAGE_HALVES (64 * HSTR)
#define KS_HOFF QS_HALVES
#define VS_HOFF (QS_HALVES + 2 * KV_STAGE_HALVES)
#define MK_BYTE_OFF ((QS_HALVES + 4 * KV_STAGE_HALVES) * 2)
#define ATTN_SMEM_BYTES (MK_BYTE_OFF + 2 * 64 * 2)

#define ONES16X2 0x3C003C00u

__global__ __launch_bounds__(128, 2)
void attn_f16(const __half* __restrict__ Qp, const __half* __restrict__ Kp,
              const __half* __restrict__ Vp, const __half* __restrict__ mkh,
              __half* __restrict__ Ao)
{
    extern __shared__ __align__(16) char smc[];
    __half* Qs = (__half*)smc;

    const unsigned qs_b = (unsigned)__cvta_generic_to_shared(smc);
    const unsigned ks_b = qs_b + KS_HOFF * 2;
    const unsigned vs_b = qs_b + VS_HOFF * 2;
    const unsigned mk_b = qs_b + MK_BYTE_OFF;

    const int tid  = threadIdx.x;
    const int wid  = tid >> 5;
    const int lane = tid & 31;
    const int g    = lane >> 2;
    const int tig  = lane & 3;
    const int wm   = wid << 5;          // warp's 32-row base
    const int lrow = (lane & 7) + ((lane >> 3) & 1) * 8;
    const int lcol = (lane >> 4) << 3;

    const int bh = blockIdx.y;
    const int b  = bh >> 3;
    const int h  = bh & 7;
    const int q0 = blockIdx.x << 7;

    const __half* Qb = Qp + ((size_t)bh * Sc + q0) * Dc;
    const __half* Kb = Kp + (size_t)bh * Sc * Dc;
    const __half* Vb = Vp + (size_t)bh * Sc * Dc;
    const __half* mb = mkh + (size_t)b * Sc;

    // stage issuer: K/V tile t (64 rows) + f16 mask slice into stage s
    auto issue = [&](int t, int s) {
        const __half* Kt = Kb + (size_t)(t << 6) * Dc;
        const __half* Vt = Vb + (size_t)(t << 6) * Dc;
        unsigned ks = ks_b + s * KV_STAGE_HALVES * 2;
        unsigned vs = vs_b + s * KV_STAGE_HALVES * 2;
#pragma unroll
        for (int p = 0; p < 4; p++) {
            int i = tid + (p << 7);
            int r = i >> 3, cc = (i & 7) << 3;
            cp16(ks + (r * HSTR + cc) * 2, Kt + r * Dc + cc);
            cp16(vs + (r * HSTR + cc) * 2, Vt + r * Dc + cc);
        }
        if (tid < 8) cp16(mk_b + s * 128 + tid * 16, mb + (t << 6) + tid * 8);
        cp_commit();
    };

    issue(0, 0);

    // Q tile copy (fp16, already scaled by gemm), then hoist A-fragments
#pragma unroll
    for (int p = 0; p < 8; p++) {
        int i = tid + (p << 7);
        int r = i >> 3, cc = (i & 7) << 3;
        *(uint4*)&Qs[r * HSTR + cc] = *(const uint4*)(Qb + r * Dc + cc);
    }
    __syncthreads();

    unsigned qa[2][4][4];       // [mt][kb4][frag] -- loop-invariant
#pragma unroll
    for (int mt = 0; mt < 2; mt++)
#pragma unroll
        for (int kb4 = 0; kb4 < 4; kb4++) {
            unsigned addr = qs_b +
                (((wm + (mt << 4) + lrow) * HSTR) + (kb4 << 4) + lcol) * 2;
            ldsm_x4(qa[mt][kb4][0], qa[mt][kb4][1],
                    qa[mt][kb4][2], qa[mt][kb4][3], addr);
        }

    float m_i[4] = {-INFINITY, -INFINITY, -INFINITY, -INFINITY};
    // o[mt][8] is the ones-column accumulator = running row sum l
    float o[2][9][4];
#pragma unroll
    for (int mt = 0; mt < 2; mt++)
#pragma unroll
        for (int nt = 0; nt < 9; nt++)
#pragma unroll
            for (int j = 0; j < 4; j++) o[mt][nt][j] = 0.f;

    const int NT = Sc / 64;
    for (int t = 0; t < NT; t++) {
        const int s = t & 1;
        if (t < NT - 1) { issue(t + 1, s ^ 1); cp_wait<1>(); }
        else            { cp_wait<0>(); }
        __syncthreads();

        const unsigned ks_s = ks_b + s * KV_STAGE_HALVES * 2;
        const unsigned vs_s = vs_b + s * KV_STAGE_HALVES * 2;
        const __half*  mksh = (const __half*)(smc + MK_BYTE_OFF) + s * 64;

        // ---- S = Q @ K^T (Q fragments from registers) ----
        float c[2][8][4];
#pragma unroll
        for (int mt = 0; mt < 2; mt++)
#pragma unroll
            for (int nt = 0; nt < 8; nt++)
#pragma unroll
                for (int j = 0; j < 4; j++) c[mt][nt][j] = 0.f;

#pragma unroll
        for (int kb4 = 0; kb4 < 4; kb4++) {
            const int kb = kb4 << 4;
#pragma unroll
            for (int np = 0; np < 4; np++) {
                unsigned addr = ks_s +
                    ((((np << 4) + lrow) * HSTR) + kb + lcol) * 2;
                unsigned b0e, b0o, b1e, b1o;
                ldsm_x4(b0e, b0o, b1e, b1o, addr);
                mma_f16(c[0][2 * np],     qa[0][kb4][0], qa[0][kb4][1],
                        qa[0][kb4][2], qa[0][kb4][3], b0e, b1e);
                mma_f16(c[0][2 * np + 1], qa[0][kb4][0], qa[0][kb4][1],
                        qa[0][kb4][2], qa[0][kb4][3], b0o, b1o);
                mma_f16(c[1][2 * np],     qa[1][kb4][0], qa[1][kb4][1],
                        qa[1][kb4][2], qa[1][kb4][3], b0e, b1e);
                mma_f16(c[1][2 * np + 1], qa[1][kb4][0], qa[1][kb4][1],
                        qa[1][kb4][2], qa[1][kb4][3], b0o, b1o);
            }
        }

        // ---- epoch boundary: refresh running max (unmasked), rescale O+l ----
        if ((t & 3) == 0) {
#pragma unroll
            for (int mt = 0; mt < 2; mt++) {
                float vmax0 = -INFINITY, vmax1 = -INFINITY;
#pragma unroll
                for (int nt = 0; nt < 8; nt++) {
                    vmax0 = fmaxf(vmax0, fmaxf(c[mt][nt][0], c[mt][nt][1]));
                    vmax1 = fmaxf(vmax1, fmaxf(c[mt][nt][2], c[mt][nt][3]));
                }
                vmax0 = fmaxf(vmax0, __shfl_xor_sync(0xffffffffu, vmax0, 1));
                vmax0 = fmaxf(vmax0, __shfl_xor_sync(0xffffffffu, vmax0, 2));
                vmax1 = fmaxf(vmax1, __shfl_xor_sync(0xffffffffu, vmax1, 1));
                vmax1 = fmaxf(vmax1, __shfl_xor_sync(0xffffffffu, vmax1, 2));

                float mn0 = fmaxf(m_i[mt * 2 + 0], vmax0);
                float mn1 = fmaxf(m_i[mt * 2 + 1], vmax1);
                float al0 = ex2(m_i[mt * 2 + 0] - mn0);
                float al1 = ex2(m_i[mt * 2 + 1] - mn1);
                m_i[mt * 2 + 0] = mn0;
                m_i[mt * 2 + 1] = mn1;
#pragma unroll
                for (int nt = 0; nt < 9; nt++) {
                    o[mt][nt][0] *= al0; o[mt][nt][1] *= al0;
                    o[mt][nt][2] *= al1; o[mt][nt][3] *= al1;
                }
            }
        }

        // ---- exp: pack (s - mn), add f16 mask (-inf), ex2.f16x2 ----
        unsigned mku[8];
#pragma unroll
        for (int nt = 0; nt < 8; nt++)
            mku[nt] = *(const unsigned*)&mksh[(nt << 3) + (tig << 1)];

        unsigned pu[2][8][2];
#pragma unroll
        for (int mt = 0; mt < 2; mt++) {
            float mn0 = m_i[mt * 2 + 0];
            float mn1 = m_i[mt * 2 + 1];
#pragma unroll
            for (int nt = 0; nt < 8; nt++) {
                pu[mt][nt][0] = ex2_f16x2(hadd2(
                    pack_f16x2(c[mt][nt][0] - mn0, c[mt][nt][1] - mn0),
                    mku[nt]));
                pu[mt][nt][1] = ex2_f16x2(hadd2(
                    pack_f16x2(c[mt][nt][2] - mn1, c[mt][nt][3] - mn1),
                    mku[nt]));
            }
        }

        // ---- O += P @ V ;  l-column += P @ ones ----
#pragma unroll
        for (int kb4 = 0; kb4 < 4; kb4++) {
            unsigned pa[2][4];
#pragma unroll
            for (int mt = 0; mt < 2; mt++) {
                pa[mt][0] = pu[mt][2 * kb4][0];
                pa[mt][1] = pu[mt][2 * kb4][1];
                pa[mt][2] = pu[mt][2 * kb4 + 1][0];
                pa[mt][3] = pu[mt][2 * kb4 + 1][1];
            }
#pragma unroll
            for (int dp = 0; dp < 4; dp++) {
                unsigned addr = vs_s +
                    ((((kb4 << 4) + lrow) * HSTR) + (dp << 4) + lcol) * 2;
                unsigned r0, r1, r2, r3;
                ldsm_x4_t(r0, r1, r2, r3, addr);
                mma_f16(o[0][2 * dp],     pa[0][0], pa[0][1], pa[0][2], pa[0][3], r0, r1);
                mma_f16(o[0][2 * dp + 1], pa[0][0], pa[0][1], pa[0][2], pa[0][3], r2, r3);
                mma_f16(o[1][2 * dp],     pa[1][0], pa[1][1], pa[1][2], pa[1][3], r0, r1);
                mma_f16(o[1][2 * dp + 1], pa[1][0], pa[1][1], pa[1][2], pa[1][3], r2, r3);
            }
            mma_f16(o[0][8], pa[0][0], pa[0][1], pa[0][2], pa[0][3],
                    ONES16X2, ONES16X2);
            mma_f16(o[1][8], pa[1][0], pa[1][1], pa[1][2], pa[1][3],
                    ONES16X2, ONES16X2);
        }
        __syncthreads();
    }

    // ---- epilogue: normalize by l (ones-column), write fp16 Ao ----
    __half* AoB = Ao + ((size_t)b * Sc) * DMc + h * Dc;
#pragma unroll
    for (int mt = 0; mt < 2; mt++) {
        float inv0 = 1.f / o[mt][8][0];
        float inv1 = 1.f / o[mt][8][2];
        int r0 = q0 + wm + (mt << 4) + g;
#pragma unroll
        for (int nt = 0; nt < 8; nt++) {
            int d = (nt << 3) + (tig << 1);
            *(unsigned*)(AoB + (size_t)r0 * DMc + d) =
                pack_f16x2(o[mt][nt][0] * inv0, o[mt][nt][1] * inv0);
            *(unsigned*)(AoB + (size_t)(r0 + 8) * DMc + d) =
                pack_f16x2(o[mt][nt][2] * inv1, o[mt][nt][3] * inv1);
        }
    }
}

// ---------------------------------------------------------------------------
extern "C" void kernel_launch(void* const* d_in, const int* in_sizes, int n_in,
                              void* d_out, int out_size)
{
    const float* q    = (const float*)d_in[0];
    const float* k    = (const float*)d_in[1];
    const float* v    = (const float*)d_in[2];
    const float* mask = (const float*)d_in[3];
    const float* Wq   = (const float*)d_in[4];
    const float* bq   = (const float*)d_in[5];
    const float* Wk   = (const float*)d_in[6];
    const float* bk   = (const float*)d_in[7];
    const float* Wv   = (const float*)d_in[8];
    const float* bv   = (const float*)d_in[9];
    const float* Wo   = (const float*)d_in[10];
    const float* bo   = (const float*)d_in[11];
    float* out = (float*)d_out;

    __half *qh, *kh, *vh, *Wqh, *Wkh, *Wvh, *Woh, *Qp, *Kp, *Vp, *Ao, *mkh;
    cudaGetSymbolAddress((void**)&qh,  g_qh);
    cudaGetSymbolAddress((void**)&kh,  g_kh);
    cudaGetSymbolAddress((void**)&vh,  g_vh);
    cudaGetSymbolAddress((void**)&Wqh, g_Wqh);
    cudaGetSymbolAddress((void**)&Wkh, g_Wkh);
    cudaGetSymbolAddress((void**)&Wvh, g_Wvh);
    cudaGetSymbolAddress((void**)&Woh, g_Woh);
    cudaGetSymbolAddress((void**)&Qp,  g_Qp);
    cudaGetSymbolAddress((void**)&Kp,  g_Kp);
    cudaGetSymbolAddress((void**)&Vp,  g_Vp);
    cudaGetSymbolAddress((void**)&Ao,  g_Ao);
    cudaGetSymbolAddress((void**)&mkh, g_mkh);

    cudaFuncSetAttribute(attn_f16, cudaFuncAttributeMaxDynamicSharedMemorySize,
                         ATTN_SMEM_BYTES);

    dim3 gin(Mc * DMc / 4 / 256, 1, 3);     // (4096,1,3)
    cvt_in<<<gin, 256>>>(q, k, v, qh, kh, vh);
    dim3 gw(DMc * DMc / 4 / 256, 1, 4);     // (256,1,4)
    cvt_w<<<gw, 256>>>(Wq, Wk, Wv, Wo, Wqh, Wkh, Wvh, Woh);
    cvt_mask<<<Bc * Sc / 256, 256>>>(mask, mkh);

    dim3 gqkv(DMc / 128, Mc / 128, 3);      // (4, 64, 3)
    gemm_qkv<<<gqkv, 256>>>(qh, kh, vh, Wqh, Wkh, Wvh, bq, bk, bv, Qp, Kp, Vp);

    dim3 ga(Sc / 128, Bc * Hc);             // (32, 16)
    attn_f16<<<ga, 128, ATTN_SMEM_BYTES>>>(Qp, Kp, Vp, mkh, Ao);

    dim3 gg(DMc / 128, Mc / 128);           // (4, 64)
    gemm_out<<<gg, 256>>>(Ao, Woh, bo, out);
}

// round 12
// speedup vs baseline: 1.1404x; 1.0035x over previous
#include <cuda_runtime.h>
#include <cuda_fp16.h>
#include <math.h>

#define Bc  2
#define Sc  4096
#define DMc 512
#define Hc  8
#define Dc  64
#define Mc  (Bc * Sc)   // 8192

#define SCL (0.125f * 1.44269504f)

// fp16 mirrors of inputs/weights + fp16 scratch
__device__ __half g_qh[Mc * DMc];
__device__ __half g_kh[Mc * DMc];
__device__ __half g_vh[Mc * DMc];
__device__ __half g_Wqh[DMc * DMc];
__device__ __half g_Wkh[DMc * DMc];
__device__ __half g_Wvh[DMc * DMc];
__device__ __half g_Woh[DMc * DMc];
__device__ __half g_Qp[Bc * Hc * Sc * Dc];
__device__ __half g_Kp[Bc * Hc * Sc * Dc];
__device__ __half g_Vp[Bc * Hc * Sc * Dc];
__device__ __half g_Ao[Mc * DMc];
__device__ __half g_mkh[Bc * Sc];          // mask as f16: 0 or -inf

// ---------------------------------------------------------------------------
// helpers
// ---------------------------------------------------------------------------
__device__ __forceinline__ unsigned pack_f16x2(float lo, float hi) {
    unsigned r;
    asm("cvt.rn.f16x2.f32 %0, %1, %2;" : "=r"(r) : "f"(hi), "f"(lo));
    return r;
}

__device__ __forceinline__ float ex2(float x) {
    float r;
    asm("ex2.approx.f32 %0, %1;" : "=f"(r) : "f"(x));
    return r;
}

__device__ __forceinline__ unsigned ex2_f16x2(unsigned x) {
    unsigned r;
    asm("ex2.approx.f16x2 %0, %1;" : "=r"(r) : "r"(x));
    return r;
}

__device__ __forceinline__ unsigned hadd2(unsigned a, unsigned b) {
    unsigned r;
    asm("add.rn.f16x2 %0, %1, %2;" : "=r"(r) : "r"(a), "r"(b));
    return r;
}

__device__ __forceinline__ void cp16(unsigned dst, const void* src) {
    asm volatile("cp.async.cg.shared.global [%0], [%1], 16;"
                 :: "r"(dst), "l"(__cvta_generic_to_global(src)));
}
__device__ __forceinline__ void cp_commit() {
    asm volatile("cp.async.commit_group;");
}
template <int N>
__device__ __forceinline__ void cp_wait() {
    asm volatile("cp.async.wait_group %0;" :: "n"(N));
}

__device__ __forceinline__ void ldsm_x4(unsigned& r0, unsigned& r1,
                                        unsigned& r2, unsigned& r3,
                                        unsigned addr) {
    asm volatile("ldmatrix.sync.aligned.m8n8.x4.shared.b16 {%0,%1,%2,%3}, [%4];"
                 : "=r"(r0), "=r"(r1), "=r"(r2), "=r"(r3) : "r"(addr));
}
__device__ __forceinline__ void ldsm_x4_t(unsigned& r0, unsigned& r1,
                                          unsigned& r2, unsigned& r3,
                                          unsigned addr) {
    asm volatile("ldmatrix.sync.aligned.m8n8.x4.trans.shared.b16 {%0,%1,%2,%3}, [%4];"
                 : "=r"(r0), "=r"(r1), "=r"(r2), "=r"(r3) : "r"(addr));
}
__device__ __forceinline__ void mma_f16(float c[4], unsigned a0, unsigned a1,
                                        unsigned a2, unsigned a3,
                                        unsigned b0, unsigned b1) {
    asm volatile(
        "mma.sync.aligned.m16n8k16.row.col.f32.f16.f16.f32 "
        "{%0,%1,%2,%3}, {%4,%5,%6,%7}, {%8,%9}, {%0,%1,%2,%3};\n"
        : "+f"(c[0]), "+f"(c[1]), "+f"(c[2]), "+f"(c[3])
        : "r"(a0), "r"(a1), "r"(a2), "r"(a3), "r"(b0), "r"(b1));
}

// ---------------------------------------------------------------------------
// fp32 -> fp16 conversion pre-pass
// ---------------------------------------------------------------------------
__global__ __launch_bounds__(256)
void cvt_in(const float* __restrict__ q, const float* __restrict__ k,
            const float* __restrict__ v,
            __half* __restrict__ qh, __half* __restrict__ kh,
            __half* __restrict__ vh)
{
    const int z = blockIdx.z;
    const float* s = z == 0 ? q  : (z == 1 ? k  : v);
    __half*      d = z == 0 ? qh : (z == 1 ? kh : vh);
    int i = blockIdx.x * 256 + threadIdx.x;          // float4 index
    float4 f = ((const float4*)s)[i];
    ((uint2*)d)[i] = make_uint2(pack_f16x2(f.x, f.y), pack_f16x2(f.z, f.w));
}

__global__ __launch_bounds__(256)
void cvt_w(const float* __restrict__ Wq, const float* __restrict__ Wk,
           const float* __restrict__ Wv, const float* __restrict__ Wo,
           __half* __restrict__ Wqh, __half* __restrict__ Wkh,
           __half* __restrict__ Wvh, __half* __restrict__ Woh)
{
    const int z = blockIdx.z;
    const float* s = z == 0 ? Wq  : (z == 1 ? Wk  : (z == 2 ? Wv  : Wo));
    __half*      d = z == 0 ? Wqh : (z == 1 ? Wkh : (z == 2 ? Wvh : Woh));
    int i = blockIdx.x * 256 + threadIdx.x;
    float4 f = ((const float4*)s)[i];
    ((uint2*)d)[i] = make_uint2(pack_f16x2(f.x, f.y), pack_f16x2(f.z, f.w));
}

// mask fp32 (1.0 = masked) -> f16 additive mask (0 or -inf)
__global__ __launch_bounds__(256)
void cvt_mask(const float* __restrict__ mask, __half* __restrict__ mkh)
{
    int i = blockIdx.x * 256 + threadIdx.x;
    mkh[i] = __ushort_as_half(mask[i] > 0.5f ? (unsigned short)0xFC00
                                             : (unsigned short)0x0000);
}

// ---------------------------------------------------------------------------
// pure-fp16 GEMM, 4-stage cp.async ring. C = X @ W (+bias) [*scale].
// Block 128x128, BK=32, 8 warps (4m x 2n), warp tile 32x64.
// Ring: prologue issues 3 chunks; loop = wait(<=2) / barrier / issue(kc+3) /
// compute(kc). Consumed chunk is 3 issues deep -> ~2 chunk-times of latency
// coverage. MODE 0: __half out, head-split, scaled. MODE 1: float out.
// ---------------------------------------------------------------------------
#define ASTR 40
#define BSTR 136
#define A_BYTES (128 * ASTR * 2)
#define B_BYTES (32 * BSTR * 2)
#define STAGE_BYTES (A_BYTES + B_BYTES)
#define GEMM_SMEM_BYTES (4 * STAGE_BYTES)

template <int MODE>
__device__ __forceinline__ void gemm_f16_body(
    const __half* __restrict__ X, const __half* __restrict__ W,
    const float* __restrict__ bias, void* outp, float scale, char* sh)
{
    const int tid  = threadIdx.x;
    const int wid  = tid >> 5;
    const int lane = tid & 31;
    const int g    = lane >> 2;
    const int tig  = lane & 3;
    const int wm   = (wid & 3) << 5;
    const int wn   = (wid >> 2) << 6;
    const int lrow = (lane & 7) + ((lane >> 3) & 1) * 8;
    const int lcol = (lane >> 4) << 3;

    const int m0 = blockIdx.y << 7;
    const int n0 = blockIdx.x << 7;

    const unsigned sh_b = (unsigned)__cvta_generic_to_shared(sh);

    float c[2][8][4];
#pragma unroll
    for (int mt = 0; mt < 2; mt++)
#pragma unroll
        for (int nt = 0; nt < 8; nt++)
#pragma unroll
            for (int j = 0; j < 4; j++) c[mt][nt][j] = 0.f;

    auto issue = [&](int kc, int s) {
        const int k0 = kc << 5;
        unsigned as = sh_b + s * STAGE_BYTES;
        unsigned bs = as + A_BYTES;
#pragma unroll
        for (int p = 0; p < 2; p++) {
            int i = tid + (p << 8);
            int r = i >> 2, cc = (i & 3) << 3;
            cp16(as + (r * ASTR + cc) * 2, X + (size_t)(m0 + r) * DMc + k0 + cc);
        }
#pragma unroll
        for (int p = 0; p < 2; p++) {
            int i = tid + (p << 8);
            int r = i >> 4, cc = (i & 15) << 3;
            cp16(bs + (r * BSTR + cc) * 2, W + (size_t)(k0 + r) * DMc + n0 + cc);
        }
        cp_commit();
    };

    issue(0, 0);
    issue(1, 1);
    issue(2, 2);

    for (int kc = 0; kc < 16; kc++) {
        if (kc <= 13)      cp_wait<2>();
        else if (kc == 14) cp_wait<1>();
        else               cp_wait<0>();
        __syncthreads();
        if (kc + 3 < 16) issue(kc + 3, (kc + 3) & 3);

        const unsigned as_b = sh_b + (kc & 3) * STAGE_BYTES;
        const unsigned bs_b = as_b + A_BYTES;
#pragma unroll
        for (int ks = 0; ks < 2; ks++) {
            const int kb = ks << 4;
            unsigned a[2][4];
#pragma unroll
            for (int mt = 0; mt < 2; mt++) {
                unsigned addr = as_b +
                    (((wm + (mt << 4) + lrow) * ASTR) + kb + lcol) * 2;
                ldsm_x4(a[mt][0], a[mt][1], a[mt][2], a[mt][3], addr);
            }
#pragma unroll
            for (int np = 0; np < 4; np++) {
                unsigned addr = bs_b +
                    (((kb + lrow) * BSTR) + wn + (np << 4) + lcol) * 2;
                unsigned r0, r1, r2, r3;
                ldsm_x4_t(r0, r1, r2, r3, addr);
                mma_f16(c[0][2 * np],     a[0][0], a[0][1], a[0][2], a[0][3], r0, r1);
                mma_f16(c[0][2 * np + 1], a[0][0], a[0][1], a[0][2], a[0][3], r2, r3);
                mma_f16(c[1][2 * np],     a[1][0], a[1][1], a[1][2], a[1][3], r0, r1);
                mma_f16(c[1][2 * np + 1], a[1][0], a[1][1], a[1][2], a[1][3], r2, r3);
            }
        }
    }

    const int b_ = m0 >> 12;
#pragma unroll
    for (int mt = 0; mt < 2; mt++) {
        int m  = m0 + wm + (mt << 4) + g;
        int s_ = m & (Sc - 1);
#pragma unroll
        for (int nt = 0; nt < 8; nt++) {
            int n = n0 + wn + (nt << 3) + (tig << 1);
            float bx = bias[n], by = bias[n + 1];
            if (MODE == 0) {
                __half* out = (__half*)outp;
                int h = n >> 6;
                int d = n & 63;
                unsigned u0 = pack_f16x2((c[mt][nt][0] + bx) * scale,
                                         (c[mt][nt][1] + by) * scale);
                unsigned u1 = pack_f16x2((c[mt][nt][2] + bx) * scale,
                                         (c[mt][nt][3] + by) * scale);
                __half* base = out + ((size_t)(b_ * Hc + h) * Sc) * Dc + d;
                *(unsigned*)(base + (size_t)s_ * Dc)       = u0;
                *(unsigned*)(base + (size_t)(s_ + 8) * Dc) = u1;
            } else {
                float* out = (float*)outp;
                *(float2*)(out + (size_t)m * DMc + n) =
                    make_float2(c[mt][nt][0] + bx, c[mt][nt][1] + by);
                *(float2*)(out + (size_t)(m + 8) * DMc + n) =
                    make_float2(c[mt][nt][2] + bx, c[mt][nt][3] + by);
            }
        }
    }
}

__global__ __launch_bounds__(256, 2)
void gemm_qkv(const __half* __restrict__ qh, const __half* __restrict__ kh,
              const __half* __restrict__ vh,
              const __half* __restrict__ Wqh, const __half* __restrict__ Wkh,
              const __half* __restrict__ Wvh,
              const float* __restrict__ bq, const float* __restrict__ bk,
              const float* __restrict__ bv,
              __half* __restrict__ Qp, __half* __restrict__ Kp,
              __half* __restrict__ Vp)
{
    extern __shared__ __align__(16) char shdyn[];
    const int z = blockIdx.z;
    const __half* X    = z == 0 ? qh  : (z == 1 ? kh  : vh);
    const __half* W    = z == 0 ? Wqh : (z == 1 ? Wkh : Wvh);
    const float*  bias = z == 0 ? bq  : (z == 1 ? bk  : bv);
    __half*       out  = z == 0 ? Qp  : (z == 1 ? Kp  : Vp);
    gemm_f16_body<0>(X, W, bias, out, z == 0 ? SCL : 1.0f, shdyn);
}

__global__ __launch_bounds__(256, 2)
void gemm_out(const __half* __restrict__ X, const __half* __restrict__ W,
              const float* __restrict__ bias, float* __restrict__ out)
{
    extern __shared__ __align__(16) char shdyn[];
    gemm_f16_body<1>(X, W, bias, out, 1.0f, shdyn);
}

// ---------------------------------------------------------------------------
// Flash attention, fp16 mma + ldmatrix, cp.async double-buffered K/V.
// Block: 128 threads (4 warps), BQ=128 (32 rows/warp), BK=64, D=64.
// Q A-fragments hoisted into registers (loaded once, loop-invariant).
// Mask fused as f16 -inf into the pack->ex2.f16x2 chain;
// epoch max over UNMASKED logits (valid uniform row shift).
// EPOCH-MAX: max/rescale refreshed every 4th tile.
// smem halves: Qs[128][72] | Ks[2][64][72] | Vs[2][64][72] | mk16[2][64] half
// l carried as a 9th output n-tile (ones-column mma).
// ---------------------------------------------------------------------------
#define HSTR 72
#define QS_HALVES (128 * HSTR)
#define KV_STAGE_HALVES (64 * HSTR)
#define KS_HOFF QS_HALVES
#define VS_HOFF (QS_HALVES + 2 * KV_STAGE_HALVES)
#define MK_BYTE_OFF ((QS_HALVES + 4 * KV_STAGE_HALVES) * 2)
#define ATTN_SMEM_BYTES (MK_BYTE_OFF + 2 * 64 * 2)

#define ONES16X2 0x3C003C00u

__global__ __launch_bounds__(128, 2)
void attn_f16(const __half* __restrict__ Qp, const __half* __restrict__ Kp,
              const __half* __restrict__ Vp, const __half* __restrict__ mkh,
              __half* __restrict__ Ao)
{
    extern __shared__ __align__(16) char smc[];
    __half* Qs = (__half*)smc;

    const unsigned qs_b = (unsigned)__cvta_generic_to_shared(smc);
    const unsigned ks_b = qs_b + KS_HOFF * 2;
    const unsigned vs_b = qs_b + VS_HOFF * 2;
    const unsigned mk_b = qs_b + MK_BYTE_OFF;

    const int tid  = threadIdx.x;
    const int wid  = tid >> 5;
    const int lane = tid & 31;
    const int g    = lane >> 2;
    const int tig  = lane & 3;
    const int wm   = wid << 5;          // warp's 32-row base
    const int lrow = (lane & 7) + ((lane >> 3) & 1) * 8;
    const int lcol = (lane >> 4) << 3;

    const int bh = blockIdx.y;
    const int b  = bh >> 3;
    const int h  = bh & 7;
    const int q0 = blockIdx.x << 7;

    const __half* Qb = Qp + ((size_t)bh * Sc + q0) * Dc;
    const __half* Kb = Kp + (size_t)bh * Sc * Dc;
    const __half* Vb = Vp + (size_t)bh * Sc * Dc;
    const __half* mb = mkh + (size_t)b * Sc;

    // stage issuer: K/V tile t (64 rows) + f16 mask slice into stage s
    auto issue = [&](int t, int s) {
        const __half* Kt = Kb + (size_t)(t << 6) * Dc;
        const __half* Vt = Vb + (size_t)(t << 6) * Dc;
        unsigned ks = ks_b + s * KV_STAGE_HALVES * 2;
        unsigned vs = vs_b + s * KV_STAGE_HALVES * 2;
#pragma unroll
        for (int p = 0; p < 4; p++) {
            int i = tid + (p << 7);
            int r = i >> 3, cc = (i & 7) << 3;
            cp16(ks + (r * HSTR + cc) * 2, Kt + r * Dc + cc);
            cp16(vs + (r * HSTR + cc) * 2, Vt + r * Dc + cc);
        }
        if (tid < 8) cp16(mk_b + s * 128 + tid * 16, mb + (t << 6) + tid * 8);
        cp_commit();
    };

    issue(0, 0);

    // Q tile copy (fp16, already scaled by gemm), then hoist A-fragments
#pragma unroll
    for (int p = 0; p < 8; p++) {
        int i = tid + (p << 7);
        int r = i >> 3, cc = (i & 7) << 3;
        *(uint4*)&Qs[r * HSTR + cc] = *(const uint4*)(Qb + r * Dc + cc);
    }
    __syncthreads();

    unsigned qa[2][4][4];       // [mt][kb4][frag] -- loop-invariant
#pragma unroll
    for (int mt = 0; mt < 2; mt++)
#pragma unroll
        for (int kb4 = 0; kb4 < 4; kb4++) {
            unsigned addr = qs_b +
                (((wm + (mt << 4) + lrow) * HSTR) + (kb4 << 4) + lcol) * 2;
            ldsm_x4(qa[mt][kb4][0], qa[mt][kb4][1],
                    qa[mt][kb4][2], qa[mt][kb4][3], addr);
        }

    float m_i[4] = {-INFINITY, -INFINITY, -INFINITY, -INFINITY};
    // o[mt][8] is the ones-column accumulator = running row sum l
    float o[2][9][4];
#pragma unroll
    for (int mt = 0; mt < 2; mt++)
#pragma unroll
        for (int nt = 0; nt < 9; nt++)
#pragma unroll
            for (int j = 0; j < 4; j++) o[mt][nt][j] = 0.f;

    const int NT = Sc / 64;
    for (int t = 0; t < NT; t++) {
        const int s = t & 1;
        if (t < NT - 1) { issue(t + 1, s ^ 1); cp_wait<1>(); }
        else            { cp_wait<0>(); }
        __syncthreads();

        const unsigned ks_s = ks_b + s * KV_STAGE_HALVES * 2;
        const unsigned vs_s = vs_b + s * KV_STAGE_HALVES * 2;
        const __half*  mksh = (const __half*)(smc + MK_BYTE_OFF) + s * 64;

        // ---- S = Q @ K^T (Q fragments from registers) ----
        float c[2][8][4];
#pragma unroll
        for (int mt = 0; mt < 2; mt++)
#pragma unroll
            for (int nt = 0; nt < 8; nt++)
#pragma unroll
                for (int j = 0; j < 4; j++) c[mt][nt][j] = 0.f;

#pragma unroll
        for (int kb4 = 0; kb4 < 4; kb4++) {
            const int kb = kb4 << 4;
#pragma unroll
            for (int np = 0; np < 4; np++) {
                unsigned addr = ks_s +
                    ((((np << 4) + lrow) * HSTR) + kb + lcol) * 2;
                unsigned b0e, b0o, b1e, b1o;
                ldsm_x4(b0e, b0o, b1e, b1o, addr);
                mma_f16(c[0][2 * np],     qa[0][kb4][0], qa[0][kb4][1],
                        qa[0][kb4][2], qa[0][kb4][3], b0e, b1e);
                mma_f16(c[0][2 * np + 1], qa[0][kb4][0], qa[0][kb4][1],
                        qa[0][kb4][2], qa[0][kb4][3], b0o, b1o);
                mma_f16(c[1][2 * np],     qa[1][kb4][0], qa[1][kb4][1],
                        qa[1][kb4][2], qa[1][kb4][3], b0e, b1e);
                mma_f16(c[1][2 * np + 1], qa[1][kb4][0], qa[1][kb4][1],
                        qa[1][kb4][2], qa[1][kb4][3], b0o, b1o);
            }
        }

        // ---- epoch boundary: refresh running max (unmasked), rescale O+l ----
        if ((t & 3) == 0) {
#pragma unroll
            for (int mt = 0; mt < 2; mt++) {
                float vmax0 = -INFINITY, vmax1 = -INFINITY;
#pragma unroll
                for (int nt = 0; nt < 8; nt++) {
                    vmax0 = fmaxf(vmax0, fmaxf(c[mt][nt][0], c[mt][nt][1]));
                    vmax1 = fmaxf(vmax1, fmaxf(c[mt][nt][2], c[mt][nt][3]));
                }
                vmax0 = fmaxf(vmax0, __shfl_xor_sync(0xffffffffu, vmax0, 1));
                vmax0 = fmaxf(vmax0, __shfl_xor_sync(0xffffffffu, vmax0, 2));
                vmax1 = fmaxf(vmax1, __shfl_xor_sync(0xffffffffu, vmax1, 1));
                vmax1 = fmaxf(vmax1, __shfl_xor_sync(0xffffffffu, vmax1, 2));

                float mn0 = fmaxf(m_i[mt * 2 + 0], vmax0);
                float mn1 = fmaxf(m_i[mt * 2 + 1], vmax1);
                float al0 = ex2(m_i[mt * 2 + 0] - mn0);
                float al1 = ex2(m_i[mt * 2 + 1] - mn1);
                m_i[mt * 2 + 0] = mn0;
                m_i[mt * 2 + 1] = mn1;
#pragma unroll
                for (int nt = 0; nt < 9; nt++) {
                    o[mt][nt][0] *= al0; o[mt][nt][1] *= al0;
                    o[mt][nt][2] *= al1; o[mt][nt][3] *= al1;
                }
            }
        }

        // ---- exp: pack (s - mn), add f16 mask (-inf), ex2.f16x2 ----
        unsigned mku[8];
#pragma unroll
        for (int nt = 0; nt < 8; nt++)
            mku[nt] = *(const unsigned*)&mksh[(nt << 3) + (tig << 1)];

        unsigned pu[2][8][2];
#pragma unroll
        for (int mt = 0; mt < 2; mt++) {
            float mn0 = m_i[mt * 2 + 0];
            float mn1 = m_i[mt * 2 + 1];
#pragma unroll
            for (int nt = 0; nt < 8; nt++) {
                pu[mt][nt][0] = ex2_f16x2(hadd2(
                    pack_f16x2(c[mt][nt][0] - mn0, c[mt][nt][1] - mn0),
                    mku[nt]));
                pu[mt][nt][1] = ex2_f16x2(hadd2(
                    pack_f16x2(c[mt][nt][2] - mn1, c[mt][nt][3] - mn1),
                    mku[nt]));
            }
        }

        // ---- O += P @ V ;  l-column += P @ ones ----
#pragma unroll
        for (int kb4 = 0; kb4 < 4; kb4++) {
            unsigned pa[2][4];
#pragma unroll
            for (int mt = 0; mt < 2; mt++) {
                pa[mt][0] = pu[mt][2 * kb4][0];
                pa[mt][1] = pu[mt][2 * kb4][1];
                pa[mt][2] = pu[mt][2 * kb4 + 1][0];
                pa[mt][3] = pu[mt][2 * kb4 + 1][1];
            }
#pragma unroll
            for (int dp = 0; dp < 4; dp++) {
                unsigned addr = vs_s +
                    ((((kb4 << 4) + lrow) * HSTR) + (dp << 4) + lcol) * 2;
                unsigned r0, r1, r2, r3;
                ldsm_x4_t(r0, r1, r2, r3, addr);
                mma_f16(o[0][2 * dp],     pa[0][0], pa[0][1], pa[0][2], pa[0][3], r0, r1);
                mma_f16(o[0][2 * dp + 1], pa[0][0], pa[0][1], pa[0][2], pa[0][3], r2, r3);
                mma_f16(o[1][2 * dp],     pa[1][0], pa[1][1], pa[1][2], pa[1][3], r0, r1);
                mma_f16(o[1][2 * dp + 1], pa[1][0], pa[1][1], pa[1][2], pa[1][3], r2, r3);
            }
            mma_f16(o[0][8], pa[0][0], pa[0][1], pa[0][2], pa[0][3],
                    ONES16X2, ONES16X2);
            mma_f16(o[1][8], pa[1][0], pa[1][1], pa[1][2], pa[1][3],
                    ONES16X2, ONES16X2);
        }
        __syncthreads();
    }

    // ---- epilogue: normalize by l (ones-column), write fp16 Ao ----
    __half* AoB = Ao + ((size_t)b * Sc) * DMc + h * Dc;
#pragma unroll
    for (int mt = 0; mt < 2; mt++) {
        float inv0 = 1.f / o[mt][8][0];
        float inv1 = 1.f / o[mt][8][2];
        int r0 = q0 + wm + (mt << 4) + g;
#pragma unroll
        for (int nt = 0; nt < 8; nt++) {
            int d = (nt << 3) + (tig << 1);
            *(unsigned*)(AoB + (size_t)r0 * DMc + d) =
                pack_f16x2(o[mt][nt][0] * inv0, o[mt][nt][1] * inv0);
            *(unsigned*)(AoB + (size_t)(r0 + 8) * DMc + d) =
                pack_f16x2(o[mt][nt][2] * inv1, o[mt][nt][3] * inv1);
        }
    }
}

// ---------------------------------------------------------------------------
extern "C" void kernel_launch(void* const* d_in, const int* in_sizes, int n_in,
                              void* d_out, int out_size)
{
    const float* q    = (const float*)d_in[0];
    const float* k    = (const float*)d_in[1];
    const float* v    = (const float*)d_in[2];
    const float* mask = (const float*)d_in[3];
    const float* Wq   = (const float*)d_in[4];
    const float* bq   = (const float*)d_in[5];
    const float* Wk   = (const float*)d_in[6];
    const float* bk   = (const float*)d_in[7];
    const float* Wv   = (const float*)d_in[8];
    const float* bv   = (const float*)d_in[9];
    const float* Wo   = (const float*)d_in[10];
    const float* bo   = (const float*)d_in[11];
    float* out = (float*)d_out;

    __half *qh, *kh, *vh, *Wqh, *Wkh, *Wvh, *Woh, *Qp, *Kp, *Vp, *Ao, *mkh;
    cudaGetSymbolAddress((void**)&qh,  g_qh);
    cudaGetSymbolAddress((void**)&kh,  g_kh);
    cudaGetSymbolAddress((void**)&vh,  g_vh);
    cudaGetSymbolAddress((void**)&Wqh, g_Wqh);
    cudaGetSymbolAddress((void**)&Wkh, g_Wkh);
    cudaGetSymbolAddress((void**)&Wvh, g_Wvh);
    cudaGetSymbolAddress((void**)&Woh, g_Woh);
    cudaGetSymbolAddress((void**)&Qp,  g_Qp);
    cudaGetSymbolAddress((void**)&Kp,  g_Kp);
    cudaGetSymbolAddress((void**)&Vp,  g_Vp);
    cudaGetSymbolAddress((void**)&Ao,  g_Ao);
    cudaGetSymbolAddress((void**)&mkh, g_mkh);

    cudaFuncSetAttribute(attn_f16, cudaFuncAttributeMaxDynamicSharedMemorySize,
                         ATTN_SMEM_BYTES);
    cudaFuncSetAttribute(gemm_qkv, cudaFuncAttributeMaxDynamicSharedMemorySize,
                         GEMM_SMEM_BYTES);
    cudaFuncSetAttribute(gemm_out, cudaFuncAttributeMaxDynamicSharedMemorySize,
                         GEMM_SMEM_BYTES);

    dim3 gin(Mc * DMc / 4 / 256, 1, 3);     // (4096,1,3)
    cvt_in<<<gin, 256>>>(q, k, v, qh, kh, vh);
    dim3 gw(DMc * DMc / 4 / 256, 1, 4);     // (256,1,4)
    cvt_w<<<gw, 256>>>(Wq, Wk, Wv, Wo, Wqh, Wkh, Wvh, Woh);
    cvt_mask<<<Bc * Sc / 256, 256>>>(mask, mkh);

    dim3 gqkv(DMc / 128, Mc / 128, 3);      // (4, 64, 3)
    gemm_qkv<<<gqkv, 256, GEMM_SMEM_BYTES>>>(qh, kh, vh, Wqh, Wkh, Wvh,
                                             bq, bk, bv, Qp, Kp, Vp);

    dim3 ga(Sc / 128, Bc * Hc);             // (32, 16)
    attn_f16<<<ga, 128, ATTN_SMEM_BYTES>>>(Qp, Kp, Vp, mkh, Ao);

    dim3 gg(DMc / 128, Mc / 128);           // (4, 64)
    gemm_out<<<gg, 256, GEMM_SMEM_BYTES>>>(Ao, Woh, bo, out);
}

// round 13
// speedup vs baseline: 1.1660x; 1.0225x over previous
#include <cuda_runtime.h>
#include <cuda_fp16.h>
#include <math.h>

#define Bc  2
#define Sc  4096
#define DMc 512
#define Hc  8
#define Dc  64
#define Mc  (Bc * Sc)   // 8192

#define SCL (0.125f * 1.44269504f)

// fp16 mirrors of inputs/weights + fp16 scratch
__device__ __half g_qh[Mc * DMc];
__device__ __half g_kh[Mc * DMc];
__device__ __half g_vh[Mc * DMc];
__device__ __half g_Wqh[DMc * DMc];
__device__ __half g_Wkh[DMc * DMc];
__device__ __half g_Wvh[DMc * DMc];
__device__ __half g_Woh[DMc * DMc];
__device__ __half g_Qp[Bc * Hc * Sc * Dc];
__device__ __half g_Kp[Bc * Hc * Sc * Dc];
__device__ __half g_Vp[Bc * Hc * Sc * Dc];
__device__ __half g_Ao[Mc * DMc];
__device__ __half g_mkh[Bc * Sc];          // mask as f16: 0 or -inf

// ---------------------------------------------------------------------------
// helpers
// ---------------------------------------------------------------------------
__device__ __forceinline__ unsigned pack_f16x2(float lo, float hi) {
    unsigned r;
    asm("cvt.rn.f16x2.f32 %0, %1, %2;" : "=r"(r) : "f"(hi), "f"(lo));
    return r;
}

__device__ __forceinline__ float ex2(float x) {
    float r;
    asm("ex2.approx.f32 %0, %1;" : "=f"(r) : "f"(x));
    return r;
}

__device__ __forceinline__ unsigned ex2_f16x2(unsigned x) {
    unsigned r;
    asm("ex2.approx.f16x2 %0, %1;" : "=r"(r) : "r"(x));
    return r;
}

__device__ __forceinline__ unsigned hadd2(unsigned a, unsigned b) {
    unsigned r;
    asm("add.rn.f16x2 %0, %1, %2;" : "=r"(r) : "r"(a), "r"(b));
    return r;
}

__device__ __forceinline__ void cp16(unsigned dst, const void* src) {
    asm volatile("cp.async.cg.shared.global [%0], [%1], 16;"
                 :: "r"(dst), "l"(__cvta_generic_to_global(src)));
}
__device__ __forceinline__ void cp_commit() {
    asm volatile("cp.async.commit_group;");
}
template <int N>
__device__ __forceinline__ void cp_wait() {
    asm volatile("cp.async.wait_group %0;" :: "n"(N));
}

__device__ __forceinline__ void ldsm_x4(unsigned& r0, unsigned& r1,
                                        unsigned& r2, unsigned& r3,
                                        unsigned addr) {
    asm volatile("ldmatrix.sync.aligned.m8n8.x4.shared.b16 {%0,%1,%2,%3}, [%4];"
                 : "=r"(r0), "=r"(r1), "=r"(r2), "=r"(r3) : "r"(addr));
}
__device__ __forceinline__ void ldsm_x4_t(unsigned& r0, unsigned& r1,
                                          unsigned& r2, unsigned& r3,
                                          unsigned addr) {
    asm volatile("ldmatrix.sync.aligned.m8n8.x4.trans.shared.b16 {%0,%1,%2,%3}, [%4];"
                 : "=r"(r0), "=r"(r1), "=r"(r2), "=r"(r3) : "r"(addr));
}
__device__ __forceinline__ void mma_f16(float c[4], unsigned a0, unsigned a1,
                                        unsigned a2, unsigned a3,
                                        unsigned b0, unsigned b1) {
    asm volatile(
        "mma.sync.aligned.m16n8k16.row.col.f32.f16.f16.f32 "
        "{%0,%1,%2,%3}, {%4,%5,%6,%7}, {%8,%9}, {%0,%1,%2,%3};\n"
        : "+f"(c[0]), "+f"(c[1]), "+f"(c[2]), "+f"(c[3])
        : "r"(a0), "r"(a1), "r"(a2), "r"(a3), "r"(b0), "r"(b1));
}

// ---------------------------------------------------------------------------
// fp32 -> fp16 conversion pre-pass
// ---------------------------------------------------------------------------
__global__ __launch_bounds__(256)
void cvt_in(const float* __restrict__ q, const float* __restrict__ k,
            const float* __restrict__ v,
            __half* __restrict__ qh, __half* __restrict__ kh,
            __half* __restrict__ vh)
{
    const int z = blockIdx.z;
    const float* s = z == 0 ? q  : (z == 1 ? k  : v);
    __half*      d = z == 0 ? qh : (z == 1 ? kh : vh);
    int i = blockIdx.x * 256 + threadIdx.x;          // float4 index
    float4 f = ((const float4*)s)[i];
    ((uint2*)d)[i] = make_uint2(pack_f16x2(f.x, f.y), pack_f16x2(f.z, f.w));
}

__global__ __launch_bounds__(256)
void cvt_w(const float* __restrict__ Wq, const float* __restrict__ Wk,
           const float* __restrict__ Wv, const float* __restrict__ Wo,
           __half* __restrict__ Wqh, __half* __restrict__ Wkh,
           __half* __restrict__ Wvh, __half* __restrict__ Woh)
{
    const int z = blockIdx.z;
    const float* s = z == 0 ? Wq  : (z == 1 ? Wk  : (z == 2 ? Wv  : Wo));
    __half*      d = z == 0 ? Wqh : (z == 1 ? Wkh : (z == 2 ? Wvh : Woh));
    int i = blockIdx.x * 256 + threadIdx.x;
    float4 f = ((const float4*)s)[i];
    ((uint2*)d)[i] = make_uint2(pack_f16x2(f.x, f.y), pack_f16x2(f.z, f.w));
}

// mask fp32 (1.0 = masked) -> f16 additive mask (0 or -inf)
__global__ __launch_bounds__(256)
void cvt_mask(const float* __restrict__ mask, __half* __restrict__ mkh)
{
    int i = blockIdx.x * 256 + threadIdx.x;
    mkh[i] = __ushort_as_half(mask[i] > 0.5f ? (unsigned short)0xFC00
                                             : (unsigned short)0x0000);
}

// ---------------------------------------------------------------------------
// pure-fp16 GEMM, 3-stage cp.async ring, BK=64. C = X @ W (+bias) [*scale].
// Block 128x128, 8 warps (4m x 2n), warp tile 32x64, 8 K-chunks of 64.
// Per-chunk compute is 64 MMA/warp -> each wait covered by ~2 big chunks;
// barrier count halved vs BK=32.  MODE 0: fp16 head-split out; MODE 1: fp32.
// ---------------------------------------------------------------------------
#define ASTR 72
#define BSTR 136
#define A_BYTES (128 * ASTR * 2)
#define B_BYTES (64 * BSTR * 2)
#define STAGE_BYTES (A_BYTES + B_BYTES)
#define GEMM_SMEM_BYTES (3 * STAGE_BYTES)

template <int MODE>
__device__ __forceinline__ void gemm_f16_body(
    const __half* __restrict__ X, const __half* __restrict__ W,
    const float* __restrict__ bias, void* outp, float scale, char* sh)
{
    const int tid  = threadIdx.x;
    const int wid  = tid >> 5;
    const int lane = tid & 31;
    const int g    = lane >> 2;
    const int tig  = lane & 3;
    const int wm   = (wid & 3) << 5;
    const int wn   = (wid >> 2) << 6;
    const int lrow = (lane & 7) + ((lane >> 3) & 1) * 8;
    const int lcol = (lane >> 4) << 3;

    const int m0 = blockIdx.y << 7;
    const int n0 = blockIdx.x << 7;

    const unsigned sh_b = (unsigned)__cvta_generic_to_shared(sh);

    float c[2][8][4];
#pragma unroll
    for (int mt = 0; mt < 2; mt++)
#pragma unroll
        for (int nt = 0; nt < 8; nt++)
#pragma unroll
            for (int j = 0; j < 4; j++) c[mt][nt][j] = 0.f;

    auto issue = [&](int kc, int s) {
        const int k0 = kc << 6;
        unsigned as = sh_b + s * STAGE_BYTES;
        unsigned bs = as + A_BYTES;
#pragma unroll
        for (int p = 0; p < 4; p++) {
            int i = tid + (p << 8);
            int r = i >> 3, cc = (i & 7) << 3;
            cp16(as + (r * ASTR + cc) * 2, X + (size_t)(m0 + r) * DMc + k0 + cc);
        }
#pragma unroll
        for (int p = 0; p < 4; p++) {
            int i = tid + (p << 8);
            int r = i >> 4, cc = (i & 15) << 3;
            cp16(bs + (r * BSTR + cc) * 2, W + (size_t)(k0 + r) * DMc + n0 + cc);
        }
        cp_commit();
    };

    issue(0, 0);
    issue(1, 1);

    for (int kc = 0; kc < 8; kc++) {
        if (kc < 7) cp_wait<1>();
        else        cp_wait<0>();
        __syncthreads();
        if (kc + 2 < 8) issue(kc + 2, (kc + 2) % 3);

        const unsigned as_b = sh_b + (kc % 3) * STAGE_BYTES;
        const unsigned bs_b = as_b + A_BYTES;
#pragma unroll
        for (int ks = 0; ks < 4; ks++) {
            const int kb = ks << 4;
            unsigned a[2][4];
#pragma unroll
            for (int mt = 0; mt < 2; mt++) {
                unsigned addr = as_b +
                    (((wm + (mt << 4) + lrow) * ASTR) + kb + lcol) * 2;
                ldsm_x4(a[mt][0], a[mt][1], a[mt][2], a[mt][3], addr);
            }
#pragma unroll
            for (int np = 0; np < 4; np++) {
                unsigned addr = bs_b +
                    (((kb + lrow) * BSTR) + wn + (np << 4) + lcol) * 2;
                unsigned r0, r1, r2, r3;
                ldsm_x4_t(r0, r1, r2, r3, addr);
                mma_f16(c[0][2 * np],     a[0][0], a[0][1], a[0][2], a[0][3], r0, r1);
                mma_f16(c[0][2 * np + 1], a[0][0], a[0][1], a[0][2], a[0][3], r2, r3);
                mma_f16(c[1][2 * np],     a[1][0], a[1][1], a[1][2], a[1][3], r0, r1);
                mma_f16(c[1][2 * np + 1], a[1][0], a[1][1], a[1][2], a[1][3], r2, r3);
            }
        }
    }

    const int b_ = m0 >> 12;
#pragma unroll
    for (int mt = 0; mt < 2; mt++) {
        int m  = m0 + wm + (mt << 4) + g;
        int s_ = m & (Sc - 1);
#pragma unroll
        for (int nt = 0; nt < 8; nt++) {
            int n = n0 + wn + (nt << 3) + (tig << 1);
            float bx = bias[n], by = bias[n + 1];
            if (MODE == 0) {
                __half* out = (__half*)outp;
                int h = n >> 6;
                int d = n & 63;
                unsigned u0 = pack_f16x2((c[mt][nt][0] + bx) * scale,
                                         (c[mt][nt][1] + by) * scale);
                unsigned u1 = pack_f16x2((c[mt][nt][2] + bx) * scale,
                                         (c[mt][nt][3] + by) * scale);
                __half* base = out + ((size_t)(b_ * Hc + h) * Sc) * Dc + d;
                *(unsigned*)(base + (size_t)s_ * Dc)       = u0;
                *(unsigned*)(base + (size_t)(s_ + 8) * Dc) = u1;
            } else {
                float* out = (float*)outp;
                *(float2*)(out + (size_t)m * DMc + n) =
                    make_float2(c[mt][nt][0] + bx, c[mt][nt][1] + by);
                *(float2*)(out + (size_t)(m + 8) * DMc + n) =
                    make_float2(c[mt][nt][2] + bx, c[mt][nt][3] + by);
            }
        }
    }
}

__global__ __launch_bounds__(256, 2)
void gemm_qkv(const __half* __restrict__ qh, const __half* __restrict__ kh,
              const __half* __restrict__ vh,
              const __half* __restrict__ Wqh, const __half* __restrict__ Wkh,
              const __half* __restrict__ Wvh,
              const float* __restrict__ bq, const float* __restrict__ bk,
              const float* __restrict__ bv,
              __half* __restrict__ Qp, __half* __restrict__ Kp,
              __half* __restrict__ Vp)
{
    extern __shared__ __align__(16) char shdyn[];
    const int z = blockIdx.z;
    const __half* X    = z == 0 ? qh  : (z == 1 ? kh  : vh);
    const __half* W    = z == 0 ? Wqh : (z == 1 ? Wkh : Wvh);
    const float*  bias = z == 0 ? bq  : (z == 1 ? bk  : bv);
    __half*       out  = z == 0 ? Qp  : (z == 1 ? Kp  : Vp);
    gemm_f16_body<0>(X, W, bias, out, z == 0 ? SCL : 1.0f, shdyn);
}

__global__ __launch_bounds__(256, 2)
void gemm_out(const __half* __restrict__ X, const __half* __restrict__ W,
              const float* __restrict__ bias, float* __restrict__ out)
{
    extern __shared__ __align__(16) char shdyn[];
    gemm_f16_body<1>(X, W, bias, out, 1.0f, shdyn);
}

// ---------------------------------------------------------------------------
// Flash attention, fp16 mma + ldmatrix, cp.async double-buffered 128-key
// macro-tiles (two 64-key sub-steps per barrier -> half the syncs).
// Block: 128 threads (4 warps), BQ=128 (32 rows/warp), D=64.
// Q A-fragments hoisted into registers. Mask fused as f16 -inf in exp chain.
// EPOCH-MAX refreshed every 4th 64-key sub-tile (t even, sub 0) -- identical
// cadence/numerics to the 64-key version.
// smem halves: Qs[128][72] | Ks[2][128][72] | Vs[2][128][72] | mk16[2][128]
// ---------------------------------------------------------------------------
#define HSTR 72
#define QS_HALVES (128 * HSTR)
#define KV_STAGE_HALVES (128 * HSTR)
#define KS_HOFF QS_HALVES
#define VS_HOFF (QS_HALVES + 2 * KV_STAGE_HALVES)
#define MK_BYTE_OFF ((QS_HALVES + 4 * KV_STAGE_HALVES) * 2)
#define ATTN_SMEM_BYTES (MK_BYTE_OFF + 2 * 128 * 2)

#define ONES16X2 0x3C003C00u

__global__ __launch_bounds__(128, 2)
void attn_f16(const __half* __restrict__ Qp, const __half* __restrict__ Kp,
              const __half* __restrict__ Vp, const __half* __restrict__ mkh,
              __half* __restrict__ Ao)
{
    extern __shared__ __align__(16) char smc[];
    __half* Qs = (__half*)smc;

    const unsigned qs_b = (unsigned)__cvta_generic_to_shared(smc);
    const unsigned ks_b = qs_b + KS_HOFF * 2;
    const unsigned vs_b = qs_b + VS_HOFF * 2;
    const unsigned mk_b = qs_b + MK_BYTE_OFF;

    const int tid  = threadIdx.x;
    const int wid  = tid >> 5;
    const int lane = tid & 31;
    const int g    = lane >> 2;
    const int tig  = lane & 3;
    const int wm   = wid << 5;          // warp's 32-row base
    const int lrow = (lane & 7) + ((lane >> 3) & 1) * 8;
    const int lcol = (lane >> 4) << 3;

    const int bh = blockIdx.y;
    const int b  = bh >> 3;
    const int h  = bh & 7;
    const int q0 = blockIdx.x << 7;

    const __half* Qb = Qp + ((size_t)bh * Sc + q0) * Dc;
    const __half* Kb = Kp + (size_t)bh * Sc * Dc;
    const __half* Vb = Vp + (size_t)bh * Sc * Dc;
    const __half* mb = mkh + (size_t)b * Sc;

    // stage issuer: K/V macro-tile t (128 rows) + f16 mask slice into stage s
    auto issue = [&](int t, int s) {
        const __half* Kt = Kb + (size_t)(t << 7) * Dc;
        const __half* Vt = Vb + (size_t)(t << 7) * Dc;
        unsigned ks = ks_b + s * KV_STAGE_HALVES * 2;
        unsigned vs = vs_b + s * KV_STAGE_HALVES * 2;
#pragma unroll
        for (int p = 0; p < 8; p++) {
            int i = tid + (p << 7);
            int r = i >> 3, cc = (i & 7) << 3;
            cp16(ks + (r * HSTR + cc) * 2, Kt + r * Dc + cc);
            cp16(vs + (r * HSTR + cc) * 2, Vt + r * Dc + cc);
        }
        if (tid < 16) cp16(mk_b + s * 256 + tid * 16, mb + (t << 7) + tid * 8);
        cp_commit();
    };

    issue(0, 0);

    // Q tile copy (fp16, already scaled by gemm), then hoist A-fragments
#pragma unroll
    for (int p = 0; p < 8; p++) {
        int i = tid + (p << 7);
        int r = i >> 3, cc = (i & 7) << 3;
        *(uint4*)&Qs[r * HSTR + cc] = *(const uint4*)(Qb + r * Dc + cc);
    }
    __syncthreads();

    unsigned qa[2][4][4];       // [mt][kb4][frag] -- loop-invariant
#pragma unroll
    for (int mt = 0; mt < 2; mt++)
#pragma unroll
        for (int kb4 = 0; kb4 < 4; kb4++) {
            unsigned addr = qs_b +
                (((wm + (mt << 4) + lrow) * HSTR) + (kb4 << 4) + lcol) * 2;
            ldsm_x4(qa[mt][kb4][0], qa[mt][kb4][1],
                    qa[mt][kb4][2], qa[mt][kb4][3], addr);
        }

    float m_i[4] = {-INFINITY, -INFINITY, -INFINITY, -INFINITY};
    // o[mt][8] is the ones-column accumulator = running row sum l
    float o[2][9][4];
#pragma unroll
    for (int mt = 0; mt < 2; mt++)
#pragma unroll
        for (int nt = 0; nt < 9; nt++)
#pragma unroll
            for (int j = 0; j < 4; j++) o[mt][nt][j] = 0.f;

    const int NT = Sc / 128;            // 32 macro-tiles
    for (int t = 0; t < NT; t++) {
        const int s = t & 1;
        if (t < NT - 1) { issue(t + 1, s ^ 1); cp_wait<1>(); }
        else            { cp_wait<0>(); }
        __syncthreads();

        const unsigned ks_st = ks_b + s * KV_STAGE_HALVES * 2;
        const unsigned vs_st = vs_b + s * KV_STAGE_HALVES * 2;

#pragma unroll
        for (int sub = 0; sub < 2; sub++) {
            const unsigned ks_s = ks_st + sub * 64 * HSTR * 2;
            const unsigned vs_s = vs_st + sub * 64 * HSTR * 2;
            const __half*  mksh = (const __half*)(smc + MK_BYTE_OFF)
                                  + s * 128 + sub * 64;

            // ---- S = Q @ K^T (Q fragments from registers) ----
            float c[2][8][4];
#pragma unroll
            for (int mt = 0; mt < 2; mt++)
#pragma unroll
                for (int nt = 0; nt < 8; nt++)
#pragma unroll
                    for (int j = 0; j < 4; j++) c[mt][nt][j] = 0.f;

#pragma unroll
            for (int kb4 = 0; kb4 < 4; kb4++) {
                const int kb = kb4 << 4;
#pragma unroll
                for (int np = 0; np < 4; np++) {
                    unsigned addr = ks_s +
                        ((((np << 4) + lrow) * HSTR) + kb + lcol) * 2;
                    unsigned b0e, b0o, b1e, b1o;
                    ldsm_x4(b0e, b0o, b1e, b1o, addr);
                    mma_f16(c[0][2 * np],     qa[0][kb4][0], qa[0][kb4][1],
                            qa[0][kb4][2], qa[0][kb4][3], b0e, b1e);
                    mma_f16(c[0][2 * np + 1], qa[0][kb4][0], qa[0][kb4][1],
                            qa[0][kb4][2], qa[0][kb4][3], b0o, b1o);
                    mma_f16(c[1][2 * np],     qa[1][kb4][0], qa[1][kb4][1],
                            qa[1][kb4][2], qa[1][kb4][3], b0e, b1e);
                    mma_f16(c[1][2 * np + 1], qa[1][kb4][0], qa[1][kb4][1],
                            qa[1][kb4][2], qa[1][kb4][3], b0o, b1o);
                }
            }

            // ---- epoch boundary (every 4th sub-tile): refresh max, rescale
            if (((t & 1) == 0) && sub == 0) {
#pragma unroll
                for (int mt = 0; mt < 2; mt++) {
                    float vmax0 = -INFINITY, vmax1 = -INFINITY;
#pragma unroll
                    for (int nt = 0; nt < 8; nt++) {
                        vmax0 = fmaxf(vmax0, fmaxf(c[mt][nt][0], c[mt][nt][1]));
                        vmax1 = fmaxf(vmax1, fmaxf(c[mt][nt][2], c[mt][nt][3]));
                    }
                    vmax0 = fmaxf(vmax0, __shfl_xor_sync(0xffffffffu, vmax0, 1));
                    vmax0 = fmaxf(vmax0, __shfl_xor_sync(0xffffffffu, vmax0, 2));
                    vmax1 = fmaxf(vmax1, __shfl_xor_sync(0xffffffffu, vmax1, 1));
                    vmax1 = fmaxf(vmax1, __shfl_xor_sync(0xffffffffu, vmax1, 2));

                    float mn0 = fmaxf(m_i[mt * 2 + 0], vmax0);
                    float mn1 = fmaxf(m_i[mt * 2 + 1], vmax1);
                    float al0 = ex2(m_i[mt * 2 + 0] - mn0);
                    float al1 = ex2(m_i[mt * 2 + 1] - mn1);
                    m_i[mt * 2 + 0] = mn0;
                    m_i[mt * 2 + 1] = mn1;
#pragma unroll
                    for (int nt = 0; nt < 9; nt++) {
                        o[mt][nt][0] *= al0; o[mt][nt][1] *= al0;
                        o[mt][nt][2] *= al1; o[mt][nt][3] *= al1;
                    }
                }
            }

            // ---- exp: pack (s - mn), add f16 mask (-inf), ex2.f16x2 ----
            unsigned mku[8];
#pragma unroll
            for (int nt = 0; nt < 8; nt++)
                mku[nt] = *(const unsigned*)&mksh[(nt << 3) + (tig << 1)];

            unsigned pu[2][8][2];
#pragma unroll
            for (int mt = 0; mt < 2; mt++) {
                float mn0 = m_i[mt * 2 + 0];
                float mn1 = m_i[mt * 2 + 1];
#pragma unroll
                for (int nt = 0; nt < 8; nt++) {
                    pu[mt][nt][0] = ex2_f16x2(hadd2(
                        pack_f16x2(c[mt][nt][0] - mn0, c[mt][nt][1] - mn0),
                        mku[nt]));
                    pu[mt][nt][1] = ex2_f16x2(hadd2(
                        pack_f16x2(c[mt][nt][2] - mn1, c[mt][nt][3] - mn1),
                        mku[nt]));
                }
            }

            // ---- O += P @ V ;  l-column += P @ ones ----
#pragma unroll
            for (int kb4 = 0; kb4 < 4; kb4++) {
                unsigned pa[2][4];
#pragma unroll
                for (int mt = 0; mt < 2; mt++) {
                    pa[mt][0] = pu[mt][2 * kb4][0];
                    pa[mt][1] = pu[mt][2 * kb4][1];
                    pa[mt][2] = pu[mt][2 * kb4 + 1][0];
                    pa[mt][3] = pu[mt][2 * kb4 + 1][1];
                }
#pragma unroll
                for (int dp = 0; dp < 4; dp++) {
                    unsigned addr = vs_s +
                        ((((kb4 << 4) + lrow) * HSTR) + (dp << 4) + lcol) * 2;
                    unsigned r0, r1, r2, r3;
                    ldsm_x4_t(r0, r1, r2, r3, addr);
                    mma_f16(o[0][2 * dp],     pa[0][0], pa[0][1], pa[0][2], pa[0][3], r0, r1);
                    mma_f16(o[0][2 * dp + 1], pa[0][0], pa[0][1], pa[0][2], pa[0][3], r2, r3);
                    mma_f16(o[1][2 * dp],     pa[1][0], pa[1][1], pa[1][2], pa[1][3], r0, r1);
                    mma_f16(o[1][2 * dp + 1], pa[1][0], pa[1][1], pa[1][2], pa[1][3], r2, r3);
                }
                mma_f16(o[0][8], pa[0][0], pa[0][1], pa[0][2], pa[0][3],
                        ONES16X2, ONES16X2);
                mma_f16(o[1][8], pa[1][0], pa[1][1], pa[1][2], pa[1][3],
                        ONES16X2, ONES16X2);
            }
        }
        __syncthreads();
    }

    // ---- epilogue: normalize by l (ones-column), write fp16 Ao ----
    __half* AoB = Ao + ((size_t)b * Sc) * DMc + h * Dc;
#pragma unroll
    for (int mt = 0; mt < 2; mt++) {
        float inv0 = 1.f / o[mt][8][0];
        float inv1 = 1.f / o[mt][8][2];
        int r0 = q0 + wm + (mt << 4) + g;
#pragma unroll
        for (int nt = 0; nt < 8; nt++) {
            int d = (nt << 3) + (tig << 1);
            *(unsigned*)(AoB + (size_t)r0 * DMc + d) =
                pack_f16x2(o[mt][nt][0] * inv0, o[mt][nt][1] * inv0);
            *(unsigned*)(AoB + (size_t)(r0 + 8) * DMc + d) =
                pack_f16x2(o[mt][nt][2] * inv1, o[mt][nt][3] * inv1);
        }
    }
}

// ---------------------------------------------------------------------------
extern "C" void kernel_launch(void* const* d_in, const int* in_sizes, int n_in,
                              void* d_out, int out_size)
{
    const float* q    = (const float*)d_in[0];
    const float* k    = (const float*)d_in[1];
    const float* v    = (const float*)d_in[2];
    const float* mask = (const float*)d_in[3];
    const float* Wq   = (const float*)d_in[4];
    const float* bq   = (const float*)d_in[5];
    const float* Wk   = (const float*)d_in[6];
    const float* bk   = (const float*)d_in[7];
    const float* Wv   = (const float*)d_in[8];
    const float* bv   = (const float*)d_in[9];
    const float* Wo   = (const float*)d_in[10];
    const float* bo   = (const float*)d_in[11];
    float* out = (float*)d_out;

    __half *qh, *kh, *vh, *Wqh, *Wkh, *Wvh, *Woh, *Qp, *Kp, *Vp, *Ao, *mkh;
    cudaGetSymbolAddress((void**)&qh,  g_qh);
    cudaGetSymbolAddress((void**)&kh,  g_kh);
    cudaGetSymbolAddress((void**)&vh,  g_vh);
    cudaGetSymbolAddress((void**)&Wqh, g_Wqh);
    cudaGetSymbolAddress((void**)&Wkh, g_Wkh);
    cudaGetSymbolAddress((void**)&Wvh, g_Wvh);
    cudaGetSymbolAddress((void**)&Woh, g_Woh);
    cudaGetSymbolAddress((void**)&Qp,  g_Qp);
    cudaGetSymbolAddress((void**)&Kp,  g_Kp);
    cudaGetSymbolAddress((void**)&Vp,  g_Vp);
    cudaGetSymbolAddress((void**)&Ao,  g_Ao);
    cudaGetSymbolAddress((void**)&mkh, g_mkh);

    cudaFuncSetAttribute(attn_f16, cudaFuncAttributeMaxDynamicSharedMemorySize,
                         ATTN_SMEM_BYTES);
    cudaFuncSetAttribute(gemm_qkv, cudaFuncAttributeMaxDynamicSharedMemorySize,
                         GEMM_SMEM_BYTES);
    cudaFuncSetAttribute(gemm_out, cudaFuncAttributeMaxDynamicSharedMemorySize,
                         GEMM_SMEM_BYTES);

    dim3 gin(Mc * DMc / 4 / 256, 1, 3);     // (4096,1,3)
    cvt_in<<<gin, 256>>>(q, k, v, qh, kh, vh);
    dim3 gw(DMc * DMc / 4 / 256, 1, 4);     // (256,1,4)
    cvt_w<<<gw, 256>>>(Wq, Wk, Wv, Wo, Wqh, Wkh, Wvh, Woh);
    cvt_mask<<<Bc * Sc / 256, 256>>>(mask, mkh);

    dim3 gqkv(DMc / 128, Mc / 128, 3);      // (4, 64, 3)
    gemm_qkv<<<gqkv, 256, GEMM_SMEM_BYTES>>>(qh, kh, vh, Wqh, Wkh, Wvh,
                                             bq, bk, bv, Qp, Kp, Vp);

    dim3 ga(Sc / 128, Bc * Hc);             // (32, 16)
    attn_f16<<<ga, 128, ATTN_SMEM_BYTES>>>(Qp, Kp, Vp, mkh, Ao);

    dim3 gg(DMc / 128, Mc / 128);           // (4, 64)
    gemm_out<<<gg, 256, GEMM_SMEM_BYTES>>>(Ao, Woh, bo, out);
}

// round 14
// speedup vs baseline: 1.1928x; 1.0230x over previous
#include <cuda_runtime.h>
#include <cuda_fp16.h>
#include <math.h>

#define Bc  2
#define Sc  4096
#define DMc 512
#define Hc  8
#define Dc  64
#define Mc  (Bc * Sc)   // 8192

#define SCL (0.125f * 1.44269504f)

// fp16 mirrors of inputs/weights + fp16 scratch
__device__ __half g_qh[Mc * DMc];
__device__ __half g_kh[Mc * DMc];
__device__ __half g_vh[Mc * DMc];
__device__ __half g_Wqh[DMc * DMc];
__device__ __half g_Wkh[DMc * DMc];
__device__ __half g_Wvh[DMc * DMc];
__device__ __half g_Woh[DMc * DMc];
__device__ __half g_Qp[Bc * Hc * Sc * Dc];
__device__ __half g_Kp[Bc * Hc * Sc * Dc];
__device__ __half g_Vp[Bc * Hc * Sc * Dc];
__device__ __half g_Ao[Mc * DMc];
__device__ __half g_mkh[Bc * Sc];          // mask as f16: 0 or -inf

// ---------------------------------------------------------------------------
// helpers
// ---------------------------------------------------------------------------
__device__ __forceinline__ unsigned pack_f16x2(float lo, float hi) {
    unsigned r;
    asm("cvt.rn.f16x2.f32 %0, %1, %2;" : "=r"(r) : "f"(hi), "f"(lo));
    return r;
}

__device__ __forceinline__ float ex2(float x) {
    float r;
    asm("ex2.approx.f32 %0, %1;" : "=f"(r) : "f"(x));
    return r;
}

__device__ __forceinline__ unsigned ex2_f16x2(unsigned x) {
    unsigned r;
    asm("ex2.approx.f16x2 %0, %1;" : "=r"(r) : "r"(x));
    return r;
}

__device__ __forceinline__ unsigned hadd2(unsigned a, unsigned b) {
    unsigned r;
    asm("add.rn.f16x2 %0, %1, %2;" : "=r"(r) : "r"(a), "r"(b));
    return r;
}

__device__ __forceinline__ void cp16(unsigned dst, const void* src) {
    asm volatile("cp.async.cg.shared.global [%0], [%1], 16;"
                 :: "r"(dst), "l"(__cvta_generic_to_global(src)));
}
__device__ __forceinline__ void cp_commit() {
    asm volatile("cp.async.commit_group;");
}
template <int N>
__device__ __forceinline__ void cp_wait() {
    asm volatile("cp.async.wait_group %0;" :: "n"(N));
}

__device__ __forceinline__ void ldsm_x4(unsigned& r0, unsigned& r1,
                                        unsigned& r2, unsigned& r3,
                                        unsigned addr) {
    asm volatile("ldmatrix.sync.aligned.m8n8.x4.shared.b16 {%0,%1,%2,%3}, [%4];"
                 : "=r"(r0), "=r"(r1), "=r"(r2), "=r"(r3) : "r"(addr));
}
__device__ __forceinline__ void ldsm_x4_t(unsigned& r0, unsigned& r1,
                                          unsigned& r2, unsigned& r3,
                                          unsigned addr) {
    asm volatile("ldmatrix.sync.aligned.m8n8.x4.trans.shared.b16 {%0,%1,%2,%3}, [%4];"
                 : "=r"(r0), "=r"(r1), "=r"(r2), "=r"(r3) : "r"(addr));
}
__device__ __forceinline__ void mma_f16(float c[4], unsigned a0, unsigned a1,
                                        unsigned a2, unsigned a3,
                                        unsigned b0, unsigned b1) {
    asm volatile(
        "mma.sync.aligned.m16n8k16.row.col.f32.f16.f16.f32 "
        "{%0,%1,%2,%3}, {%4,%5,%6,%7}, {%8,%9}, {%0,%1,%2,%3};\n"
        : "+f"(c[0]), "+f"(c[1]), "+f"(c[2]), "+f"(c[3])
        : "r"(a0), "r"(a1), "r"(a2), "r"(a3), "r"(b0), "r"(b1));
}

// ---------------------------------------------------------------------------
// merged fp32 -> fp16 conversion pre-pass (inputs + weights + mask, 1 launch)
// block ranges: [0, 12288) inputs (4096/tensor), [12288, 13312) weights
// (256/matrix), [13312, 13320) mask.
// ---------------------------------------------------------------------------
#define IN_BLKS  (Mc * DMc / 1024)     // 4096
#define W_BLKS   (DMc * DMc / 1024)    // 256
#define CVT_BLKS (3 * IN_BLKS + 4 * W_BLKS + Bc * Sc / 1024)  // 13320

__global__ __launch_bounds__(256)
void cvt_all(const float* __restrict__ q, const float* __restrict__ k,
             const float* __restrict__ v,
             const float* __restrict__ Wq, const float* __restrict__ Wk,
             const float* __restrict__ Wv, const float* __restrict__ Wo,
             const float* __restrict__ mask,
             __half* __restrict__ qh, __half* __restrict__ kh,
             __half* __restrict__ vh,
             __half* __restrict__ Wqh, __half* __restrict__ Wkh,
             __half* __restrict__ Wvh, __half* __restrict__ Woh,
             __half* __restrict__ mkh)
{
    const int bid = blockIdx.x;
    const int tid = threadIdx.x;

    if (bid < 3 * IN_BLKS) {
        const int z = bid / IN_BLKS;
        const int i = (bid % IN_BLKS) * 256 + tid;
        const float* s = z == 0 ? q  : (z == 1 ? k  : v);
        __half*      d = z == 0 ? qh : (z == 1 ? kh : vh);
        float4 f = ((const float4*)s)[i];
        ((uint2*)d)[i] = make_uint2(pack_f16x2(f.x, f.y), pack_f16x2(f.z, f.w));
    } else if (bid < 3 * IN_BLKS + 4 * W_BLKS) {
        const int r = bid - 3 * IN_BLKS;
        const int z = r / W_BLKS;
        const int i = (r % W_BLKS) * 256 + tid;
        const float* s = z == 0 ? Wq  : (z == 1 ? Wk  : (z == 2 ? Wv  : Wo));
        __half*      d = z == 0 ? Wqh : (z == 1 ? Wkh : (z == 2 ? Wvh : Woh));
        float4 f = ((const float4*)s)[i];
        ((uint2*)d)[i] = make_uint2(pack_f16x2(f.x, f.y), pack_f16x2(f.z, f.w));
    } else {
        const int i = (bid - 3 * IN_BLKS - 4 * W_BLKS) * 256 + tid;  // float4
        float4 f = ((const float4*)mask)[i];
        unsigned lo = (f.x > 0.5f ? 0xFC00u : 0u) |
                      ((f.y > 0.5f ? 0xFC00u : 0u) << 16);
        unsigned hi = (f.z > 0.5f ? 0xFC00u : 0u) |
                      ((f.w > 0.5f ? 0xFC00u : 0u) << 16);
        ((uint2*)mkh)[i] = make_uint2(lo, hi);
    }
}

// ---------------------------------------------------------------------------
// pure-fp16 GEMM, 3-stage cp.async ring, BK=64. C = X @ W (+bias) [*scale].
// Block 128x128, 8 warps (4m x 2n), warp tile 32x64, 8 K-chunks of 64.
// MODE 0: fp16 head-split out; MODE 1: fp32 row-major out.
// ---------------------------------------------------------------------------
#define ASTR 72
#define BSTR 136
#define A_BYTES (128 * ASTR * 2)
#define B_BYTES (64 * BSTR * 2)
#define STAGE_BYTES (A_BYTES + B_BYTES)
#define GEMM_SMEM_BYTES (3 * STAGE_BYTES)

template <int MODE>
__device__ __forceinline__ void gemm_f16_body(
    const __half* __restrict__ X, const __half* __restrict__ W,
    const float* __restrict__ bias, void* outp, float scale, char* sh)
{
    const int tid  = threadIdx.x;
    const int wid  = tid >> 5;
    const int lane = tid & 31;
    const int g    = lane >> 2;
    const int tig  = lane & 3;
    const int wm   = (wid & 3) << 5;
    const int wn   = (wid >> 2) << 6;
    const int lrow = (lane & 7) + ((lane >> 3) & 1) * 8;
    const int lcol = (lane >> 4) << 3;

    const int m0 = blockIdx.y << 7;
    const int n0 = blockIdx.x << 7;

    const unsigned sh_b = (unsigned)__cvta_generic_to_shared(sh);

    float c[2][8][4];
#pragma unroll
    for (int mt = 0; mt < 2; mt++)
#pragma unroll
        for (int nt = 0; nt < 8; nt++)
#pragma unroll
            for (int j = 0; j < 4; j++) c[mt][nt][j] = 0.f;

    auto issue = [&](int kc, int s) {
        const int k0 = kc << 6;
        unsigned as = sh_b + s * STAGE_BYTES;
        unsigned bs = as + A_BYTES;
#pragma unroll
        for (int p = 0; p < 4; p++) {
            int i = tid + (p << 8);
            int r = i >> 3, cc = (i & 7) << 3;
            cp16(as + (r * ASTR + cc) * 2, X + (size_t)(m0 + r) * DMc + k0 + cc);
        }
#pragma unroll
        for (int p = 0; p < 4; p++) {
            int i = tid + (p << 8);
            int r = i >> 4, cc = (i & 15) << 3;
            cp16(bs + (r * BSTR + cc) * 2, W + (size_t)(k0 + r) * DMc + n0 + cc);
        }
        cp_commit();
    };

    issue(0, 0);
    issue(1, 1);

    for (int kc = 0; kc < 8; kc++) {
        if (kc < 7) cp_wait<1>();
        else        cp_wait<0>();
        __syncthreads();
        if (kc + 2 < 8) issue(kc + 2, (kc + 2) % 3);

        const unsigned as_b = sh_b + (kc % 3) * STAGE_BYTES;
        const unsigned bs_b = as_b + A_BYTES;
#pragma unroll
        for (int ks = 0; ks < 4; ks++) {
            const int kb = ks << 4;
            unsigned a[2][4];
#pragma unroll
            for (int mt = 0; mt < 2; mt++) {
                unsigned addr = as_b +
                    (((wm + (mt << 4) + lrow) * ASTR) + kb + lcol) * 2;
                ldsm_x4(a[mt][0], a[mt][1], a[mt][2], a[mt][3], addr);
            }
#pragma unroll
            for (int np = 0; np < 4; np++) {
                unsigned addr = bs_b +
                    (((kb + lrow) * BSTR) + wn + (np << 4) + lcol) * 2;
                unsigned r0, r1, r2, r3;
                ldsm_x4_t(r0, r1, r2, r3, addr);
                mma_f16(c[0][2 * np],     a[0][0], a[0][1], a[0][2], a[0][3], r0, r1);
                mma_f16(c[0][2 * np + 1], a[0][0], a[0][1], a[0][2], a[0][3], r2, r3);
                mma_f16(c[1][2 * np],     a[1][0], a[1][1], a[1][2], a[1][3], r0, r1);
                mma_f16(c[1][2 * np + 1], a[1][0], a[1][1], a[1][2], a[1][3], r2, r3);
            }
        }
    }

    const int b_ = m0 >> 12;
#pragma unroll
    for (int mt = 0; mt < 2; mt++) {
        int m  = m0 + wm + (mt << 4) + g;
        int s_ = m & (Sc - 1);
#pragma unroll
        for (int nt = 0; nt < 8; nt++) {
            int n = n0 + wn + (nt << 3) + (tig << 1);
            float bx = bias[n], by = bias[n + 1];
            if (MODE == 0) {
                __half* out = (__half*)outp;
                int h = n >> 6;
                int d = n & 63;
                unsigned u0 = pack_f16x2((c[mt][nt][0] + bx) * scale,
                                         (c[mt][nt][1] + by) * scale);
                unsigned u1 = pack_f16x2((c[mt][nt][2] + bx) * scale,
                                         (c[mt][nt][3] + by) * scale);
                __half* base = out + ((size_t)(b_ * Hc + h) * Sc) * Dc + d;
                *(unsigned*)(base + (size_t)s_ * Dc)       = u0;
                *(unsigned*)(base + (size_t)(s_ + 8) * Dc) = u1;
            } else {
                float* out = (float*)outp;
                *(float2*)(out + (size_t)m * DMc + n) =
                    make_float2(c[mt][nt][0] + bx, c[mt][nt][1] + by);
                *(float2*)(out + (size_t)(m + 8) * DMc + n) =
                    make_float2(c[mt][nt][2] + bx, c[mt][nt][3] + by);
            }
        }
    }
}

__global__ __launch_bounds__(256, 2)
void gemm_qkv(const __half* __restrict__ qh, const __half* __restrict__ kh,
              const __half* __restrict__ vh,
              const __half* __restrict__ Wqh, const __half* __restrict__ Wkh,
              const __half* __restrict__ Wvh,
              const float* __restrict__ bq, const float* __restrict__ bk,
              const float* __restrict__ bv,
              __half* __restrict__ Qp, __half* __restrict__ Kp,
              __half* __restrict__ Vp)
{
    extern __shared__ __align__(16) char shdyn[];
    const int z = blockIdx.z;
    const __half* X    = z == 0 ? qh  : (z == 1 ? kh  : vh);
    const __half* W    = z == 0 ? Wqh : (z == 1 ? Wkh : Wvh);
    const float*  bias = z == 0 ? bq  : (z == 1 ? bk  : bv);
    __half*       out  = z == 0 ? Qp  : (z == 1 ? Kp  : Vp);
    gemm_f16_body<0>(X, W, bias, out, z == 0 ? SCL : 1.0f, shdyn);
}

__global__ __launch_bounds__(256, 2)
void gemm_out(const __half* __restrict__ X, const __half* __restrict__ W,
              const float* __restrict__ bias, float* __restrict__ out)
{
    extern __shared__ __align__(16) char shdyn[];
    gemm_f16_body<1>(X, W, bias, out, 1.0f, shdyn);
}

// ---------------------------------------------------------------------------
// Flash attention, fp16 mma + ldmatrix, cp.async double-buffered 128-key
// macro-tiles. SINGLE barrier per macro-tile: wait<0> -> barrier ->
// issue(t+1) -> compute(sub0, sub1). issue(t+1) is safe after the barrier:
// all warps have finished compute(t-1), the last reader of the stage being
// overwritten. Prefetch lead = one full macro-tile of compute.
// Block: 128 threads (4 warps), BQ=128 (32 rows/warp), D=64.
// Q A-fragments hoisted. Mask fused as f16 -inf in exp chain.
// EPOCH-MAX refreshed every 4th 64-key sub-tile.
// smem halves: Qs[128][72] | Ks[2][128][72] | Vs[2][128][72] | mk16[2][128]
// ---------------------------------------------------------------------------
#define HSTR 72
#define QS_HALVES (128 * HSTR)
#define KV_STAGE_HALVES (128 * HSTR)
#define KS_HOFF QS_HALVES
#define VS_HOFF (QS_HALVES + 2 * KV_STAGE_HALVES)
#define MK_BYTE_OFF ((QS_HALVES + 4 * KV_STAGE_HALVES) * 2)
#define ATTN_SMEM_BYTES (MK_BYTE_OFF + 2 * 128 * 2)

#define ONES16X2 0x3C003C00u

__global__ __launch_bounds__(128, 2)
void attn_f16(const __half* __restrict__ Qp, const __half* __restrict__ Kp,
              const __half* __restrict__ Vp, const __half* __restrict__ mkh,
              __half* __restrict__ Ao)
{
    extern __shared__ __align__(16) char smc[];
    __half* Qs = (__half*)smc;

    const unsigned qs_b = (unsigned)__cvta_generic_to_shared(smc);
    const unsigned ks_b = qs_b + KS_HOFF * 2;
    const unsigned vs_b = qs_b + VS_HOFF * 2;
    const unsigned mk_b = qs_b + MK_BYTE_OFF;

    const int tid  = threadIdx.x;
    const int wid  = tid >> 5;
    const int lane = tid & 31;
    const int g    = lane >> 2;
    const int tig  = lane & 3;
    const int wm   = wid << 5;          // warp's 32-row base
    const int lrow = (lane & 7) + ((lane >> 3) & 1) * 8;
    const int lcol = (lane >> 4) << 3;

    const int bh = blockIdx.y;
    const int b  = bh >> 3;
    const int h  = bh & 7;
    const int q0 = blockIdx.x << 7;

    const __half* Qb = Qp + ((size_t)bh * Sc + q0) * Dc;
    const __half* Kb = Kp + (size_t)bh * Sc * Dc;
    const __half* Vb = Vp + (size_t)bh * Sc * Dc;
    const __half* mb = mkh + (size_t)b * Sc;

    // stage issuer: K/V macro-tile t (128 rows) + f16 mask slice into stage s
    auto issue = [&](int t, int s) {
        const __half* Kt = Kb + (size_t)(t << 7) * Dc;
        const __half* Vt = Vb + (size_t)(t << 7) * Dc;
        unsigned ks = ks_b + s * KV_STAGE_HALVES * 2;
        unsigned vs = vs_b + s * KV_STAGE_HALVES * 2;
#pragma unroll
        for (int p = 0; p < 8; p++) {
            int i = tid + (p << 7);
            int r = i >> 3, cc = (i & 7) << 3;
            cp16(ks + (r * HSTR + cc) * 2, Kt + r * Dc + cc);
            cp16(vs + (r * HSTR + cc) * 2, Vt + r * Dc + cc);
        }
        if (tid < 16) cp16(mk_b + s * 256 + tid * 16, mb + (t << 7) + tid * 8);
        cp_commit();
    };

    issue(0, 0);

    // Q tile copy (fp16, already scaled by gemm), then hoist A-fragments
#pragma unroll
    for (int p = 0; p < 8; p++) {
        int i = tid + (p << 7);
        int r = i >> 3, cc = (i & 7) << 3;
        *(uint4*)&Qs[r * HSTR + cc] = *(const uint4*)(Qb + r * Dc + cc);
    }
    __syncthreads();

    unsigned qa[2][4][4];       // [mt][kb4][frag] -- loop-invariant
#pragma unroll
    for (int mt = 0; mt < 2; mt++)
#pragma unroll
        for (int kb4 = 0; kb4 < 4; kb4++) {
            unsigned addr = qs_b +
                (((wm + (mt << 4) + lrow) * HSTR) + (kb4 << 4) + lcol) * 2;
            ldsm_x4(qa[mt][kb4][0], qa[mt][kb4][1],
                    qa[mt][kb4][2], qa[mt][kb4][3], addr);
        }

    float m_i[4] = {-INFINITY, -INFINITY, -INFINITY, -INFINITY};
    // o[mt][8] is the ones-column accumulator = running row sum l
    float o[2][9][4];
#pragma unroll
    for (int mt = 0; mt < 2; mt++)
#pragma unroll
        for (int nt = 0; nt < 9; nt++)
#pragma unroll
            for (int j = 0; j < 4; j++) o[mt][nt][j] = 0.f;

    const int NT = Sc / 128;            // 32 macro-tiles
    for (int t = 0; t < NT; t++) {
        const int s = t & 1;
        cp_wait<0>();
        __syncthreads();
        if (t < NT - 1) issue(t + 1, s ^ 1);

        const unsigned ks_st = ks_b + s * KV_STAGE_HALVES * 2;
        const unsigned vs_st = vs_b + s * KV_STAGE_HALVES * 2;

#pragma unroll
        for (int sub = 0; sub < 2; sub++) {
            const unsigned ks_s = ks_st + sub * 64 * HSTR * 2;
            const unsigned vs_s = vs_st + sub * 64 * HSTR * 2;
            const __half*  mksh = (const __half*)(smc + MK_BYTE_OFF)
                                  + s * 128 + sub * 64;

            // ---- S = Q @ K^T (Q fragments from registers) ----
            float c[2][8][4];
#pragma unroll
            for (int mt = 0; mt < 2; mt++)
#pragma unroll
                for (int nt = 0; nt < 8; nt++)
#pragma unroll
                    for (int j = 0; j < 4; j++) c[mt][nt][j] = 0.f;

#pragma unroll
            for (int kb4 = 0; kb4 < 4; kb4++) {
                const int kb = kb4 << 4;
#pragma unroll
                for (int np = 0; np < 4; np++) {
                    unsigned addr = ks_s +
                        ((((np << 4) + lrow) * HSTR) + kb + lcol) * 2;
                    unsigned b0e, b0o, b1e, b1o;
                    ldsm_x4(b0e, b0o, b1e, b1o, addr);
                    mma_f16(c[0][2 * np],     qa[0][kb4][0], qa[0][kb4][1],
                            qa[0][kb4][2], qa[0][kb4][3], b0e, b1e);
                    mma_f16(c[0][2 * np + 1], qa[0][kb4][0], qa[0][kb4][1],
                            qa[0][kb4][2], qa[0][kb4][3], b0o, b1o);
                    mma_f16(c[1][2 * np],     qa[1][kb4][0], qa[1][kb4][1],
                            qa[1][kb4][2], qa[1][kb4][3], b0e, b1e);
                    mma_f16(c[1][2 * np + 1], qa[1][kb4][0], qa[1][kb4][1],
                            qa[1][kb4][2], qa[1][kb4][3], b0o, b1o);
                }
            }

            // ---- epoch boundary (every 4th sub-tile): refresh max, rescale
            if (((t & 1) == 0) && sub == 0) {
#pragma unroll
                for (int mt = 0; mt < 2; mt++) {
                    float vmax0 = -INFINITY, vmax1 = -INFINITY;
#pragma unroll
                    for (int nt = 0; nt < 8; nt++) {
                        vmax0 = fmaxf(vmax0, fmaxf(c[mt][nt][0], c[mt][nt][1]));
                        vmax1 = fmaxf(vmax1, fmaxf(c[mt][nt][2], c[mt][nt][3]));
                    }
                    vmax0 = fmaxf(vmax0, __shfl_xor_sync(0xffffffffu, vmax0, 1));
                    vmax0 = fmaxf(vmax0, __shfl_xor_sync(0xffffffffu, vmax0, 2));
                    vmax1 = fmaxf(vmax1, __shfl_xor_sync(0xffffffffu, vmax1, 1));
                    vmax1 = fmaxf(vmax1, __shfl_xor_sync(0xffffffffu, vmax1, 2));

                    float mn0 = fmaxf(m_i[mt * 2 + 0], vmax0);
                    float mn1 = fmaxf(m_i[mt * 2 + 1], vmax1);
                    float al0 = ex2(m_i[mt * 2 + 0] - mn0);
                    float al1 = ex2(m_i[mt * 2 + 1] - mn1);
                    m_i[mt * 2 + 0] = mn0;
                    m_i[mt * 2 + 1] = mn1;
#pragma unroll
                    for (int nt = 0; nt < 9; nt++) {
                        o[mt][nt][0] *= al0; o[mt][nt][1] *= al0;
                        o[mt][nt][2] *= al1; o[mt][nt][3] *= al1;
                    }
                }
            }

            // ---- exp: pack (s - mn), add f16 mask (-inf), ex2.f16x2 ----
            unsigned mku[8];
#pragma unroll
            for (int nt = 0; nt < 8; nt++)
                mku[nt] = *(const unsigned*)&mksh[(nt << 3) + (tig << 1)];

            unsigned pu[2][8][2];
#pragma unroll
            for (int mt = 0; mt < 2; mt++) {
                float mn0 = m_i[mt * 2 + 0];
                float mn1 = m_i[mt * 2 + 1];
#pragma unroll
                for (int nt = 0; nt < 8; nt++) {
                    pu[mt][nt][0] = ex2_f16x2(hadd2(
                        pack_f16x2(c[mt][nt][0] - mn0, c[mt][nt][1] - mn0),
                        mku[nt]));
                    pu[mt][nt][1] = ex2_f16x2(hadd2(
                        pack_f16x2(c[mt][nt][2] - mn1, c[mt][nt][3] - mn1),
                        mku[nt]));
                }
            }

            // ---- O += P @ V ;  l-column += P @ ones ----
#pragma unroll
            for (int kb4 = 0; kb4 < 4; kb4++) {
                unsigned pa[2][4];
#pragma unroll
                for (int mt = 0; mt < 2; mt++) {
                    pa[mt][0] = pu[mt][2 * kb4][0];
                    pa[mt][1] = pu[mt][2 * kb4][1];
                    pa[mt][2] = pu[mt][2 * kb4 + 1][0];
                    pa[mt][3] = pu[mt][2 * kb4 + 1][1];
                }
#pragma unroll
                for (int dp = 0; dp < 4; dp++) {
                    unsigned addr = vs_s +
                        ((((kb4 << 4) + lrow) * HSTR) + (dp << 4) + lcol) * 2;
                    unsigned r0, r1, r2, r3;
                    ldsm_x4_t(r0, r1, r2, r3, addr);
                    mma_f16(o[0][2 * dp],     pa[0][0], pa[0][1], pa[0][2], pa[0][3], r0, r1);
                    mma_f16(o[0][2 * dp + 1], pa[0][0], pa[0][1], pa[0][2], pa[0][3], r2, r3);
                    mma_f16(o[1][2 * dp],     pa[1][0], pa[1][1], pa[1][2], pa[1][3], r0, r1);
                    mma_f16(o[1][2 * dp + 1], pa[1][0], pa[1][1], pa[1][2], pa[1][3], r2, r3);
                }
                mma_f16(o[0][8], pa[0][0], pa[0][1], pa[0][2], pa[0][3],
                        ONES16X2, ONES16X2);
                mma_f16(o[1][8], pa[1][0], pa[1][1], pa[1][2], pa[1][3],
                        ONES16X2, ONES16X2);
            }
        }
    }

    // ---- epilogue: normalize by l (ones-column), write fp16 Ao ----
    __half* AoB = Ao + ((size_t)b * Sc) * DMc + h * Dc;
#pragma unroll
    for (int mt = 0; mt < 2; mt++) {
        float inv0 = 1.f / o[mt][8][0];
        float inv1 = 1.f / o[mt][8][2];
        int r0 = q0 + wm + (mt << 4) + g;
#pragma unroll
        for (int nt = 0; nt < 8; nt++) {
            int d = (nt << 3) + (tig << 1);
            *(unsigned*)(AoB + (size_t)r0 * DMc + d) =
                pack_f16x2(o[mt][nt][0] * inv0, o[mt][nt][1] * inv0);
            *(unsigned*)(AoB + (size_t)(r0 + 8) * DMc + d) =
                pack_f16x2(o[mt][nt][2] * inv1, o[mt][nt][3] * inv1);
        }
    }
}

// ---------------------------------------------------------------------------
extern "C" void kernel_launch(void* const* d_in, const int* in_sizes, int n_in,
                              void* d_out, int out_size)
{
    const float* q    = (const float*)d_in[0];
    const float* k    = (const float*)d_in[1];
    const float* v    = (const float*)d_in[2];
    const float* mask = (const float*)d_in[3];
    const float* Wq   = (const float*)d_in[4];
    const float* bq   = (const float*)d_in[5];
    const float* Wk   = (const float*)d_in[6];
    const float* bk   = (const float*)d_in[7];
    const float* Wv   = (const float*)d_in[8];
    const float* bv   = (const float*)d_in[9];
    const float* Wo   = (const float*)d_in[10];
    const float* bo   = (const float*)d_in[11];
    float* out = (float*)d_out;

    __half *qh, *kh, *vh, *Wqh, *Wkh, *Wvh, *Woh, *Qp, *Kp, *Vp, *Ao, *mkh;
    cudaGetSymbolAddress((void**)&qh,  g_qh);
    cudaGetSymbolAddress((void**)&kh,  g_kh);
    cudaGetSymbolAddress((void**)&vh,  g_vh);
    cudaGetSymbolAddress((void**)&Wqh, g_Wqh);
    cudaGetSymbolAddress((void**)&Wkh, g_Wkh);
    cudaGetSymbolAddress((void**)&Wvh, g_Wvh);
    cudaGetSymbolAddress((void**)&Woh, g_Woh);
    cudaGetSymbolAddress((void**)&Qp,  g_Qp);
    cudaGetSymbolAddress((void**)&Kp,  g_Kp);
    cudaGetSymbolAddress((void**)&Vp,  g_Vp);
    cudaGetSymbolAddress((void**)&Ao,  g_Ao);
    cudaGetSymbolAddress((void**)&mkh, g_mkh);

    cudaFuncSetAttribute(attn_f16, cudaFuncAttributeMaxDynamicSharedMemorySize,
                         ATTN_SMEM_BYTES);
    cudaFuncSetAttribute(gemm_qkv, cudaFuncAttributeMaxDynamicSharedMemorySize,
                         GEMM_SMEM_BYTES);
    cudaFuncSetAttribute(gemm_out, cudaFuncAttributeMaxDynamicSharedMemorySize,
                         GEMM_SMEM_BYTES);

    cvt_all<<<CVT_BLKS, 256>>>(q, k, v, Wq, Wk, Wv, Wo, mask,
                               qh, kh, vh, Wqh, Wkh, Wvh, Woh, mkh);

    dim3 gqkv(DMc / 128, Mc / 128, 3);      // (4, 64, 3)
    gemm_qkv<<<gqkv, 256, GEMM_SMEM_BYTES>>>(qh, kh, vh, Wqh, Wkh, Wvh,
                                             bq, bk, bv, Qp, Kp, Vp);

    dim3 ga(Sc / 128, Bc * Hc);             // (32, 16)
    attn_f16<<<ga, 128, ATTN_SMEM_BYTES>>>(Qp, Kp, Vp, mkh, Ao);

    dim3 gg(DMc / 128, Mc / 128);           // (4, 64)
    gemm_out<<<gg, 256, GEMM_SMEM_BYTES>>>(Ao, Woh, bo, out);
}

// round 15
// speedup vs baseline: 1.1941x; 1.0011x over previous
#include <cuda_runtime.h>
#include <cuda_fp16.h>
#include <math.h>

#define Bc  2
#define Sc  4096
#define DMc 512
#define Hc  8
#define Dc  64
#define Mc  (Bc * Sc)   // 8192

#define SCL (0.125f * 1.44269504f)

// fp16 mirrors of inputs/weights + fp16 scratch
__device__ __half g_qh[Mc * DMc];
__device__ __half g_kh[Mc * DMc];
__device__ __half g_vh[Mc * DMc];
__device__ __half g_Wqh[DMc * DMc];
__device__ __half g_Wkh[DMc * DMc];
__device__ __half g_Wvh[DMc * DMc];
__device__ __half g_Woh[DMc * DMc];
__device__ __half g_Qp[Bc * Hc * Sc * Dc];
__device__ __half g_Kp[Bc * Hc * Sc * Dc];
__device__ __half g_Vp[Bc * Hc * Sc * Dc];
__device__ __half g_Ao[Mc * DMc];
__device__ __half g_mkh[Bc * Sc];          // mask as f16: 0 or -inf

// ---------------------------------------------------------------------------
// helpers
// ---------------------------------------------------------------------------
__device__ __forceinline__ unsigned pack_f16x2(float lo, float hi) {
    unsigned r;
    asm("cvt.rn.f16x2.f32 %0, %1, %2;" : "=r"(r) : "f"(hi), "f"(lo));
    return r;
}

__device__ __forceinline__ float ex2(float x) {
    float r;
    asm("ex2.approx.f32 %0, %1;" : "=f"(r) : "f"(x));
    return r;
}

__device__ __forceinline__ unsigned ex2_f16x2(unsigned x) {
    unsigned r;
    asm("ex2.approx.f16x2 %0, %1;" : "=r"(r) : "r"(x));
    return r;
}

__device__ __forceinline__ unsigned hadd2(unsigned a, unsigned b) {
    unsigned r;
    asm("add.rn.f16x2 %0, %1, %2;" : "=r"(r) : "r"(a), "r"(b));
    return r;
}

__device__ __forceinline__ void cp16(unsigned dst, const void* src) {
    asm volatile("cp.async.cg.shared.global [%0], [%1], 16;"
                 :: "r"(dst), "l"(__cvta_generic_to_global(src)));
}
__device__ __forceinline__ void cp_commit() {
    asm volatile("cp.async.commit_group;");
}
template <int N>
__device__ __forceinline__ void cp_wait() {
    asm volatile("cp.async.wait_group %0;" :: "n"(N));
}

__device__ __forceinline__ void ldsm_x4(unsigned& r0, unsigned& r1,
                                        unsigned& r2, unsigned& r3,
                                        unsigned addr) {
    asm volatile("ldmatrix.sync.aligned.m8n8.x4.shared.b16 {%0,%1,%2,%3}, [%4];"
                 : "=r"(r0), "=r"(r1), "=r"(r2), "=r"(r3) : "r"(addr));
}
__device__ __forceinline__ void ldsm_x4_t(unsigned& r0, unsigned& r1,
                                          unsigned& r2, unsigned& r3,
                                          unsigned addr) {
    asm volatile("ldmatrix.sync.aligned.m8n8.x4.trans.shared.b16 {%0,%1,%2,%3}, [%4];"
                 : "=r"(r0), "=r"(r1), "=r"(r2), "=r"(r3) : "r"(addr));
}
__device__ __forceinline__ void mma_f16(float c[4], unsigned a0, unsigned a1,
                                        unsigned a2, unsigned a3,
                                        unsigned b0, unsigned b1) {
    asm volatile(
        "mma.sync.aligned.m16n8k16.row.col.f32.f16.f16.f32 "
        "{%0,%1,%2,%3}, {%4,%5,%6,%7}, {%8,%9}, {%0,%1,%2,%3};\n"
        : "+f"(c[0]), "+f"(c[1]), "+f"(c[2]), "+f"(c[3])
        : "r"(a0), "r"(a1), "r"(a2), "r"(a3), "r"(b0), "r"(b1));
}

// ---------------------------------------------------------------------------
// merged fp32 -> fp16 conversion pre-pass (inputs + weights + mask, 1 launch)
// ---------------------------------------------------------------------------
#define IN_BLKS  (Mc * DMc / 1024)     // 4096
#define W_BLKS   (DMc * DMc / 1024)    // 256
#define CVT_BLKS (3 * IN_BLKS + 4 * W_BLKS + Bc * Sc / 1024)  // 13320

__global__ __launch_bounds__(256)
void cvt_all(const float* __restrict__ q, const float* __restrict__ k,
             const float* __restrict__ v,
             const float* __restrict__ Wq, const float* __restrict__ Wk,
             const float* __restrict__ Wv, const float* __restrict__ Wo,
             const float* __restrict__ mask,
             __half* __restrict__ qh, __half* __restrict__ kh,
             __half* __restrict__ vh,
             __half* __restrict__ Wqh, __half* __restrict__ Wkh,
             __half* __restrict__ Wvh, __half* __restrict__ Woh,
             __half* __restrict__ mkh)
{
    const int bid = blockIdx.x;
    const int tid = threadIdx.x;

    if (bid < 3 * IN_BLKS) {
        const int z = bid / IN_BLKS;
        const int i = (bid % IN_BLKS) * 256 + tid;
        const float* s = z == 0 ? q  : (z == 1 ? k  : v);
        __half*      d = z == 0 ? qh : (z == 1 ? kh : vh);
        float4 f = ((const float4*)s)[i];
        ((uint2*)d)[i] = make_uint2(pack_f16x2(f.x, f.y), pack_f16x2(f.z, f.w));
    } else if (bid < 3 * IN_BLKS + 4 * W_BLKS) {
        const int r = bid - 3 * IN_BLKS;
        const int z = r / W_BLKS;
        const int i = (r % W_BLKS) * 256 + tid;
        const float* s = z == 0 ? Wq  : (z == 1 ? Wk  : (z == 2 ? Wv  : Wo));
        __half*      d = z == 0 ? Wqh : (z == 1 ? Wkh : (z == 2 ? Wvh : Woh));
        float4 f = ((const float4*)s)[i];
        ((uint2*)d)[i] = make_uint2(pack_f16x2(f.x, f.y), pack_f16x2(f.z, f.w));
    } else {
        const int i = (bid - 3 * IN_BLKS - 4 * W_BLKS) * 256 + tid;  // float4
        float4 f = ((const float4*)mask)[i];
        unsigned lo = (f.x > 0.5f ? 0xFC00u : 0u) |
                      ((f.y > 0.5f ? 0xFC00u : 0u) << 16);
        unsigned hi = (f.z > 0.5f ? 0xFC00u : 0u) |
                      ((f.w > 0.5f ? 0xFC00u : 0u) << 16);
        ((uint2*)mkh)[i] = make_uint2(lo, hi);
    }
}

// ---------------------------------------------------------------------------
// pure-fp16 GEMM, 3-stage cp.async ring, BK=64. C = X @ W (+bias) [*scale].
// Block 128x128, 8 warps (4m x 2n), warp tile 32x64, 8 K-chunks of 64.
// MODE 0: fp16 head-split out; MODE 1: fp32 row-major out.
// ---------------------------------------------------------------------------
#define ASTR 72
#define BSTR 136
#define A_BYTES (128 * ASTR * 2)
#define B_BYTES (64 * BSTR * 2)
#define STAGE_BYTES (A_BYTES + B_BYTES)
#define GEMM_SMEM_BYTES (3 * STAGE_BYTES)

template <int MODE>
__device__ __forceinline__ void gemm_f16_body(
    const __half* __restrict__ X, const __half* __restrict__ W,
    const float* __restrict__ bias, void* outp, float scale, char* sh)
{
    const int tid  = threadIdx.x;
    const int wid  = tid >> 5;
    const int lane = tid & 31;
    const int g    = lane >> 2;
    const int tig  = lane & 3;
    const int wm   = (wid & 3) << 5;
    const int wn   = (wid >> 2) << 6;
    const int lrow = (lane & 7) + ((lane >> 3) & 1) * 8;
    const int lcol = (lane >> 4) << 3;

    const int m0 = blockIdx.y << 7;
    const int n0 = blockIdx.x << 7;

    const unsigned sh_b = (unsigned)__cvta_generic_to_shared(sh);

    float c[2][8][4];
#pragma unroll
    for (int mt = 0; mt < 2; mt++)
#pragma unroll
        for (int nt = 0; nt < 8; nt++)
#pragma unroll
            for (int j = 0; j < 4; j++) c[mt][nt][j] = 0.f;

    auto issue = [&](int kc, int s) {
        const int k0 = kc << 6;
        unsigned as = sh_b + s * STAGE_BYTES;
        unsigned bs = as + A_BYTES;
#pragma unroll
        for (int p = 0; p < 4; p++) {
            int i = tid + (p << 8);
            int r = i >> 3, cc = (i & 7) << 3;
            cp16(as + (r * ASTR + cc) * 2, X + (size_t)(m0 + r) * DMc + k0 + cc);
        }
#pragma unroll
        for (int p = 0; p < 4; p++) {
            int i = tid + (p << 8);
            int r = i >> 4, cc = (i & 15) << 3;
            cp16(bs + (r * BSTR + cc) * 2, W + (size_t)(k0 + r) * DMc + n0 + cc);
        }
        cp_commit();
    };

    issue(0, 0);
    issue(1, 1);

    for (int kc = 0; kc < 8; kc++) {
        if (kc < 7) cp_wait<1>();
        else        cp_wait<0>();
        __syncthreads();
        if (kc + 2 < 8) issue(kc + 2, (kc + 2) % 3);

        const unsigned as_b = sh_b + (kc % 3) * STAGE_BYTES;
        const unsigned bs_b = as_b + A_BYTES;
#pragma unroll
        for (int ks = 0; ks < 4; ks++) {
            const int kb = ks << 4;
            unsigned a[2][4];
#pragma unroll
            for (int mt = 0; mt < 2; mt++) {
                unsigned addr = as_b +
                    (((wm + (mt << 4) + lrow) * ASTR) + kb + lcol) * 2;
                ldsm_x4(a[mt][0], a[mt][1], a[mt][2], a[mt][3], addr);
            }
#pragma unroll
            for (int np = 0; np < 4; np++) {
                unsigned addr = bs_b +
                    (((kb + lrow) * BSTR) + wn + (np << 4) + lcol) * 2;
                unsigned r0, r1, r2, r3;
                ldsm_x4_t(r0, r1, r2, r3, addr);
                mma_f16(c[0][2 * np],     a[0][0], a[0][1], a[0][2], a[0][3], r0, r1);
                mma_f16(c[0][2 * np + 1], a[0][0], a[0][1], a[0][2], a[0][3], r2, r3);
                mma_f16(c[1][2 * np],     a[1][0], a[1][1], a[1][2], a[1][3], r0, r1);
                mma_f16(c[1][2 * np + 1], a[1][0], a[1][1], a[1][2], a[1][3], r2, r3);
            }
        }
    }

    const int b_ = m0 >> 12;
#pragma unroll
    for (int mt = 0; mt < 2; mt++) {
        int m  = m0 + wm + (mt << 4) + g;
        int s_ = m & (Sc - 1);
#pragma unroll
        for (int nt = 0; nt < 8; nt++) {
            int n = n0 + wn + (nt << 3) + (tig << 1);
            float bx = bias[n], by = bias[n + 1];
            if (MODE == 0) {
                __half* out = (__half*)outp;
                int h = n >> 6;
                int d = n & 63;
                unsigned u0 = pack_f16x2((c[mt][nt][0] + bx) * scale,
                                         (c[mt][nt][1] + by) * scale);
                unsigned u1 = pack_f16x2((c[mt][nt][2] + bx) * scale,
                                         (c[mt][nt][3] + by) * scale);
                __half* base = out + ((size_t)(b_ * Hc + h) * Sc) * Dc + d;
                *(unsigned*)(base + (size_t)s_ * Dc)       = u0;
                *(unsigned*)(base + (size_t)(s_ + 8) * Dc) = u1;
            } else {
                float* out = (float*)outp;
                *(float2*)(out + (size_t)m * DMc + n) =
                    make_float2(c[mt][nt][0] + bx, c[mt][nt][1] + by);
                *(float2*)(out + (size_t)(m + 8) * DMc + n) =
                    make_float2(c[mt][nt][2] + bx, c[mt][nt][3] + by);
            }
        }
    }
}

__global__ __launch_bounds__(256, 2)
void gemm_qkv(const __half* __restrict__ qh, const __half* __restrict__ kh,
              const __half* __restrict__ vh,
              const __half* __restrict__ Wqh, const __half* __restrict__ Wkh,
              const __half* __restrict__ Wvh,
              const float* __restrict__ bq, const float* __restrict__ bk,
              const float* __restrict__ bv,
              __half* __restrict__ Qp, __half* __restrict__ Kp,
              __half* __restrict__ Vp)
{
    extern __shared__ __align__(16) char shdyn[];
    const int z = blockIdx.z;
    const __half* X    = z == 0 ? qh  : (z == 1 ? kh  : vh);
    const __half* W    = z == 0 ? Wqh : (z == 1 ? Wkh : Wvh);
    const float*  bias = z == 0 ? bq  : (z == 1 ? bk  : bv);
    __half*       out  = z == 0 ? Qp  : (z == 1 ? Kp  : Vp);
    gemm_f16_body<0>(X, W, bias, out, z == 0 ? SCL : 1.0f, shdyn);
}

__global__ __launch_bounds__(256, 2)
void gemm_out(const __half* __restrict__ X, const __half* __restrict__ W,
              const float* __restrict__ bias, float* __restrict__ out)
{
    extern __shared__ __align__(16) char shdyn[];
    gemm_f16_body<1>(X, W, bias, out, 1.0f, shdyn);
}

// ---------------------------------------------------------------------------
// Flash attention, fp16 mma + ldmatrix, cp.async double-buffered 128-key
// macro-tiles, single barrier per macro-tile.
// EXP/PV INTERLEAVE: per kb4 block, the 4 exp packs (MUFU) are computed
// immediately before that block's 18 HMMA -- MUFU of block i+1 overlaps
// the tensor drain of block i, and the pu[] array is eliminated.
// Q A-fragments hoisted. Mask fused as f16 -inf. EPOCH-MAX every 4th
// 64-key sub-tile. Numerically identical to the phase-separated version.
// smem halves: Qs[128][72] | Ks[2][128][72] | Vs[2][128][72] | mk16[2][128]
// ---------------------------------------------------------------------------
#define HSTR 72
#define QS_HALVES (128 * HSTR)
#define KV_STAGE_HALVES (128 * HSTR)
#define KS_HOFF QS_HALVES
#define VS_HOFF (QS_HALVES + 2 * KV_STAGE_HALVES)
#define MK_BYTE_OFF ((QS_HALVES + 4 * KV_STAGE_HALVES) * 2)
#define ATTN_SMEM_BYTES (MK_BYTE_OFF + 2 * 128 * 2)

#define ONES16X2 0x3C003C00u

__global__ __launch_bounds__(128, 2)
void attn_f16(const __half* __restrict__ Qp, const __half* __restrict__ Kp,
              const __half* __restrict__ Vp, const __half* __restrict__ mkh,
              __half* __restrict__ Ao)
{
    extern __shared__ __align__(16) char smc[];
    __half* Qs = (__half*)smc;

    const unsigned qs_b = (unsigned)__cvta_generic_to_shared(smc);
    const unsigned ks_b = qs_b + KS_HOFF * 2;
    const unsigned vs_b = qs_b + VS_HOFF * 2;
    const unsigned mk_b = qs_b + MK_BYTE_OFF;

    const int tid  = threadIdx.x;
    const int wid  = tid >> 5;
    const int lane = tid & 31;
    const int g    = lane >> 2;
    const int tig  = lane & 3;
    const int wm   = wid << 5;          // warp's 32-row base
    const int lrow = (lane & 7) + ((lane >> 3) & 1) * 8;
    const int lcol = (lane >> 4) << 3;

    const int bh = blockIdx.y;
    const int b  = bh >> 3;
    const int h  = bh & 7;
    const int q0 = blockIdx.x << 7;

    const __half* Qb = Qp + ((size_t)bh * Sc + q0) * Dc;
    const __half* Kb = Kp + (size_t)bh * Sc * Dc;
    const __half* Vb = Vp + (size_t)bh * Sc * Dc;
    const __half* mb = mkh + (size_t)b * Sc;

    // stage issuer: K/V macro-tile t (128 rows) + f16 mask slice into stage s
    auto issue = [&](int t, int s) {
        const __half* Kt = Kb + (size_t)(t << 7) * Dc;
        const __half* Vt = Vb + (size_t)(t << 7) * Dc;
        unsigned ks = ks_b + s * KV_STAGE_HALVES * 2;
        unsigned vs = vs_b + s * KV_STAGE_HALVES * 2;
#pragma unroll
        for (int p = 0; p < 8; p++) {
            int i = tid + (p << 7);
            int r = i >> 3, cc = (i & 7) << 3;
            cp16(ks + (r * HSTR + cc) * 2, Kt + r * Dc + cc);
            cp16(vs + (r * HSTR + cc) * 2, Vt + r * Dc + cc);
        }
        if (tid < 16) cp16(mk_b + s * 256 + tid * 16, mb + (t << 7) + tid * 8);
        cp_commit();
    };

    issue(0, 0);

    // Q tile copy (fp16, already scaled by gemm), then hoist A-fragments
#pragma unroll
    for (int p = 0; p < 8; p++) {
        int i = tid + (p << 7);
        int r = i >> 3, cc = (i & 7) << 3;
        *(uint4*)&Qs[r * HSTR + cc] = *(const uint4*)(Qb + r * Dc + cc);
    }
    __syncthreads();

    unsigned qa[2][4][4];       // [mt][kb4][frag] -- loop-invariant
#pragma unroll
    for (int mt = 0; mt < 2; mt++)
#pragma unroll
        for (int kb4 = 0; kb4 < 4; kb4++) {
            unsigned addr = qs_b +
                (((wm + (mt << 4) + lrow) * HSTR) + (kb4 << 4) + lcol) * 2;
            ldsm_x4(qa[mt][kb4][0], qa[mt][kb4][1],
                    qa[mt][kb4][2], qa[mt][kb4][3], addr);
        }

    float m_i[4] = {-INFINITY, -INFINITY, -INFINITY, -INFINITY};
    // o[mt][8] is the ones-column accumulator = running row sum l
    float o[2][9][4];
#pragma unroll
    for (int mt = 0; mt < 2; mt++)
#pragma unroll
        for (int nt = 0; nt < 9; nt++)
#pragma unroll
            for (int j = 0; j < 4; j++) o[mt][nt][j] = 0.f;

    const int NT = Sc / 128;            // 32 macro-tiles
    for (int t = 0; t < NT; t++) {
        const int s = t & 1;
        cp_wait<0>();
        __syncthreads();
        if (t < NT - 1) issue(t + 1, s ^ 1);

        const unsigned ks_st = ks_b + s * KV_STAGE_HALVES * 2;
        const unsigned vs_st = vs_b + s * KV_STAGE_HALVES * 2;

#pragma unroll
        for (int sub = 0; sub < 2; sub++) {
            const unsigned ks_s = ks_st + sub * 64 * HSTR * 2;
            const unsigned vs_s = vs_st + sub * 64 * HSTR * 2;
            const __half*  mksh = (const __half*)(smc + MK_BYTE_OFF)
                                  + s * 128 + sub * 64;

            // ---- S = Q @ K^T (Q fragments from registers) ----
            float c[2][8][4];
#pragma unroll
            for (int mt = 0; mt < 2; mt++)
#pragma unroll
                for (int nt = 0; nt < 8; nt++)
#pragma unroll
                    for (int j = 0; j < 4; j++) c[mt][nt][j] = 0.f;

#pragma unroll
            for (int kb4 = 0; kb4 < 4; kb4++) {
                const int kb = kb4 << 4;
#pragma unroll
                for (int np = 0; np < 4; np++) {
                    unsigned addr = ks_s +
                        ((((np << 4) + lrow) * HSTR) + kb + lcol) * 2;
                    unsigned b0e, b0o, b1e, b1o;
                    ldsm_x4(b0e, b0o, b1e, b1o, addr);
                    mma_f16(c[0][2 * np],     qa[0][kb4][0], qa[0][kb4][1],
                            qa[0][kb4][2], qa[0][kb4][3], b0e, b1e);
                    mma_f16(c[0][2 * np + 1], qa[0][kb4][0], qa[0][kb4][1],
                            qa[0][kb4][2], qa[0][kb4][3], b0o, b1o);
                    mma_f16(c[1][2 * np],     qa[1][kb4][0], qa[1][kb4][1],
                            qa[1][kb4][2], qa[1][kb4][3], b0e, b1e);
                    mma_f16(c[1][2 * np + 1], qa[1][kb4][0], qa[1][kb4][1],
                            qa[1][kb4][2], qa[1][kb4][3], b0o, b1o);
                }
            }

            // ---- epoch boundary (every 4th sub-tile): refresh max, rescale
            if (((t & 1) == 0) && sub == 0) {
#pragma unroll
                for (int mt = 0; mt < 2; mt++) {
                    float vmax0 = -INFINITY, vmax1 = -INFINITY;
#pragma unroll
                    for (int nt = 0; nt < 8; nt++) {
                        vmax0 = fmaxf(vmax0, fmaxf(c[mt][nt][0], c[mt][nt][1]));
                        vmax1 = fmaxf(vmax1, fmaxf(c[mt][nt][2], c[mt][nt][3]));
                    }
                    vmax0 = fmaxf(vmax0, __shfl_xor_sync(0xffffffffu, vmax0, 1));
                    vmax0 = fmaxf(vmax0, __shfl_xor_sync(0xffffffffu, vmax0, 2));
                    vmax1 = fmaxf(vmax1, __shfl_xor_sync(0xffffffffu, vmax1, 1));
                    vmax1 = fmaxf(vmax1, __shfl_xor_sync(0xffffffffu, vmax1, 2));

                    float mn0 = fmaxf(m_i[mt * 2 + 0], vmax0);
                    float mn1 = fmaxf(m_i[mt * 2 + 1], vmax1);
                    float al0 = ex2(m_i[mt * 2 + 0] - mn0);
                    float al1 = ex2(m_i[mt * 2 + 1] - mn1);
                    m_i[mt * 2 + 0] = mn0;
                    m_i[mt * 2 + 1] = mn1;
#pragma unroll
                    for (int nt = 0; nt < 9; nt++) {
                        o[mt][nt][0] *= al0; o[mt][nt][1] *= al0;
                        o[mt][nt][2] *= al1; o[mt][nt][3] *= al1;
                    }
                }
            }

            // ---- mask regs for this sub-tile ----
            unsigned mku[8];
#pragma unroll
            for (int nt = 0; nt < 8; nt++)
                mku[nt] = *(const unsigned*)&mksh[(nt << 3) + (tig << 1)];

            // ---- interleaved: per kb4, exp packs then PV mma + ones ----
#pragma unroll
            for (int kb4 = 0; kb4 < 4; kb4++) {
                const int nt0 = 2 * kb4;
                const int nt1 = 2 * kb4 + 1;
                unsigned pa[2][4];
#pragma unroll
                for (int mt = 0; mt < 2; mt++) {
                    float mn0 = m_i[mt * 2 + 0];
                    float mn1 = m_i[mt * 2 + 1];
                    pa[mt][0] = ex2_f16x2(hadd2(
                        pack_f16x2(c[mt][nt0][0] - mn0, c[mt][nt0][1] - mn0),
                        mku[nt0]));
                    pa[mt][1] = ex2_f16x2(hadd2(
                        pack_f16x2(c[mt][nt0][2] - mn1, c[mt][nt0][3] - mn1),
                        mku[nt0]));
                    pa[mt][2] = ex2_f16x2(hadd2(
                        pack_f16x2(c[mt][nt1][0] - mn0, c[mt][nt1][1] - mn0),
                        mku[nt1]));
                    pa[mt][3] = ex2_f16x2(hadd2(
                        pack_f16x2(c[mt][nt1][2] - mn1, c[mt][nt1][3] - mn1),
                        mku[nt1]));
                }
#pragma unroll
                for (int dp = 0; dp < 4; dp++) {
                    unsigned addr = vs_s +
                        ((((kb4 << 4) + lrow) * HSTR) + (dp << 4) + lcol) * 2;
                    unsigned r0, r1, r2, r3;
                    ldsm_x4_t(r0, r1, r2, r3, addr);
                    mma_f16(o[0][2 * dp],     pa[0][0], pa[0][1], pa[0][2], pa[0][3], r0, r1);
                    mma_f16(o[0][2 * dp + 1], pa[0][0], pa[0][1], pa[0][2], pa[0][3], r2, r3);
                    mma_f16(o[1][2 * dp],     pa[1][0], pa[1][1], pa[1][2], pa[1][3], r0, r1);
                    mma_f16(o[1][2 * dp + 1], pa[1][0], pa[1][1], pa[1][2], pa[1][3], r2, r3);
                }
                mma_f16(o[0][8], pa[0][0], pa[0][1], pa[0][2], pa[0][3],
                        ONES16X2, ONES16X2);
                mma_f16(o[1][8], pa[1][0], pa[1][1], pa[1][2], pa[1][3],
                        ONES16X2, ONES16X2);
            }
        }
    }

    // ---- epilogue: normalize by l (ones-column), write fp16 Ao ----
    __half* AoB = Ao + ((size_t)b * Sc) * DMc + h * Dc;
#pragma unroll
    for (int mt = 0; mt < 2; mt++) {
        float inv0 = 1.f / o[mt][8][0];
        float inv1 = 1.f / o[mt][8][2];
        int r0 = q0 + wm + (mt << 4) + g;
#pragma unroll
        for (int nt = 0; nt < 8; nt++) {
            int d = (nt << 3) + (tig << 1);
            *(unsigned*)(AoB + (size_t)r0 * DMc + d) =
                pack_f16x2(o[mt][nt][0] * inv0, o[mt][nt][1] * inv0);
            *(unsigned*)(AoB + (size_t)(r0 + 8) * DMc + d) =
                pack_f16x2(o[mt][nt][2] * inv1, o[mt][nt][3] * inv1);
        }
    }
}

// ---------------------------------------------------------------------------
extern "C" void kernel_launch(void* const* d_in, const int* in_sizes, int n_in,
                              void* d_out, int out_size)
{
    const float* q    = (const float*)d_in[0];
    const float* k    = (const float*)d_in[1];
    const float* v    = (const float*)d_in[2];
    const float* mask = (const float*)d_in[3];
    const float* Wq   = (const float*)d_in[4];
    const float* bq   = (const float*)d_in[5];
    const float* Wk   = (const float*)d_in[6];
    const float* bk   = (const float*)d_in[7];
    const float* Wv   = (const float*)d_in[8];
    const float* bv   = (const float*)d_in[9];
    const float* Wo   = (const float*)d_in[10];
    const float* bo   = (const float*)d_in[11];
    float* out = (float*)d_out;

    __half *qh, *kh, *vh, *Wqh, *Wkh, *Wvh, *Woh, *Qp, *Kp, *Vp, *Ao, *mkh;
    cudaGetSymbolAddress((void**)&qh,  g_qh);
    cudaGetSymbolAddress((void**)&kh,  g_kh);
    cudaGetSymbolAddress((void**)&vh,  g_vh);
    cudaGetSymbolAddress((void**)&Wqh, g_Wqh);
    cudaGetSymbolAddress((void**)&Wkh, g_Wkh);
    cudaGetSymbolAddress((void**)&Wvh, g_Wvh);
    cudaGetSymbolAddress((void**)&Woh, g_Woh);
    cudaGetSymbolAddress((void**)&Qp,  g_Qp);
    cudaGetSymbolAddress((void**)&Kp,  g_Kp);
    cudaGetSymbolAddress((void**)&Vp,  g_Vp);
    cudaGetSymbolAddress((void**)&Ao,  g_Ao);
    cudaGetSymbolAddress((void**)&mkh, g_mkh);

    cudaFuncSetAttribute(attn_f16, cudaFuncAttributeMaxDynamicSharedMemorySize,
                         ATTN_SMEM_BYTES);
    cudaFuncSetAttribute(gemm_qkv, cudaFuncAttributeMaxDynamicSharedMemorySize,
                         GEMM_SMEM_BYTES);
    cudaFuncSetAttribute(gemm_out, cudaFuncAttributeMaxDynamicSharedMemorySize,
                         GEMM_SMEM_BYTES);

    cvt_all<<<CVT_BLKS, 256>>>(q, k, v, Wq, Wk, Wv, Wo, mask,
                               qh, kh, vh, Wqh, Wkh, Wvh, Woh, mkh);

    dim3 gqkv(DMc / 128, Mc / 128, 3);      // (4, 64, 3)
    gemm_qkv<<<gqkv, 256, GEMM_SMEM_BYTES>>>(qh, kh, vh, Wqh, Wkh, Wvh,
                                             bq, bk, bv, Qp, Kp, Vp);

    dim3 ga(Sc / 128, Bc * Hc);             // (32, 16)
    attn_f16<<<ga, 128, ATTN_SMEM_BYTES>>>(Qp, Kp, Vp, mkh, Ao);

    dim3 gg(DMc / 128, Mc / 128);           // (4, 64)
    gemm_out<<<gg, 256, GEMM_SMEM_BYTES>>>(Ao, Woh, bo, out);
}

// round 17
// speedup vs baseline: 1.1991x; 1.0041x over previous
#include <cuda_runtime.h>
#include <cuda_fp16.h>
#include <math.h>

#define Bc  2
#define Sc  4096
#define DMc 512
#define Hc  8
#define Dc  64
#define Mc  (Bc * Sc)   // 8192

#define SCL (0.125f * 1.44269504f)

// fp16 mirrors of inputs/weights + fp16 scratch
__device__ __half g_qh[Mc * DMc];
__device__ __half g_kh[Mc * DMc];
__device__ __half g_vh[Mc * DMc];
__device__ __half g_Wqh[DMc * DMc];
__device__ __half g_Wkh[DMc * DMc];
__device__ __half g_Wvh[DMc * DMc];
__device__ __half g_Woh[DMc * DMc];
__device__ __half g_Qp[Bc * Hc * Sc * Dc];
__device__ __half g_Kp[Bc * Hc * Sc * Dc];
__device__ __half g_Vp[Bc * Hc * Sc * Dc];
__device__ __half g_Ao[Mc * DMc];
__device__ __half g_mkh[Bc * Sc];          // mask as f16: 0 or -inf

// ---------------------------------------------------------------------------
// helpers
// ---------------------------------------------------------------------------
__device__ __forceinline__ unsigned pack_f16x2(float lo, float hi) {
    unsigned r;
    asm("cvt.rn.f16x2.f32 %0, %1, %2;" : "=r"(r) : "f"(hi), "f"(lo));
    return r;
}

__device__ __forceinline__ float ex2(float x) {
    float r;
    asm("ex2.approx.f32 %0, %1;" : "=f"(r) : "f"(x));
    return r;
}

__device__ __forceinline__ unsigned ex2_f16x2(unsigned x) {
    unsigned r;
    asm("ex2.approx.f16x2 %0, %1;" : "=r"(r) : "r"(x));
    return r;
}

__device__ __forceinline__ unsigned hadd2(unsigned a, unsigned b) {
    unsigned r;
    asm("add.rn.f16x2 %0, %1, %2;" : "=r"(r) : "r"(a), "r"(b));
    return r;
}

__device__ __forceinline__ void cp16(unsigned dst, const void* src) {
    asm volatile("cp.async.cg.shared.global [%0], [%1], 16;"
                 :: "r"(dst), "l"(__cvta_generic_to_global(src)));
}
__device__ __forceinline__ void cp_commit() {
    asm volatile("cp.async.commit_group;");
}
template <int N>
__device__ __forceinline__ void cp_wait() {
    asm volatile("cp.async.wait_group %0;" :: "n"(N));
}

__device__ __forceinline__ void ldsm_x4(unsigned& r0, unsigned& r1,
                                        unsigned& r2, unsigned& r3,
                                        unsigned addr) {
    asm volatile("ldmatrix.sync.aligned.m8n8.x4.shared.b16 {%0,%1,%2,%3}, [%4];"
                 : "=r"(r0), "=r"(r1), "=r"(r2), "=r"(r3) : "r"(addr));
}
__device__ __forceinline__ void ldsm_x4_t(unsigned& r0, unsigned& r1,
                                          unsigned& r2, unsigned& r3,
                                          unsigned addr) {
    asm volatile("ldmatrix.sync.aligned.m8n8.x4.trans.shared.b16 {%0,%1,%2,%3}, [%4];"
                 : "=r"(r0), "=r"(r1), "=r"(r2), "=r"(r3) : "r"(addr));
}
__device__ __forceinline__ void mma_f16(float c[4], unsigned a0, unsigned a1,
                                        unsigned a2, unsigned a3,
                                        unsigned b0, unsigned b1) {
    asm volatile(
        "mma.sync.aligned.m16n8k16.row.col.f32.f16.f16.f32 "
        "{%0,%1,%2,%3}, {%4,%5,%6,%7}, {%8,%9}, {%0,%1,%2,%3};\n"
        : "+f"(c[0]), "+f"(c[1]), "+f"(c[2]), "+f"(c[3])
        : "r"(a0), "r"(a1), "r"(a2), "r"(a3), "r"(b0), "r"(b1));
}

// ---------------------------------------------------------------------------
// merged fp32 -> fp16 conversion pre-pass (inputs + weights + mask, 1 launch)
// ---------------------------------------------------------------------------
#define IN_BLKS  (Mc * DMc / 1024)     // 4096
#define W_BLKS   (DMc * DMc / 1024)    // 256
#define CVT_BLKS (3 * IN_BLKS + 4 * W_BLKS + Bc * Sc / 1024)  // 13320

__global__ __launch_bounds__(256)
void cvt_all(const float* __restrict__ q, const float* __restrict__ k,
             const float* __restrict__ v,
             const float* __restrict__ Wq, const float* __restrict__ Wk,
             const float* __restrict__ Wv, const float* __restrict__ Wo,
             const float* __restrict__ mask,
             __half* __restrict__ qh, __half* __restrict__ kh,
             __half* __restrict__ vh,
             __half* __restrict__ Wqh, __half* __restrict__ Wkh,
             __half* __restrict__ Wvh, __half* __restrict__ Woh,
             __half* __restrict__ mkh)
{
    const int bid = blockIdx.x;
    const int tid = threadIdx.x;

    if (bid < 3 * IN_BLKS) {
        const int z = bid / IN_BLKS;
        const int i = (bid % IN_BLKS) * 256 + tid;
        const float* s = z == 0 ? q  : (z == 1 ? k  : v);
        __half*      d = z == 0 ? qh : (z == 1 ? kh : vh);
        float4 f = ((const float4*)s)[i];
        ((uint2*)d)[i] = make_uint2(pack_f16x2(f.x, f.y), pack_f16x2(f.z, f.w));
    } else if (bid < 3 * IN_BLKS + 4 * W_BLKS) {
        const int r = bid - 3 * IN_BLKS;
        const int z = r / W_BLKS;
        const int i = (r % W_BLKS) * 256 + tid;
        const float* s = z == 0 ? Wq  : (z == 1 ? Wk  : (z == 2 ? Wv  : Wo));
        __half*      d = z == 0 ? Wqh : (z == 1 ? Wkh : (z == 2 ? Wvh : Woh));
        float4 f = ((const float4*)s)[i];
        ((uint2*)d)[i] = make_uint2(pack_f16x2(f.x, f.y), pack_f16x2(f.z, f.w));
    } else {
        const int i = (bid - 3 * IN_BLKS - 4 * W_BLKS) * 256 + tid;  // float4
        float4 f = ((const float4*)mask)[i];
        unsigned lo = (f.x > 0.5f ? 0xFC00u : 0u) |
                      ((f.y > 0.5f ? 0xFC00u : 0u) << 16);
        unsigned hi = (f.z > 0.5f ? 0xFC00u : 0u) |
                      ((f.w > 0.5f ? 0xFC00u : 0u) << 16);
        ((uint2*)mkh)[i] = make_uint2(lo, hi);
    }
}

// ---------------------------------------------------------------------------
// pure-fp16 GEMM, 3-stage cp.async ring, BK=64. C = X @ W (+bias) [*scale].
// Block 128x128, 8 warps (4m x 2n), warp tile 32x64, 8 K-chunks of 64.
// MODE 0: fp16 head-split out; MODE 1: fp32 row-major out.
// ---------------------------------------------------------------------------
#define ASTR 72
#define BSTR 136
#define A_BYTES (128 * ASTR * 2)
#define B_BYTES (64 * BSTR * 2)
#define STAGE_BYTES (A_BYTES + B_BYTES)
#define GEMM_SMEM_BYTES (3 * STAGE_BYTES)

template <int MODE>
__device__ __forceinline__ void gemm_f16_body(
    const __half* __restrict__ X, const __half* __restrict__ W,
    const float* __restrict__ bias, void* outp, float scale, char* sh)
{
    const int tid  = threadIdx.x;
    const int wid  = tid >> 5;
    const int lane = tid & 31;
    const int g    = lane >> 2;
    const int tig  = lane & 3;
    const int wm   = (wid & 3) << 5;
    const int wn   = (wid >> 2) << 6;
    const int lrow = (lane & 7) + ((lane >> 3) & 1) * 8;
    const int lcol = (lane >> 4) << 3;

    const int m0 = blockIdx.y << 7;
    const int n0 = blockIdx.x << 7;

    const unsigned sh_b = (unsigned)__cvta_generic_to_shared(sh);

    float c[2][8][4];
#pragma unroll
    for (int mt = 0; mt < 2; mt++)
#pragma unroll
        for (int nt = 0; nt < 8; nt++)
#pragma unroll
            for (int j = 0; j < 4; j++) c[mt][nt][j] = 0.f;

    auto issue = [&](int kc, int s) {
        const int k0 = kc << 6;
        unsigned as = sh_b + s * STAGE_BYTES;
        unsigned bs = as + A_BYTES;
#pragma unroll
        for (int p = 0; p < 4; p++) {
            int i = tid + (p << 8);
            int r = i >> 3, cc = (i & 7) << 3;
            cp16(as + (r * ASTR + cc) * 2, X + (size_t)(m0 + r) * DMc + k0 + cc);
        }
#pragma unroll
        for (int p = 0; p < 4; p++) {
            int i = tid + (p << 8);
            int r = i >> 4, cc = (i & 15) << 3;
            cp16(bs + (r * BSTR + cc) * 2, W + (size_t)(k0 + r) * DMc + n0 + cc);
        }
        cp_commit();
    };

    issue(0, 0);
    issue(1, 1);

    for (int kc = 0; kc < 8; kc++) {
        if (kc < 7) cp_wait<1>();
        else        cp_wait<0>();
        __syncthreads();
        if (kc + 2 < 8) issue(kc + 2, (kc + 2) % 3);

        const unsigned as_b = sh_b + (kc % 3) * STAGE_BYTES;
        const unsigned bs_b = as_b + A_BYTES;
#pragma unroll
        for (int ks = 0; ks < 4; ks++) {
            const int kb = ks << 4;
            unsigned a[2][4];
#pragma unroll
            for (int mt = 0; mt < 2; mt++) {
                unsigned addr = as_b +
                    (((wm + (mt << 4) + lrow) * ASTR) + kb + lcol) * 2;
                ldsm_x4(a[mt][0], a[mt][1], a[mt][2], a[mt][3], addr);
            }
#pragma unroll
            for (int np = 0; np < 4; np++) {
                unsigned addr = bs_b +
                    (((kb + lrow) * BSTR) + wn + (np << 4) + lcol) * 2;
                unsigned r0, r1, r2, r3;
                ldsm_x4_t(r0, r1, r2, r3, addr);
                mma_f16(c[0][2 * np],     a[0][0], a[0][1], a[0][2], a[0][3], r0, r1);
                mma_f16(c[0][2 * np + 1], a[0][0], a[0][1], a[0][2], a[0][3], r2, r3);
                mma_f16(c[1][2 * np],     a[1][0], a[1][1], a[1][2], a[1][3], r0, r1);
                mma_f16(c[1][2 * np + 1], a[1][0], a[1][1], a[1][2], a[1][3], r2, r3);
            }
        }
    }

    const int b_ = m0 >> 12;
#pragma unroll
    for (int mt = 0; mt < 2; mt++) {
        int m  = m0 + wm + (mt << 4) + g;
        int s_ = m & (Sc - 1);
#pragma unroll
        for (int nt = 0; nt < 8; nt++) {
            int n = n0 + wn + (nt << 3) + (tig << 1);
            float bx = __ldg(bias + n), by = __ldg(bias + n + 1);
            if (MODE == 0) {
                __half* out = (__half*)outp;
                int h = n >> 6;
                int d = n & 63;
                unsigned u0 = pack_f16x2((c[mt][nt][0] + bx) * scale,
                                         (c[mt][nt][1] + by) * scale);
                unsigned u1 = pack_f16x2((c[mt][nt][2] + bx) * scale,
                                         (c[mt][nt][3] + by) * scale);
                __half* base = out + ((size_t)(b_ * Hc + h) * Sc) * Dc + d;
                *(unsigned*)(base + (size_t)s_ * Dc)       = u0;
                *(unsigned*)(base + (size_t)(s_ + 8) * Dc) = u1;
            } else {
                float* out = (float*)outp;
                *(float2*)(out + (size_t)m * DMc + n) =
                    make_float2(c[mt][nt][0] + bx, c[mt][nt][1] + by);
                *(float2*)(out + (size_t)(m + 8) * DMc + n) =
                    make_float2(c[mt][nt][2] + bx, c[mt][nt][3] + by);
            }
        }
    }
}

__global__ __launch_bounds__(256, 2)
void gemm_qkv(const __half* __restrict__ qh, const __half* __restrict__ kh,
              const __half* __restrict__ vh,
              const __half* __restrict__ Wqh, const __half* __restrict__ Wkh,
              const __half* __restrict__ Wvh,
              const float* __restrict__ bq, const float* __restrict__ bk,
              const float* __restrict__ bv,
              __half* __restrict__ Qp, __half* __restrict__ Kp,
              __half* __restrict__ Vp)
{
    extern __shared__ __align__(16) char shdyn[];
    const int z = blockIdx.z;
    const __half* X    = z == 0 ? qh  : (z == 1 ? kh  : vh);
    const __half* W    = z == 0 ? Wqh : (z == 1 ? Wkh : Wvh);
    const float*  bias = z == 0 ? bq  : (z == 1 ? bk  : bv);
    __half*       out  = z == 0 ? Qp  : (z == 1 ? Kp  : Vp);
    gemm_f16_body<0>(X, W, bias, out, z == 0 ? SCL : 1.0f, shdyn);
}

__global__ __launch_bounds__(256, 2)
void gemm_out(const __half* __restrict__ X, const __half* __restrict__ W,
              const float* __restrict__ bias, float* __restrict__ out)
{
    extern __shared__ __align__(16) char shdyn[];
    gemm_f16_body<1>(X, W, bias, out, 1.0f, shdyn);
}

// ---------------------------------------------------------------------------
// Flash attention, fp16 mma + ldmatrix, cp.async double-buffered 128-key
// macro-tiles, single barrier per macro-tile. Q-frags hoisted, f16 -inf mask
// fused into the exp chain (mask LDS hoisted ahead of the QK mma loop so its
// latency overlaps tensor work), epoch-max every 4th 64-key sub-tile,
// l as ones-column mma, exp/PV interleaved per kb4.
// smem halves: Qs[128][72] | Ks[2][128][72] | Vs[2][128][72] | mk16[2][128]
// ---------------------------------------------------------------------------
#define HSTR 72
#define QS_HALVES (128 * HSTR)
#define KV_STAGE_HALVES (128 * HSTR)
#define KS_HOFF QS_HALVES
#define VS_HOFF (QS_HALVES + 2 * KV_STAGE_HALVES)
#define MK_BYTE_OFF ((QS_HALVES + 4 * KV_STAGE_HALVES) * 2)
#define ATTN_SMEM_BYTES (MK_BYTE_OFF + 2 * 128 * 2)

#define ONES16X2 0x3C003C00u

__global__ __launch_bounds__(128, 2)
void attn_f16(const __half* __restrict__ Qp, const __half* __restrict__ Kp,
              const __half* __restrict__ Vp, const __half* __restrict__ mkh,
              __half* __restrict__ Ao)
{
    extern __shared__ __align__(16) char smc[];
    __half* Qs = (__half*)smc;

    const unsigned qs_b = (unsigned)__cvta_generic_to_shared(smc);
    const unsigned ks_b = qs_b + KS_HOFF * 2;
    const unsigned vs_b = qs_b + VS_HOFF * 2;
    const unsigned mk_b = qs_b + MK_BYTE_OFF;

    const int tid  = threadIdx.x;
    const int wid  = tid >> 5;
    const int lane = tid & 31;
    const int g    = lane >> 2;
    const int tig  = lane & 3;
    const int wm   = wid << 5;          // warp's 32-row base
    const int lrow = (lane & 7) + ((lane >> 3) & 1) * 8;
    const int lcol = (lane >> 4) << 3;

    const int bh = blockIdx.y;
    const int b  = bh >> 3;
    const int h  = bh & 7;
    const int q0 = blockIdx.x << 7;

    const __half* Qb = Qp + ((size_t)bh * Sc + q0) * Dc;
    const __half* Kb = Kp + (size_t)bh * Sc * Dc;
    const __half* Vb = Vp + (size_t)bh * Sc * Dc;
    const __half* mb = mkh + (size_t)b * Sc;

    // stage issuer: K/V macro-tile t (128 rows) + f16 mask slice into stage s
    auto issue = [&](int t, int s) {
        const __half* Kt = Kb + (size_t)(t << 7) * Dc;
        const __half* Vt = Vb + (size_t)(t << 7) * Dc;
        unsigned ks = ks_b + s * KV_STAGE_HALVES * 2;
        unsigned vs = vs_b + s * KV_STAGE_HALVES * 2;
#pragma unroll
        for (int p = 0; p < 8; p++) {
            int i = tid + (p << 7);
            int r = i >> 3, cc = (i & 7) << 3;
            cp16(ks + (r * HSTR + cc) * 2, Kt + r * Dc + cc);
            cp16(vs + (r * HSTR + cc) * 2, Vt + r * Dc + cc);
        }
        if (tid < 16) cp16(mk_b + s * 256 + tid * 16, mb + (t << 7) + tid * 8);
        cp_commit();
    };

    issue(0, 0);

    // Q tile copy (fp16, already scaled by gemm), then hoist A-fragments
#pragma unroll
    for (int p = 0; p < 8; p++) {
        int i = tid + (p << 7);
        int r = i >> 3, cc = (i & 7) << 3;
        *(uint4*)&Qs[r * HSTR + cc] = *(const uint4*)(Qb + r * Dc + cc);
    }
    __syncthreads();

    unsigned qa[2][4][4];       // [mt][kb4][frag] -- loop-invariant
#pragma unroll
    for (int mt = 0; mt < 2; mt++)
#pragma unroll
        for (int kb4 = 0; kb4 < 4; kb4++) {
            unsigned addr = qs_b +
                (((wm + (mt << 4) + lrow) * HSTR) + (kb4 << 4) + lcol) * 2;
            ldsm_x4(qa[mt][kb4][0], qa[mt][kb4][1],
                    qa[mt][kb4][2], qa[mt][kb4][3], addr);
        }

    float m_i[4] = {-INFINITY, -INFINITY, -INFINITY, -INFINITY};
    // o[mt][8] is the ones-column accumulator = running row sum l
    float o[2][9][4];
#pragma unroll
    for (int mt = 0; mt < 2; mt++)
#pragma unroll
        for (int nt = 0; nt < 9; nt++)
#pragma unroll
            for (int j = 0; j < 4; j++) o[mt][nt][j] = 0.f;

    const int NT = Sc / 128;            // 32 macro-tiles
    for (int t = 0; t < NT; t++) {
        const int s = t & 1;
        cp_wait<0>();
        __syncthreads();
        if (t < NT - 1) issue(t + 1, s ^ 1);

        const unsigned ks_st = ks_b + s * KV_STAGE_HALVES * 2;
        const unsigned vs_st = vs_b + s * KV_STAGE_HALVES * 2;

#pragma unroll
        for (int sub = 0; sub < 2; sub++) {
            const unsigned ks_s = ks_st + sub * 64 * HSTR * 2;
            const unsigned vs_s = vs_st + sub * 64 * HSTR * 2;
            const __half*  mksh = (const __half*)(smc + MK_BYTE_OFF)
                                  + s * 128 + sub * 64;

            // ---- mask regs loaded EARLY: LDS latency hides under QK mma ----
            unsigned mku[8];
#pragma unroll
            for (int nt = 0; nt < 8; nt++)
                mku[nt] = *(const unsigned*)&mksh[(nt << 3) + (tig << 1)];

            // ---- S = Q @ K^T (Q fragments from registers) ----
            float c[2][8][4];
#pragma unroll
            for (int mt = 0; mt < 2; mt++)
#pragma unroll
                for (int nt = 0; nt < 8; nt++)
#pragma unroll
                    for (int j = 0; j < 4; j++) c[mt][nt][j] = 0.f;

#pragma unroll
            for (int kb4 = 0; kb4 < 4; kb4++) {
                const int kb = kb4 << 4;
#pragma unroll
                for (int np = 0; np < 4; np++) {
                    unsigned addr = ks_s +
                        ((((np << 4) + lrow) * HSTR) + kb + lcol) * 2;
                    unsigned b0e, b0o, b1e, b1o;
                    ldsm_x4(b0e, b0o, b1e, b1o, addr);
                    mma_f16(c[0][2 * np],     qa[0][kb4][0], qa[0][kb4][1],
                            qa[0][kb4][2], qa[0][kb4][3], b0e, b1e);
                    mma_f16(c[0][2 * np + 1], qa[0][kb4][0], qa[0][kb4][1],
                            qa[0][kb4][2], qa[0][kb4][3], b0o, b1o);
                    mma_f16(c[1][2 * np],     qa[1][kb4][0], qa[1][kb4][1],
                            qa[1][kb4][2], qa[1][kb4][3], b0e, b1e);
                    mma_f16(c[1][2 * np + 1], qa[1][kb4][0], qa[1][kb4][1],
                            qa[1][kb4][2], qa[1][kb4][3], b0o, b1o);
                }
            }

            // ---- epoch boundary (every 4th sub-tile): refresh max, rescale
            if (((t & 1) == 0) && sub == 0) {
#pragma unroll
                for (int mt = 0; mt < 2; mt++) {
                    float vmax0 = -INFINITY, vmax1 = -INFINITY;
#pragma unroll
                    for (int nt = 0; nt < 8; nt++) {
                        vmax0 = fmaxf(vmax0, fmaxf(c[mt][nt][0], c[mt][nt][1]));
                        vmax1 = fmaxf(vmax1, fmaxf(c[mt][nt][2], c[mt][nt][3]));
                    }
                    vmax0 = fmaxf(vmax0, __shfl_xor_sync(0xffffffffu, vmax0, 1));
                    vmax0 = fmaxf(vmax0, __shfl_xor_sync(0xffffffffu, vmax0, 2));
                    vmax1 = fmaxf(vmax1, __shfl_xor_sync(0xffffffffu, vmax1, 1));
                    vmax1 = fmaxf(vmax1, __shfl_xor_sync(0xffffffffu, vmax1, 2));

                    float mn0 = fmaxf(m_i[mt * 2 + 0], vmax0);
                    float mn1 = fmaxf(m_i[mt * 2 + 1], vmax1);
                    float al0 = ex2(m_i[mt * 2 + 0] - mn0);
                    float al1 = ex2(m_i[mt * 2 + 1] - mn1);
                    m_i[mt * 2 + 0] = mn0;
                    m_i[mt * 2 + 1] = mn1;
#pragma unroll
                    for (int nt = 0; nt < 9; nt++) {
                        o[mt][nt][0] *= al0; o[mt][nt][1] *= al0;
                        o[mt][nt][2] *= al1; o[mt][nt][3] *= al1;
                    }
                }
            }

            // ---- interleaved: per kb4, exp packs then PV mma + ones ----
#pragma unroll
            for (int kb4 = 0; kb4 < 4; kb4++) {
                const int nt0 = 2 * kb4;
                const int nt1 = 2 * kb4 + 1;
                unsigned pa[2][4];
#pragma unroll
                for (int mt = 0; mt < 2; mt++) {
                    float mn0 = m_i[mt * 2 + 0];
                    float mn1 = m_i[mt * 2 + 1];
                    pa[mt][0] = ex2_f16x2(hadd2(
                        pack_f16x2(c[mt][nt0][0] - mn0, c[mt][nt0][1] - mn0),
                        mku[nt0]));
                    pa[mt][1] = ex2_f16x2(hadd2(
                        pack_f16x2(c[mt][nt0][2] - mn1, c[mt][nt0][3] - mn1),
                        mku[nt0]));
                    pa[mt][2] = ex2_f16x2(hadd2(
                        pack_f16x2(c[mt][nt1][0] - mn0, c[mt][nt1][1] - mn0),
                        mku[nt1]));
                    pa[mt][3] = ex2_f16x2(hadd2(
                        pack_f16x2(c[mt][nt1][2] - mn1, c[mt][nt1][3] - mn1),
                        mku[nt1]));
                }
#pragma unroll
                for (int dp = 0; dp < 4; dp++) {
                    unsigned addr = vs_s +
                        ((((kb4 << 4) + lrow) * HSTR) + (dp << 4) + lcol) * 2;
                    unsigned r0, r1, r2, r3;
                    ldsm_x4_t(r0, r1, r2, r3, addr);
                    mma_f16(o[0][2 * dp],     pa[0][0], pa[0][1], pa[0][2], pa[0][3], r0, r1);
                    mma_f16(o[0][2 * dp + 1], pa[0][0], pa[0][1], pa[0][2], pa[0][3], r2, r3);
                    mma_f16(o[1][2 * dp],     pa[1][0], pa[1][1], pa[1][2], pa[1][3], r0, r1);
                    mma_f16(o[1][2 * dp + 1], pa[1][0], pa[1][1], pa[1][2], pa[1][3], r2, r3);
                }
                mma_f16(o[0][8], pa[0][0], pa[0][1], pa[0][2], pa[0][3],
                        ONES16X2, ONES16X2);
                mma_f16(o[1][8], pa[1][0], pa[1][1], pa[1][2], pa[1][3],
                        ONES16X2, ONES16X2);
            }
        }
    }

    // ---- epilogue: normalize by l (ones-column), write fp16 Ao ----
    __half* AoB = Ao + ((size_t)b * Sc) * DMc + h * Dc;
#pragma unroll
    for (int mt = 0; mt < 2; mt++) {
        float inv0 = 1.f / o[mt][8][0];
        float inv1 = 1.f / o[mt][8][2];
        int r0 = q0 + wm + (mt << 4) + g;
#pragma unroll
        for (int nt = 0; nt < 8; nt++) {
            int d = (nt << 3) + (tig << 1);
            *(unsigned*)(AoB + (size_t)r0 * DMc + d) =
                pack_f16x2(o[mt][nt][0] * inv0, o[mt][nt][1] * inv0);
            *(unsigned*)(AoB + (size_t)(r0 + 8) * DMc + d) =
                pack_f16x2(o[mt][nt][2] * inv1, o[mt][nt][3] * inv1);
        }
    }
}

// ---------------------------------------------------------------------------
extern "C" void kernel_launch(void* const* d_in, const int* in_sizes, int n_in,
                              void* d_out, int out_size)
{
    const float* q    = (const float*)d_in[0];
    const float* k    = (const float*)d_in[1];
    const float* v    = (const float*)d_in[2];
    const float* mask = (const float*)d_in[3];
    const float* Wq   = (const float*)d_in[4];
    const float* bq   = (const float*)d_in[5];
    const float* Wk   = (const float*)d_in[6];
    const float* bk   = (const float*)d_in[7];
    const float* Wv   = (const float*)d_in[8];
    const float* bv   = (const float*)d_in[9];
    const float* Wo   = (const float*)d_in[10];
    const float* bo   = (const float*)d_in[11];
    float* out = (float*)d_out;

    __half *qh, *kh, *vh, *Wqh, *Wkh, *Wvh, *Woh, *Qp, *Kp, *Vp, *Ao, *mkh;
    cudaGetSymbolAddress((void**)&qh,  g_qh);
    cudaGetSymbolAddress((void**)&kh,  g_kh);
    cudaGetSymbolAddress((void**)&vh,  g_vh);
    cudaGetSymbolAddress((void**)&Wqh, g_Wqh);
    cudaGetSymbolAddress((void**)&Wkh, g_Wkh);
    cudaGetSymbolAddress((void**)&Wvh, g_Wvh);
    cudaGetSymbolAddress((void**)&Woh, g_Woh);
    cudaGetSymbolAddress((void**)&Qp,  g_Qp);
    cudaGetSymbolAddress((void**)&Kp,  g_Kp);
    cudaGetSymbolAddress((void**)&Vp,  g_Vp);
    cudaGetSymbolAddress((void**)&Ao,  g_Ao);
    cudaGetSymbolAddress((void**)&mkh, g_mkh);

    cudaFuncSetAttribute(attn_f16, cudaFuncAttributeMaxDynamicSharedMemorySize,
                         ATTN_SMEM_BYTES);
    cudaFuncSetAttribute(gemm_qkv, cudaFuncAttributeMaxDynamicSharedMemorySize,
                         GEMM_SMEM_BYTES);
    cudaFuncSetAttribute(gemm_out, cudaFuncAttributeMaxDynamicSharedMemorySize,
                         GEMM_SMEM_BYTES);

    cvt_all<<<CVT_BLKS, 256>>>(q, k, v, Wq, Wk, Wv, Wo, mask,
                               qh, kh, vh, Wqh, Wkh, Wvh, Woh, mkh);

    dim3 gqkv(DMc / 128, Mc / 128, 3);      // (4, 64, 3)
    gemm_qkv<<<gqkv, 256, GEMM_SMEM_BYTES>>>(qh, kh, vh, Wqh, Wkh, Wvh,
                                             bq, bk, bv, Qp, Kp, Vp);

    dim3 ga(Sc / 128, Bc * Hc);             // (32, 16)
    attn_f16<<<ga, 128, ATTN_SMEM_BYTES>>>(Qp, Kp, Vp, mkh, Ao);

    dim3 gg(DMc / 128, Mc / 128);           // (4, 64)
    gemm_out<<<gg, 256, GEMM_SMEM_BYTES>>>(Ao, Woh, bo, out);
}